// round 2
// baseline (speedup 1.0000x reference)
#include <cuda_runtime.h>
#include <cuda_bf16.h>
#include <math.h>

#define NNODE 16384
#define HEADS 8
#define DIM   64
#define HDIM  512

// ------------------------- device scratch (no allocs allowed) -------------------------
__device__ int   g_rank[2][NNODE];
__device__ int   g_order[16 * NNODE];
__device__ float g_h[NNODE * DIM];
__device__ float g_xn[NNODE * DIM];
__device__ float g_f[NNODE * DIM];
__device__ float g_tmp[NNODE * DIM];
__device__ float g_hist[NNODE * 320];
__device__ float g_q[NNODE * HDIM];
__device__ float g_k[NNODE * HDIM];
__device__ float g_v[NNODE * HDIM];
__device__ float g_agg[NNODE * HDIM];
__device__ float g_outr[16 * NNODE * DIM];   // [nh*8+h][node][d]
__device__ float g_lser[16 * NNODE];
__device__ float g_W2[16];                   // [h][c]
__device__ float g_t0[NNODE * 32];
__device__ float g_u [NNODE * 256];
__device__ float g_u2[NNODE * 256];
__device__ float g_t [NNODE * 32];
__device__ float g_part[128 * 32];

// ------------------------- coord sort: rank = inverse stable argsort -------------------------
__global__ void coord_sort_k(const float* __restrict__ coords) {
    extern __shared__ unsigned long long sk8[];   // 16384 x 8B
    int axis = blockIdx.x;
    int t = threadIdx.x;
    for (int i = t; i < NNODE; i += 1024) {
        unsigned bits = __float_as_uint(coords[i * 3 + axis]);   // coords >= 0 -> monotone
        sk8[i] = ((unsigned long long)bits << 14) | (unsigned)i;
    }
    __syncthreads();
    for (int k = 2; k <= NNODE; k <<= 1) {
        for (int j = k >> 1; j > 0; j >>= 1) {
            for (int i = t; i < NNODE; i += 1024) {
                int ixj = i ^ j;
                if (ixj > i) {
                    unsigned long long a = sk8[i], b = sk8[ixj];
                    bool asc = ((i & k) == 0);
                    if ((a > b) == asc) { sk8[i] = b; sk8[ixj] = a; }
                }
            }
            __syncthreads();
        }
    }
    for (int i = t; i < NNODE; i += 1024) {
        int idx = (int)(sk8[i] & 16383ull);
        g_rank[axis][idx] = i;
    }
}

// ------------------------- bucket keys + stable sort per (nh,h) -------------------------
__global__ void bucket_k(const float* __restrict__ regions) {
    extern __shared__ int sk[];                  // 16384 ints
    __shared__ int red[1024];
    int row = blockIdx.x;                        // nh*8 + h
    int t = threadIdx.x;
    int nh = row >> 3, h = row & 7;
    float qe = 16384.0f / regions[nh * 16 + h];
    float qp = 16384.0f / regions[nh * 16 + 8 + h];
    int lmax = 0;
    for (int i = t; i < NNODE; i += 1024) {
        int re = (int)floorf((float)g_rank[0][i] / qe) + 1;
        int rp = (int)floorf((float)g_rank[1][i] / qp) + 1;
        sk[i] = (rp << 16) | re;
        lmax = max(lmax, re);
    }
    red[t] = lmax;
    __syncthreads();
    for (int s = 512; s > 0; s >>= 1) {
        if (t < s) red[t] = max(red[t], red[t + s]);
        __syncthreads();
    }
    int nb = (int)ceilf(log2f((float)red[0] + 1.0f));
    __syncthreads();
    for (int i = t; i < NNODE; i += 1024) {
        int v = sk[i];
        int key = ((v >> 16) << nb) | (v & 0xffff);
        sk[i] = (key << 14) | i;                 // stability via idx in low bits
    }
    __syncthreads();
    for (int k = 2; k <= NNODE; k <<= 1) {
        for (int j = k >> 1; j > 0; j >>= 1) {
            for (int i = t; i < NNODE; i += 1024) {
                int ixj = i ^ j;
                if (ixj > i) {
                    int a = sk[i], b = sk[ixj];
                    bool asc = ((i & k) == 0);
                    if ((a > b) == asc) { sk[i] = b; sk[ixj] = a; }
                }
            }
            __syncthreads();
        }
    }
    for (int i = t; i < NNODE; i += 1024) g_order[row * NNODE + i] = sk[i] & 16383;
}

// ------------------------- RPE distance weights: W[h,c] = sum_k omega(h,c*8+k)^2 -------------------------
__global__ void w2_k(const float* __restrict__ wrpe) {   // wrpe: [512,16] for this layer
    __shared__ float sq[128];
    int t = threadIdx.x;                 // 128 threads
    int h = t >> 4, m = t & 15;
    float s = 0.f;
    for (int d = 0; d < 64; d++) s += wrpe[(h * 64 + d) * 16 + m];
    float om = s * (1.0f / 64.0f);
    sq[t] = om * om;
    __syncthreads();
    if (t < 16) {
        int hh = t >> 1, c = t & 1;
        float w = 0.f;
        for (int kk = 0; kk < 8; kk++) w += sq[hh * 16 + c * 8 + kk];
        g_W2[t] = w;
    }
}

// ------------------------- LayerNorm over 64 (one warp per row) -------------------------
__global__ void ln64_k(const float* __restrict__ in, float* __restrict__ out,
                       const float* __restrict__ g, const float* __restrict__ b) {
    int w = threadIdx.x >> 5, lane = threadIdx.x & 31;
    int row = blockIdx.x * 8 + w;
    const float* x = in + (size_t)row * 64;
    float a = x[lane], c = x[lane + 32];
    float sum = a + c;
    for (int o = 16; o; o >>= 1) sum += __shfl_xor_sync(0xffffffffu, sum, o);
    float mu = sum * (1.0f / 64.0f);
    float da = a - mu, dc = c - mu;
    float vs = da * da + dc * dc;
    for (int o = 16; o; o >>= 1) vs += __shfl_xor_sync(0xffffffffu, vs, o);
    float rs = rsqrtf(vs * (1.0f / 64.0f) + 1e-5f);
    out[(size_t)row * 64 + lane]      = da * rs * g[lane] + b[lane];
    out[(size_t)row * 64 + lane + 32] = dc * rs * g[lane + 32] + b[lane + 32];
}

// ------------------------- LayerNorm over 256 + tanh (one block per row) -------------------------
__global__ void ln256t_k(const float* __restrict__ in, float* __restrict__ out,
                         const float* __restrict__ g, const float* __restrict__ b) {
    __shared__ float red[256];
    int row = blockIdx.x, t = threadIdx.x;
    float x = in[(size_t)row * 256 + t];
    red[t] = x;
    __syncthreads();
    for (int s = 128; s; s >>= 1) { if (t < s) red[t] += red[t + s]; __syncthreads(); }
    float mu = red[0] * (1.0f / 256.0f);
    __syncthreads();
    float d = x - mu;
    red[t] = d * d;
    __syncthreads();
    for (int s = 128; s; s >>= 1) { if (t < s) red[t] += red[t + s]; __syncthreads(); }
    float rs = rsqrtf(red[0] * (1.0f / 256.0f) + 1e-5f);
    out[(size_t)row * 256 + t] = tanhf(d * rs * g[t] + b[t]);
}

// ------------------------- generic tiled SGEMM with fused epilogue -------------------------
#define FMA16(av, bv, acc)                                                         \
    acc[0][0]+=av.x*bv.x; acc[0][1]+=av.x*bv.y; acc[0][2]+=av.x*bv.z; acc[0][3]+=av.x*bv.w; \
    acc[1][0]+=av.y*bv.x; acc[1][1]+=av.y*bv.y; acc[1][2]+=av.y*bv.z; acc[1][3]+=av.y*bv.w; \
    acc[2][0]+=av.z*bv.x; acc[2][1]+=av.z*bv.y; acc[2][2]+=av.z*bv.z; acc[2][3]+=av.z*bv.w; \
    acc[3][0]+=av.w*bv.x; acc[3][1]+=av.w*bv.y; acc[3][2]+=av.w*bv.z; acc[3][3]+=av.w*bv.w;

__global__ void __launch_bounds__(256) gemm_k(
    const float* __restrict__ A, const float* __restrict__ B, float* __restrict__ C,
    float* __restrict__ C2, int ldc2,
    const float* __restrict__ bias, const float* __restrict__ resid,
    int M, int N, int K, float alpha, int act)
{
    __shared__ float As[16][68];
    __shared__ float Bs[16][68];
    int tid = threadIdx.x;
    int row0 = blockIdx.x * 64, col0 = blockIdx.y * 64;
    int tm = tid >> 4, tn = tid & 15;
    int arow = tid >> 2, ac = tid & 3;
    int bk = tid >> 4, bn = tid & 15;
    float acc[4][4] = {};
    for (int k0 = 0; k0 < K; k0 += 16) {
        float4 a = *(const float4*)&A[(size_t)(row0 + arow) * K + k0 + ac * 4];
        As[ac * 4 + 0][arow] = a.x; As[ac * 4 + 1][arow] = a.y;
        As[ac * 4 + 2][arow] = a.z; As[ac * 4 + 3][arow] = a.w;
        int bcol = col0 + bn * 4;
        float4 bv = make_float4(0.f, 0.f, 0.f, 0.f);
        if (bcol < N) bv = *(const float4*)&B[(size_t)(k0 + bk) * N + bcol];
        *(float4*)&Bs[bk][bn * 4] = bv;
        __syncthreads();
#pragma unroll
        for (int kk = 0; kk < 16; kk++) {
            float4 av = *(const float4*)&As[kk][tm * 4];
            float4 bw = *(const float4*)&Bs[kk][tn * 4];
            FMA16(av, bw, acc)
        }
        __syncthreads();
    }
#pragma unroll
    for (int ii = 0; ii < 4; ii++) {
        int r = row0 + tm * 4 + ii;
#pragma unroll
        for (int jj = 0; jj < 4; jj++) {
            int ccol = col0 + tn * 4 + jj;
            if (ccol < N) {
                float vv = alpha * acc[ii][jj];
                if (bias) vv += bias[ccol];
                if (act == 1) vv = fmaxf(vv, 0.f);
                else if (act == 2) vv = tanhf(vv);
                if (resid) vv += resid[(size_t)r * N + ccol];
                C[(size_t)r * N + ccol] = vv;
                if (C2) C2[(size_t)r * ldc2 + ccol] = vv;
            }
        }
    }
}

// ------------------------- attention: one 64x64 bucket per block -------------------------
__global__ void __launch_bounds__(256) attn_k(
    const float* __restrict__ q, const float* __restrict__ k, const float* __restrict__ v,
    const float* __restrict__ coords)
{
    extern __shared__ float sh[];
    float* Qs = sh;                // [64][68], reused as S[j][i]
    float* Ks = sh + 64 * 68;      // [64][68]  (K transposed: Ks[d][j])
    float* Vs = sh + 2 * 64 * 68;  // [64][68]  (Vs[j][d])
    __shared__ int   nd[64];
    __shared__ float cx[64], cy[64], red[4][64], invs[64];

    int tid = threadIdx.x;
    int blk = blockIdx.x, h = blockIdx.y, nh = blockIdx.z;
    int row = nh * 8 + h;
    const int* ord = g_order + row * NNODE + blk * 64;
    if (tid < 64) {
        int nn = ord[tid];
        nd[tid] = nn;
        cx[tid] = coords[nn * 3 + 0];
        cy[tid] = coords[nn * 3 + 1];
    }
    __syncthreads();
    for (int idx = tid; idx < 4096; idx += 256) {
        int i = idx >> 6, d = idx & 63;
        int base = nd[i] * HDIM + h * 64 + d;
        Qs[d * 68 + i] = q[base];
        Ks[d * 68 + i] = k[base];
        Vs[i * 68 + d] = v[base];
    }
    __syncthreads();

    int tm = tid >> 4, tn = tid & 15;
    float acc[4][4] = {};
#pragma unroll 8
    for (int kk = 0; kk < 64; kk++) {
        float4 av = *(const float4*)&Qs[kk * 68 + tm * 4];
        float4 bw = *(const float4*)&Ks[kk * 68 + tn * 4];
        FMA16(av, bw, acc)
    }
    float W0 = g_W2[h * 2 + 0], W1 = g_W2[h * 2 + 1];
    __syncthreads();
#pragma unroll
    for (int ii = 0; ii < 4; ii++) {
#pragma unroll
        for (int jj = 0; jj < 4; jj++) {
            int i = tm * 4 + ii, j = tn * 4 + jj;
            float dx = cx[i] - cx[j], dy = cy[i] - cy[j];
            Qs[j * 68 + i] = acc[ii][jj] - W0 * dx * dx - W1 * dy * dy;
        }
    }
    __syncthreads();

    // softmax over j for each column i
    int ci = tid & 63, seg = tid >> 6;
    float ml = -3.0e38f;
    for (int jj = 0; jj < 16; jj++) ml = fmaxf(ml, Qs[(seg * 16 + jj) * 68 + ci]);
    red[seg][ci] = ml;
    __syncthreads();
    float mm = fmaxf(fmaxf(red[0][ci], red[1][ci]), fmaxf(red[2][ci], red[3][ci]));
    __syncthreads();
    float sl = 0.f;
    for (int jj = 0; jj < 16; jj++) {
        int j = seg * 16 + jj;
        float e = expf(Qs[j * 68 + ci] - mm);
        Qs[j * 68 + ci] = e;
        sl += e;
    }
    red[seg][ci] = sl;
    __syncthreads();
    float ssum = red[0][ci] + red[1][ci] + red[2][ci] + red[3][ci];
    if (seg == 0) {
        g_lser[row * NNODE + nd[ci]] = mm + logf(ssum);
        invs[ci] = 1.0f / ssum;
    }
    __syncthreads();

    // o = P @ V
    float acc2[4][4] = {};
#pragma unroll 8
    for (int j = 0; j < 64; j++) {
        float4 pv = *(const float4*)&Qs[j * 68 + tm * 4];
        float4 vv = *(const float4*)&Vs[j * 68 + tn * 4];
        FMA16(pv, vv, acc2)
    }
#pragma unroll
    for (int ii = 0; ii < 4; ii++) {
        int qi = tm * 4 + ii;
        float sc = invs[qi];
        float4 o = make_float4(acc2[ii][0] * sc, acc2[ii][1] * sc,
                               acc2[ii][2] * sc, acc2[ii][3] * sc);
        *(float4*)&g_outr[((size_t)row * NNODE + nd[qi]) * 64 + tn * 4] = o;
    }
}

// ------------------------- combine two hash rounds by lse softmax -------------------------
__global__ void combine_k() {
    int gid = blockIdx.x * 256 + threadIdx.x;    // < N*512
    int n = gid >> 9, c = gid & 511, h = c >> 6, d = c & 63;
    float l0 = g_lser[h * NNODE + n];
    float l1 = g_lser[(8 + h) * NNODE + n];
    float m = fmaxf(l0, l1);
    float e0 = expf(l0 - m), e1 = expf(l1 - m);
    float inv = 1.0f / (e0 + e1);
    float o0 = g_outr[((size_t)h * NNODE + n) * 64 + d];
    float o1 = g_outr[((size_t)(8 + h) * NNODE + n) * 64 + d];
    g_agg[gid] = (e0 * o0 + e1 * o1) * inv;
}

// ------------------------- reductions + final projection -------------------------
__global__ void red1_k(const float* __restrict__ t) {   // t: [16384][32]
    __shared__ float sm[256];
    int blk = blockIdx.x, tid = threadIdx.x;
    int col = tid & 31, r0 = tid >> 5;
    float s = 0.f;
    for (int r = r0; r < 128; r += 8) s += t[(size_t)(blk * 128 + r) * 32 + col];
    sm[tid] = s;
    __syncthreads();
    for (int s2 = 4; s2; s2 >>= 1) {
        if (r0 < s2) sm[tid] += sm[tid + s2 * 32];
        __syncthreads();
    }
    if (r0 == 0) g_part[blk * 32 + col] = sm[col];
}

__global__ void red2_k(const float* __restrict__ pw, const float* __restrict__ pb,
                       float* __restrict__ out) {
    __shared__ float mean[32];
    int t = threadIdx.x;
    if (t < 32) {
        float s = 0.f;
        for (int b = 0; b < 128; b++) s += g_part[b * 32 + t];
        mean[t] = s * (1.0f / 16384.0f);
    }
    __syncthreads();
    if (t < 32) {
        float s = pb[t];
        for (int c = 0; c < 32; c++) s += mean[c] * pw[c * 32 + t];
        out[t] = s;
    }
}

// ------------------------- host orchestration -------------------------
extern "C" void kernel_launch(void* const* d_in, const int* in_sizes, int n_in,
                              void* d_out, int out_size)
{
    const float* x      = (const float*)d_in[0];
    const float* coords = (const float*)d_in[1];
    const float* regions= (const float*)d_in[3];
    const float* fe_w1  = (const float*)d_in[4];
    const float* fe_b1  = (const float*)d_in[5];
    const float* fe_w2  = (const float*)d_in[6];
    const float* fe_b2  = (const float*)d_in[7];
    const float* ln1_g  = (const float*)d_in[8];
    const float* ln1_b  = (const float*)d_in[9];
    const float* wq     = (const float*)d_in[10];
    const float* wk     = (const float*)d_in[11];
    const float* wv     = (const float*)d_in[12];
    const float* wrpe   = (const float*)d_in[13];
    const float* ow     = (const float*)d_in[14];
    const float* ob     = (const float*)d_in[15];
    const float* ln2_g  = (const float*)d_in[16];
    const float* ln2_b  = (const float*)d_in[17];
    const float* f1w    = (const float*)d_in[18];
    const float* f1b    = (const float*)d_in[19];
    const float* f2w    = (const float*)d_in[20];
    const float* f2b    = (const float*)d_in[21];
    const float* Wcat   = (const float*)d_in[22];
    const float* m1w    = (const float*)d_in[23];
    const float* m1b    = (const float*)d_in[24];
    const float* mlng   = (const float*)d_in[25];
    const float* mlnb   = (const float*)d_in[26];
    const float* m2w    = (const float*)d_in[27];
    const float* m2b    = (const float*)d_in[28];
    const float* pw     = (const float*)d_in[29];
    const float* pb     = (const float*)d_in[30];
    float* out = (float*)d_out;

    cudaFuncSetAttribute(coord_sort_k, cudaFuncAttributeMaxDynamicSharedMemorySize, 131072);
    cudaFuncSetAttribute(bucket_k,     cudaFuncAttributeMaxDynamicSharedMemorySize, 65536);
    cudaFuncSetAttribute(attn_k,       cudaFuncAttributeMaxDynamicSharedMemorySize, 52224);

    float *p_h, *p_xn, *p_f, *p_tmp, *p_hist, *p_q, *p_k, *p_v, *p_agg;
    float *p_t0, *p_u, *p_u2, *p_t;
    cudaGetSymbolAddress((void**)&p_h,    g_h);
    cudaGetSymbolAddress((void**)&p_xn,   g_xn);
    cudaGetSymbolAddress((void**)&p_f,    g_f);
    cudaGetSymbolAddress((void**)&p_tmp,  g_tmp);
    cudaGetSymbolAddress((void**)&p_hist, g_hist);
    cudaGetSymbolAddress((void**)&p_q,    g_q);
    cudaGetSymbolAddress((void**)&p_k,    g_k);
    cudaGetSymbolAddress((void**)&p_v,    g_v);
    cudaGetSymbolAddress((void**)&p_agg,  g_agg);
    cudaGetSymbolAddress((void**)&p_t0,   g_t0);
    cudaGetSymbolAddress((void**)&p_u,    g_u);
    cudaGetSymbolAddress((void**)&p_u2,   g_u2);
    cudaGetSymbolAddress((void**)&p_t,    g_t);

    const int M = NNODE;
    // bucket ordering (depends only on coords/regions)
    coord_sort_k<<<2, 1024, 131072>>>(coords);
    bucket_k<<<16, 1024, 65536>>>(regions);

    // feat encoder: h = relu(x@fe_w1+b1)@fe_w2+b2 ; hist[:,0:64] = h
    gemm_k<<<dim3(256, 1), 256>>>(x, fe_w1, p_tmp, nullptr, 0, fe_b1, nullptr, M, 64, 16, 1.f, 1);
    gemm_k<<<dim3(256, 1), 256>>>(p_tmp, fe_w2, p_h, p_hist, 320, fe_b2, nullptr, M, 64, 64, 1.f, 0);

    for (int l = 0; l < 4; l++) {
        w2_k<<<1, 128>>>(wrpe + (size_t)l * 512 * 16);
        ln64_k<<<2048, 256>>>(p_h, p_xn, ln1_g + l * 64, ln1_b + l * 64);
        gemm_k<<<dim3(256, 8), 256>>>(p_xn, wq + (size_t)l * 64 * 512, p_q, nullptr, 0,
                                      nullptr, nullptr, M, 512, 64, 0.125f, 0);
        gemm_k<<<dim3(256, 8), 256>>>(p_xn, wk + (size_t)l * 64 * 512, p_k, nullptr, 0,
                                      nullptr, nullptr, M, 512, 64, 1.f, 0);
        gemm_k<<<dim3(256, 8), 256>>>(p_xn, wv + (size_t)l * 64 * 512, p_v, nullptr, 0,
                                      nullptr, nullptr, M, 512, 64, 1.f, 0);
        attn_k<<<dim3(256, 8, 2), 256, 52224>>>(p_q, p_k, p_v, coords);
        combine_k<<<32768, 256>>>();
        gemm_k<<<dim3(256, 1), 256>>>(p_agg, ow + (size_t)l * 512 * 64, p_h, nullptr, 0,
                                      ob + l * 64, p_h, M, 64, 512, 1.f, 0);
        ln64_k<<<2048, 256>>>(p_h, p_f, ln2_g + l * 64, ln2_b + l * 64);
        gemm_k<<<dim3(256, 1), 256>>>(p_f, f1w + (size_t)l * 64 * 64, p_tmp, nullptr, 0,
                                      f1b + l * 64, nullptr, M, 64, 64, 1.f, 1);
        gemm_k<<<dim3(256, 1), 256>>>(p_tmp, f2w + (size_t)l * 64 * 64, p_h,
                                      p_hist + (l + 1) * 64, 320,
                                      f2b + l * 64, p_h, M, 64, 64, 1.f, 0);
    }

    // head
    gemm_k<<<dim3(256, 1), 256>>>(p_hist, Wcat, p_t0, nullptr, 0, nullptr, nullptr, M, 32, 320, 1.f, 2);
    gemm_k<<<dim3(256, 4), 256>>>(p_t0, m1w, p_u, nullptr, 0, m1b, nullptr, M, 256, 32, 1.f, 0);
    ln256t_k<<<16384, 256>>>(p_u, p_u2, mlng, mlnb);
    gemm_k<<<dim3(256, 1), 256>>>(p_u2, m2w, p_t, nullptr, 0, m2b, p_t0, M, 32, 256, 1.f, 0);
    red1_k<<<128, 256>>>(p_t);
    red2_k<<<1, 256>>>(pw, pb, out);
}

// round 3
// speedup vs baseline: 1.1753x; 1.1753x over previous
#include <cuda_runtime.h>
#include <cuda_bf16.h>
#include <math.h>

#define NNODE 16384
#define HEADS 8
#define DIM   64
#define HDIM  512

// ------------------------- device scratch (no allocs allowed) -------------------------
__device__ int   g_rank[2][NNODE];
__device__ int   g_order[16 * NNODE];
__device__ float g_h[NNODE * DIM];
__device__ float g_xn[NNODE * DIM];
__device__ float g_f[NNODE * DIM];
__device__ float g_tmp[NNODE * DIM];
__device__ float g_hist[NNODE * 320];
__device__ float g_q[NNODE * HDIM];
__device__ float g_k[NNODE * HDIM];
__device__ float g_v[NNODE * HDIM];
__device__ float g_agg[NNODE * HDIM];
__device__ float g_outr[16 * NNODE * DIM];   // [nh*8+h][node][d]
__device__ float g_lser[16 * NNODE];
__device__ float g_W2[16];                   // [h][c]
__device__ float g_t0[NNODE * 32];
__device__ float g_u [NNODE * 256];
__device__ float g_u2[NNODE * 256];
__device__ float g_t [NNODE * 32];
__device__ float g_part[128 * 32];

// ------------------------- tf32 helpers -------------------------
__device__ __forceinline__ unsigned f2tf(float f) {
    unsigned u;
    asm("cvt.rna.tf32.f32 %0, %1;" : "=r"(u) : "f"(f));
    return u;
}

__device__ __forceinline__ void mma_tf32(float c[4], unsigned a0, unsigned a1,
                                         unsigned a2, unsigned a3,
                                         unsigned b0, unsigned b1) {
    asm volatile(
        "mma.sync.aligned.m16n8k8.row.col.f32.tf32.tf32.f32 "
        "{%0,%1,%2,%3}, {%4,%5,%6,%7}, {%8,%9}, {%0,%1,%2,%3};"
        : "+f"(c[0]), "+f"(c[1]), "+f"(c[2]), "+f"(c[3])
        : "r"(a0), "r"(a1), "r"(a2), "r"(a3), "r"(b0), "r"(b1));
}

// ------------------------- coord sort: rank = inverse stable argsort -------------------------
__global__ void coord_sort_k(const float* __restrict__ coords) {
    extern __shared__ unsigned long long sk8[];   // 16384 x 8B
    int axis = blockIdx.x;
    int t = threadIdx.x;
    for (int i = t; i < NNODE; i += 1024) {
        unsigned bits = __float_as_uint(coords[i * 3 + axis]);   // coords >= 0 -> monotone
        sk8[i] = ((unsigned long long)bits << 14) | (unsigned)i;
    }
    __syncthreads();
    for (int k = 2; k <= NNODE; k <<= 1) {
        for (int j = k >> 1; j > 0; j >>= 1) {
            for (int i = t; i < NNODE; i += 1024) {
                int ixj = i ^ j;
                if (ixj > i) {
                    unsigned long long a = sk8[i], b = sk8[ixj];
                    bool asc = ((i & k) == 0);
                    if ((a > b) == asc) { sk8[i] = b; sk8[ixj] = a; }
                }
            }
            __syncthreads();
        }
    }
    for (int i = t; i < NNODE; i += 1024) {
        int idx = (int)(sk8[i] & 16383ull);
        g_rank[axis][idx] = i;
    }
}

// ------------------------- bucket keys + stable sort per (nh,h) -------------------------
__global__ void bucket_k(const float* __restrict__ regions) {
    extern __shared__ int sk[];                  // 16384 ints
    __shared__ int red[1024];
    int row = blockIdx.x;                        // nh*8 + h
    int t = threadIdx.x;
    int nh = row >> 3, h = row & 7;
    float qe = 16384.0f / regions[nh * 16 + h];
    float qp = 16384.0f / regions[nh * 16 + 8 + h];
    int lmax = 0;
    for (int i = t; i < NNODE; i += 1024) {
        int re = (int)floorf((float)g_rank[0][i] / qe) + 1;
        int rp = (int)floorf((float)g_rank[1][i] / qp) + 1;
        sk[i] = (rp << 16) | re;
        lmax = max(lmax, re);
    }
    red[t] = lmax;
    __syncthreads();
    for (int s = 512; s > 0; s >>= 1) {
        if (t < s) red[t] = max(red[t], red[t + s]);
        __syncthreads();
    }
    int nb = (int)ceilf(log2f((float)red[0] + 1.0f));
    __syncthreads();
    for (int i = t; i < NNODE; i += 1024) {
        int v = sk[i];
        int key = ((v >> 16) << nb) | (v & 0xffff);
        sk[i] = (key << 14) | i;                 // stability via idx in low bits
    }
    __syncthreads();
    for (int k = 2; k <= NNODE; k <<= 1) {
        for (int j = k >> 1; j > 0; j >>= 1) {
            for (int i = t; i < NNODE; i += 1024) {
                int ixj = i ^ j;
                if (ixj > i) {
                    int a = sk[i], b = sk[ixj];
                    bool asc = ((i & k) == 0);
                    if ((a > b) == asc) { sk[i] = b; sk[ixj] = a; }
                }
            }
            __syncthreads();
        }
    }
    for (int i = t; i < NNODE; i += 1024) g_order[row * NNODE + i] = sk[i] & 16383;
}

// ------------------------- RPE distance weights: W[h,c] = sum_k omega(h,c*8+k)^2 -------------------------
__global__ void w2_k(const float* __restrict__ wrpe) {   // wrpe: [512,16] for this layer
    __shared__ float sq[128];
    int t = threadIdx.x;                 // 128 threads
    int h = t >> 4, m = t & 15;
    float s = 0.f;
    for (int d = 0; d < 64; d++) s += wrpe[(h * 64 + d) * 16 + m];
    float om = s * (1.0f / 64.0f);
    sq[t] = om * om;
    __syncthreads();
    if (t < 16) {
        int hh = t >> 1, c = t & 1;
        float w = 0.f;
        for (int kk = 0; kk < 8; kk++) w += sq[hh * 16 + c * 8 + kk];
        g_W2[t] = w;
    }
}

// ------------------------- LayerNorm over 64 (one warp per row) -------------------------
__global__ void ln64_k(const float* __restrict__ in, float* __restrict__ out,
                       const float* __restrict__ g, const float* __restrict__ b) {
    int w = threadIdx.x >> 5, lane = threadIdx.x & 31;
    int row = blockIdx.x * 8 + w;
    const float* x = in + (size_t)row * 64;
    float a = x[lane], c = x[lane + 32];
    float sum = a + c;
    for (int o = 16; o; o >>= 1) sum += __shfl_xor_sync(0xffffffffu, sum, o);
    float mu = sum * (1.0f / 64.0f);
    float da = a - mu, dc = c - mu;
    float vs = da * da + dc * dc;
    for (int o = 16; o; o >>= 1) vs += __shfl_xor_sync(0xffffffffu, vs, o);
    float rs = rsqrtf(vs * (1.0f / 64.0f) + 1e-5f);
    out[(size_t)row * 64 + lane]      = da * rs * g[lane] + b[lane];
    out[(size_t)row * 64 + lane + 32] = dc * rs * g[lane + 32] + b[lane + 32];
}

// ------------------------- LayerNorm over 256 + tanh (one block per row) -------------------------
__global__ void ln256t_k(const float* __restrict__ in, float* __restrict__ out,
                         const float* __restrict__ g, const float* __restrict__ b) {
    __shared__ float red[256];
    int row = blockIdx.x, t = threadIdx.x;
    float x = in[(size_t)row * 256 + t];
    red[t] = x;
    __syncthreads();
    for (int s = 128; s; s >>= 1) { if (t < s) red[t] += red[t + s]; __syncthreads(); }
    float mu = red[0] * (1.0f / 256.0f);
    __syncthreads();
    float d = x - mu;
    red[t] = d * d;
    __syncthreads();
    for (int s = 128; s; s >>= 1) { if (t < s) red[t] += red[t + s]; __syncthreads(); }
    float rs = rsqrtf(red[0] * (1.0f / 256.0f) + 1e-5f);
    out[(size_t)row * 256 + t] = tanhf(d * rs * g[t] + b[t]);
}

// ------------------------- scalar FFMA SGEMM (exact; small shapes only) -------------------------
#define FMA16(av, bv, acc)                                                         \
    acc[0][0]+=av.x*bv.x; acc[0][1]+=av.x*bv.y; acc[0][2]+=av.x*bv.z; acc[0][3]+=av.x*bv.w; \
    acc[1][0]+=av.y*bv.x; acc[1][1]+=av.y*bv.y; acc[1][2]+=av.y*bv.z; acc[1][3]+=av.y*bv.w; \
    acc[2][0]+=av.z*bv.x; acc[2][1]+=av.z*bv.y; acc[2][2]+=av.z*bv.z; acc[2][3]+=av.z*bv.w; \
    acc[3][0]+=av.w*bv.x; acc[3][1]+=av.w*bv.y; acc[3][2]+=av.w*bv.z; acc[3][3]+=av.w*bv.w;

__global__ void __launch_bounds__(256) gemm_k(
    const float* __restrict__ A, const float* __restrict__ B, float* __restrict__ C,
    float* __restrict__ C2, int ldc2,
    const float* __restrict__ bias, const float* __restrict__ resid,
    int M, int N, int K, float alpha, int act)
{
    __shared__ float As[16][68];
    __shared__ float Bs[16][68];
    int tid = threadIdx.x;
    int row0 = blockIdx.x * 64, col0 = blockIdx.y * 64;
    int tm = tid >> 4, tn = tid & 15;
    int arow = tid >> 2, ac = tid & 3;
    int bk = tid >> 4, bn = tid & 15;
    float acc[4][4] = {};
    for (int k0 = 0; k0 < K; k0 += 16) {
        float4 a = *(const float4*)&A[(size_t)(row0 + arow) * K + k0 + ac * 4];
        As[ac * 4 + 0][arow] = a.x; As[ac * 4 + 1][arow] = a.y;
        As[ac * 4 + 2][arow] = a.z; As[ac * 4 + 3][arow] = a.w;
        int bcol = col0 + bn * 4;
        float4 bv = make_float4(0.f, 0.f, 0.f, 0.f);
        if (bcol < N) bv = *(const float4*)&B[(size_t)(k0 + bk) * N + bcol];
        *(float4*)&Bs[bk][bn * 4] = bv;
        __syncthreads();
#pragma unroll
        for (int kk = 0; kk < 16; kk++) {
            float4 av = *(const float4*)&As[kk][tm * 4];
            float4 bw = *(const float4*)&Bs[kk][tn * 4];
            FMA16(av, bw, acc)
        }
        __syncthreads();
    }
#pragma unroll
    for (int ii = 0; ii < 4; ii++) {
        int r = row0 + tm * 4 + ii;
#pragma unroll
        for (int jj = 0; jj < 4; jj++) {
            int ccol = col0 + tn * 4 + jj;
            if (ccol < N) {
                float vv = alpha * acc[ii][jj];
                if (bias) vv += bias[ccol];
                if (act == 1) vv = fmaxf(vv, 0.f);
                else if (act == 2) vv = tanhf(vv);
                if (resid) vv += resid[(size_t)r * N + ccol];
                C[(size_t)r * N + ccol] = vv;
                if (C2) C2[(size_t)r * ldc2 + ccol] = vv;
            }
        }
    }
}

// ------------------------- TF32 tensor-core GEMM: 64x64 tiles, K in 64-chunks -------------------------
__global__ void __launch_bounds__(256) mma_gemm(
    const float* __restrict__ A, const float* __restrict__ B, float* __restrict__ C,
    float* __restrict__ C2, int ldc2,
    const float* __restrict__ bias, const float* __restrict__ resid,
    int M, int N, int K, float alpha, int act)
{
    __shared__ unsigned As[64 * 68];
    __shared__ unsigned Bs[64 * 68];
    int tid = threadIdx.x;
    int wid = tid >> 5, lane = tid & 31;
    int g = lane >> 2, t = lane & 3;
    int row0 = blockIdx.x * 64, col0 = blockIdx.y * 64;
    int r0 = (wid & 3) * 16, c0 = (wid >> 2) * 32;
    float acc[4][4] = {};   // [nt][creg]

    for (int kc = 0; kc < K; kc += 64) {
#pragma unroll
        for (int it = 0; it < 4; it++) {
            int idx = tid + it * 256;            // 0..1023
            int r = idx >> 4, kq = (idx & 15) * 4;
            // A tile
            float4 av = make_float4(0.f, 0.f, 0.f, 0.f);
            if (kc + kq < K)                      // K multiple of 16
                av = *(const float4*)&A[(size_t)(row0 + r) * K + kc + kq];
            As[r * 68 + kq + 0] = f2tf(av.x); As[r * 68 + kq + 1] = f2tf(av.y);
            As[r * 68 + kq + 2] = f2tf(av.z); As[r * 68 + kq + 3] = f2tf(av.w);
            // B tile (B is K x N row-major)
            float4 bv = make_float4(0.f, 0.f, 0.f, 0.f);
            int bn = col0 + kq;
            if ((kc + r < K) && (bn < N))
                bv = *(const float4*)&B[(size_t)(kc + r) * N + bn];
            Bs[r * 68 + kq + 0] = f2tf(bv.x); Bs[r * 68 + kq + 1] = f2tf(bv.y);
            Bs[r * 68 + kq + 2] = f2tf(bv.z); Bs[r * 68 + kq + 3] = f2tf(bv.w);
        }
        __syncthreads();
#pragma unroll
        for (int ks = 0; ks < 8; ks++) {
            int k0 = ks * 8;
            unsigned a0 = As[(r0 + g) * 68 + k0 + t];
            unsigned a1 = As[(r0 + g + 8) * 68 + k0 + t];
            unsigned a2 = As[(r0 + g) * 68 + k0 + t + 4];
            unsigned a3 = As[(r0 + g + 8) * 68 + k0 + t + 4];
#pragma unroll
            for (int nt = 0; nt < 4; nt++) {
                int n = c0 + nt * 8 + g;
                unsigned b0 = Bs[(k0 + t) * 68 + n];
                unsigned b1 = Bs[(k0 + t + 4) * 68 + n];
                mma_tf32(acc[nt], a0, a1, a2, a3, b0, b1);
            }
        }
        __syncthreads();
    }
#pragma unroll
    for (int nt = 0; nt < 4; nt++) {
#pragma unroll
        for (int cr = 0; cr < 4; cr++) {
            int r = row0 + r0 + g + (cr >> 1) * 8;
            int ccol = col0 + c0 + nt * 8 + 2 * t + (cr & 1);
            if (ccol < N) {
                float vv = alpha * acc[nt][cr];
                if (bias) vv += bias[ccol];
                if (act == 1) vv = fmaxf(vv, 0.f);
                else if (act == 2) vv = tanhf(vv);
                if (resid) vv += resid[(size_t)r * N + ccol];
                C[(size_t)r * N + ccol] = vv;
                if (C2) C2[(size_t)r * ldc2 + ccol] = vv;
            }
        }
    }
}

// ------------------------- attention: one 64x64 bucket per block, tf32 mma -------------------------
__global__ void __launch_bounds__(256) attn_k(
    const float* __restrict__ q, const float* __restrict__ k, const float* __restrict__ v,
    const float* __restrict__ coords)
{
    extern __shared__ unsigned sh[];
    unsigned* Qs = sh;                 // [64][68] tf32 Q[i][k]; reused as S/P [j][i]
    unsigned* Ks = sh + 64 * 68;       // [64][68] tf32 K[j][k]
    unsigned* Vs = sh + 2 * 64 * 68;   // [64][68] tf32 V[j][d]
    __shared__ int   nd[64];
    __shared__ float cx[64], cy[64], redm[4][64], reds[4][64];

    int tid = threadIdx.x;
    int blk = blockIdx.x, h = blockIdx.y, nh = blockIdx.z;
    int row = nh * 8 + h;
    const int* ord = g_order + row * NNODE + blk * 64;
    if (tid < 64) {
        int nn = ord[tid];
        nd[tid] = nn;
        cx[tid] = coords[nn * 3 + 0];
        cy[tid] = coords[nn * 3 + 1];
    }
    __syncthreads();
    for (int idx = tid; idx < 4096; idx += 256) {
        int i = idx >> 6, d = idx & 63;
        int base = nd[i] * HDIM + h * 64 + d;
        Qs[i * 68 + d] = f2tf(q[base]);
        Ks[i * 68 + d] = f2tf(k[base]);
        Vs[i * 68 + d] = f2tf(v[base]);
    }
    __syncthreads();

    int wid = tid >> 5, lane = tid & 31;
    int g = lane >> 2, t = lane & 3;
    int r0 = (wid & 3) * 16, c0 = (wid >> 2) * 32;

    // S = Q @ K^T   (warp tile: rows r0..r0+15, cols c0..c0+31)
    float acc[4][4] = {};
#pragma unroll
    for (int ks = 0; ks < 8; ks++) {
        int k0 = ks * 8;
        unsigned a0 = Qs[(r0 + g) * 68 + k0 + t];
        unsigned a1 = Qs[(r0 + g + 8) * 68 + k0 + t];
        unsigned a2 = Qs[(r0 + g) * 68 + k0 + t + 4];
        unsigned a3 = Qs[(r0 + g + 8) * 68 + k0 + t + 4];
#pragma unroll
        for (int nt = 0; nt < 4; nt++) {
            int j = c0 + nt * 8 + g;
            unsigned b0 = Ks[j * 68 + k0 + t];
            unsigned b1 = Ks[j * 68 + k0 + t + 4];
            mma_tf32(acc[nt], a0, a1, a2, a3, b0, b1);
        }
    }
    float W0 = g_W2[h * 2 + 0], W1 = g_W2[h * 2 + 1];
    __syncthreads();                    // done reading Qs/Ks

    // write S transposed into Qs: Ss[j][i], with RPE term
    float* Ss = (float*)Qs;
#pragma unroll
    for (int nt = 0; nt < 4; nt++) {
        int j0 = c0 + nt * 8 + 2 * t;
#pragma unroll
        for (int cr = 0; cr < 4; cr++) {
            int i = r0 + g + (cr >> 1) * 8;
            int j = j0 + (cr & 1);
            float dx = cx[i] - cx[j], dy = cy[i] - cy[j];
            Ss[j * 68 + i] = acc[nt][cr] - W0 * dx * dx - W1 * dy * dy;
        }
    }
    __syncthreads();

    // softmax over j for each query i (thread layout: ci = query, seg handles 16 j)
    int ci = tid & 63, seg = tid >> 6;
    float ml = -3.0e38f;
#pragma unroll
    for (int jj = 0; jj < 16; jj++) ml = fmaxf(ml, Ss[(seg * 16 + jj) * 68 + ci]);
    redm[seg][ci] = ml;
    __syncthreads();
    float mm = fmaxf(fmaxf(redm[0][ci], redm[1][ci]), fmaxf(redm[2][ci], redm[3][ci]));
    float ev[16];
    float sl = 0.f;
#pragma unroll
    for (int jj = 0; jj < 16; jj++) {
        float e = expf(Ss[(seg * 16 + jj) * 68 + ci] - mm);
        ev[jj] = e;
        sl += e;
    }
    reds[seg][ci] = sl;
    __syncthreads();
    float ssum = reds[0][ci] + reds[1][ci] + reds[2][ci] + reds[3][ci];
    float inv = 1.0f / ssum;
    if (seg == 0) g_lser[row * NNODE + nd[ci]] = mm + logf(ssum);
    unsigned* Ps = Qs;
#pragma unroll
    for (int jj = 0; jj < 16; jj++)
        Ps[(seg * 16 + jj) * 68 + ci] = f2tf(ev[jj] * inv);
    __syncthreads();

    // O = P @ V   (P stored [j][i] -> A fragment from Ps[(k)(..)][i])
    float oacc[4][4] = {};
#pragma unroll
    for (int ks = 0; ks < 8; ks++) {
        int k0 = ks * 8;
        unsigned a0 = Ps[(k0 + t) * 68 + r0 + g];
        unsigned a1 = Ps[(k0 + t) * 68 + r0 + g + 8];
        unsigned a2 = Ps[(k0 + t + 4) * 68 + r0 + g];
        unsigned a3 = Ps[(k0 + t + 4) * 68 + r0 + g + 8];
#pragma unroll
        for (int nt = 0; nt < 4; nt++) {
            int n = c0 + nt * 8 + g;
            unsigned b0 = Vs[(k0 + t) * 68 + n];
            unsigned b1 = Vs[(k0 + t + 4) * 68 + n];
            mma_tf32(oacc[nt], a0, a1, a2, a3, b0, b1);
        }
    }
#pragma unroll
    for (int nt = 0; nt < 4; nt++) {
        int d0 = c0 + nt * 8 + 2 * t;
        int iA = r0 + g, iB = r0 + g + 8;
        *(float2*)&g_outr[((size_t)row * NNODE + nd[iA]) * 64 + d0] =
            make_float2(oacc[nt][0], oacc[nt][1]);
        *(float2*)&g_outr[((size_t)row * NNODE + nd[iB]) * 64 + d0] =
            make_float2(oacc[nt][2], oacc[nt][3]);
    }
}

// ------------------------- combine two hash rounds by lse softmax -------------------------
__global__ void combine_k() {
    int gid = blockIdx.x * 256 + threadIdx.x;    // < N*512
    int n = gid >> 9, c = gid & 511, h = c >> 6, d = c & 63;
    float l0 = g_lser[h * NNODE + n];
    float l1 = g_lser[(8 + h) * NNODE + n];
    float m = fmaxf(l0, l1);
    float e0 = expf(l0 - m), e1 = expf(l1 - m);
    float inv = 1.0f / (e0 + e1);
    float o0 = g_outr[((size_t)h * NNODE + n) * 64 + d];
    float o1 = g_outr[((size_t)(8 + h) * NNODE + n) * 64 + d];
    g_agg[gid] = (e0 * o0 + e1 * o1) * inv;
}

// ------------------------- reductions + final projection -------------------------
__global__ void red1_k(const float* __restrict__ t) {   // t: [16384][32]
    __shared__ float sm[256];
    int blk = blockIdx.x, tid = threadIdx.x;
    int col = tid & 31, r0 = tid >> 5;
    float s = 0.f;
    for (int r = r0; r < 128; r += 8) s += t[(size_t)(blk * 128 + r) * 32 + col];
    sm[tid] = s;
    __syncthreads();
    for (int s2 = 4; s2; s2 >>= 1) {
        if (r0 < s2) sm[tid] += sm[tid + s2 * 32];
        __syncthreads();
    }
    if (r0 == 0) g_part[blk * 32 + col] = sm[col];
}

__global__ void red2_k(const float* __restrict__ pw, const float* __restrict__ pb,
                       float* __restrict__ out) {
    __shared__ float mean[32];
    int t = threadIdx.x;
    if (t < 32) {
        float s = 0.f;
        for (int b = 0; b < 128; b++) s += g_part[b * 32 + t];
        mean[t] = s * (1.0f / 16384.0f);
    }
    __syncthreads();
    if (t < 32) {
        float s = pb[t];
        for (int c = 0; c < 32; c++) s += mean[c] * pw[c * 32 + t];
        out[t] = s;
    }
}

// ------------------------- host orchestration -------------------------
extern "C" void kernel_launch(void* const* d_in, const int* in_sizes, int n_in,
                              void* d_out, int out_size)
{
    const float* x      = (const float*)d_in[0];
    const float* coords = (const float*)d_in[1];
    const float* regions= (const float*)d_in[3];
    const float* fe_w1  = (const float*)d_in[4];
    const float* fe_b1  = (const float*)d_in[5];
    const float* fe_w2  = (const float*)d_in[6];
    const float* fe_b2  = (const float*)d_in[7];
    const float* ln1_g  = (const float*)d_in[8];
    const float* ln1_b  = (const float*)d_in[9];
    const float* wq     = (const float*)d_in[10];
    const float* wk     = (const float*)d_in[11];
    const float* wv     = (const float*)d_in[12];
    const float* wrpe   = (const float*)d_in[13];
    const float* ow     = (const float*)d_in[14];
    const float* ob     = (const float*)d_in[15];
    const float* ln2_g  = (const float*)d_in[16];
    const float* ln2_b  = (const float*)d_in[17];
    const float* f1w    = (const float*)d_in[18];
    const float* f1b    = (const float*)d_in[19];
    const float* f2w    = (const float*)d_in[20];
    const float* f2b    = (const float*)d_in[21];
    const float* Wcat   = (const float*)d_in[22];
    const float* m1w    = (const float*)d_in[23];
    const float* m1b    = (const float*)d_in[24];
    const float* mlng   = (const float*)d_in[25];
    const float* mlnb   = (const float*)d_in[26];
    const float* m2w    = (const float*)d_in[27];
    const float* m2b    = (const float*)d_in[28];
    const float* pw     = (const float*)d_in[29];
    const float* pb     = (const float*)d_in[30];
    float* out = (float*)d_out;

    cudaFuncSetAttribute(coord_sort_k, cudaFuncAttributeMaxDynamicSharedMemorySize, 131072);
    cudaFuncSetAttribute(bucket_k,     cudaFuncAttributeMaxDynamicSharedMemorySize, 65536);
    cudaFuncSetAttribute(attn_k,       cudaFuncAttributeMaxDynamicSharedMemorySize, 52224);

    float *p_h, *p_xn, *p_f, *p_tmp, *p_hist, *p_q, *p_k, *p_v, *p_agg;
    float *p_t0, *p_u, *p_u2, *p_t;
    cudaGetSymbolAddress((void**)&p_h,    g_h);
    cudaGetSymbolAddress((void**)&p_xn,   g_xn);
    cudaGetSymbolAddress((void**)&p_f,    g_f);
    cudaGetSymbolAddress((void**)&p_tmp,  g_tmp);
    cudaGetSymbolAddress((void**)&p_hist, g_hist);
    cudaGetSymbolAddress((void**)&p_q,    g_q);
    cudaGetSymbolAddress((void**)&p_k,    g_k);
    cudaGetSymbolAddress((void**)&p_v,    g_v);
    cudaGetSymbolAddress((void**)&p_agg,  g_agg);
    cudaGetSymbolAddress((void**)&p_t0,   g_t0);
    cudaGetSymbolAddress((void**)&p_u,    g_u);
    cudaGetSymbolAddress((void**)&p_u2,   g_u2);
    cudaGetSymbolAddress((void**)&p_t,    g_t);

    const int M = NNODE;
    // bucket ordering (depends only on coords/regions)
    coord_sort_k<<<2, 1024, 131072>>>(coords);
    bucket_k<<<16, 1024, 65536>>>(regions);

    // feat encoder: h = relu(x@fe_w1+b1)@fe_w2+b2 ; hist[:,0:64] = h   (exact FFMA path)
    gemm_k<<<dim3(256, 1), 256>>>(x, fe_w1, p_tmp, nullptr, 0, fe_b1, nullptr, M, 64, 16, 1.f, 1);
    gemm_k<<<dim3(256, 1), 256>>>(p_tmp, fe_w2, p_h, p_hist, 320, fe_b2, nullptr, M, 64, 64, 1.f, 0);

    for (int l = 0; l < 4; l++) {
        w2_k<<<1, 128>>>(wrpe + (size_t)l * 512 * 16);
        ln64_k<<<2048, 256>>>(p_h, p_xn, ln1_g + l * 64, ln1_b + l * 64);
        mma_gemm<<<dim3(256, 8), 256>>>(p_xn, wq + (size_t)l * 64 * 512, p_q, nullptr, 0,
                                        nullptr, nullptr, M, 512, 64, 0.125f, 0);
        mma_gemm<<<dim3(256, 8), 256>>>(p_xn, wk + (size_t)l * 64 * 512, p_k, nullptr, 0,
                                        nullptr, nullptr, M, 512, 64, 1.f, 0);
        mma_gemm<<<dim3(256, 8), 256>>>(p_xn, wv + (size_t)l * 64 * 512, p_v, nullptr, 0,
                                        nullptr, nullptr, M, 512, 64, 1.f, 0);
        attn_k<<<dim3(256, 8, 2), 256, 52224>>>(p_q, p_k, p_v, coords);
        combine_k<<<32768, 256>>>();
        mma_gemm<<<dim3(256, 1), 256>>>(p_agg, ow + (size_t)l * 512 * 64, p_h, nullptr, 0,
                                        ob + l * 64, p_h, M, 64, 512, 1.f, 0);
        ln64_k<<<2048, 256>>>(p_h, p_f, ln2_g + l * 64, ln2_b + l * 64);
        gemm_k<<<dim3(256, 1), 256>>>(p_f, f1w + (size_t)l * 64 * 64, p_tmp, nullptr, 0,
                                      f1b + l * 64, nullptr, M, 64, 64, 1.f, 1);
        gemm_k<<<dim3(256, 1), 256>>>(p_tmp, f2w + (size_t)l * 64 * 64, p_h,
                                      p_hist + (l + 1) * 64, 320,
                                      f2b + l * 64, p_h, M, 64, 64, 1.f, 0);
    }

    // head (exact FFMA path)
    gemm_k<<<dim3(256, 1), 256>>>(p_hist, Wcat, p_t0, nullptr, 0, nullptr, nullptr, M, 32, 320, 1.f, 2);
    gemm_k<<<dim3(256, 4), 256>>>(p_t0, m1w, p_u, nullptr, 0, m1b, nullptr, M, 256, 32, 1.f, 0);
    ln256t_k<<<16384, 256>>>(p_u, p_u2, mlng, mlnb);
    gemm_k<<<dim3(256, 1), 256>>>(p_u2, m2w, p_t, nullptr, 0, m2b, p_t0, M, 32, 256, 1.f, 0);
    red1_k<<<128, 256>>>(p_t);
    red2_k<<<1, 256>>>(pw, pb, out);
}

// round 4
// speedup vs baseline: 1.3396x; 1.1398x over previous
#include <cuda_runtime.h>
#include <cuda_bf16.h>
#include <math.h>

#define NNODE 16384
#define HEADS 8
#define DIM   64
#define HDIM  512

// ------------------------- device scratch (no allocs allowed) -------------------------
__device__ int   g_rank[2][NNODE];
__device__ int   g_order[16 * NNODE];
__device__ float g_h[NNODE * DIM];
__device__ float g_xn[NNODE * DIM];
__device__ float g_tmp[NNODE * DIM];
__device__ float g_hist[NNODE * 320];
__device__ float g_q[NNODE * HDIM];
__device__ float g_k[NNODE * HDIM];
__device__ float g_v[NNODE * HDIM];
__device__ float g_outr[16 * NNODE * DIM];   // [nh*8+h][node][d]
__device__ float g_lser[16 * NNODE];
__device__ float g_W2[4 * 16];               // [layer][h][c]
__device__ float g_t0[NNODE * 32];
__device__ float g_u [NNODE * 256];
__device__ float g_u2[NNODE * 256];
__device__ float g_t [NNODE * 32];
__device__ float g_part[128 * 32];

// ------------------------- tf32 helpers -------------------------
__device__ __forceinline__ unsigned f2tf(float f) {
    unsigned u;
    asm("cvt.rna.tf32.f32 %0, %1;" : "=r"(u) : "f"(f));
    return u;
}

__device__ __forceinline__ void mma_tf32(float c[4], unsigned a0, unsigned a1,
                                         unsigned a2, unsigned a3,
                                         unsigned b0, unsigned b1) {
    asm volatile(
        "mma.sync.aligned.m16n8k8.row.col.f32.tf32.tf32.f32 "
        "{%0,%1,%2,%3}, {%4,%5,%6,%7}, {%8,%9}, {%0,%1,%2,%3};"
        : "+f"(c[0]), "+f"(c[1]), "+f"(c[2]), "+f"(c[3])
        : "r"(a0), "r"(a1), "r"(a2), "r"(a3), "r"(b0), "r"(b1));
}

// ------------------------- counting ranks for coords (stable) -------------------------
__global__ void __launch_bounds__(256) rank_k(const float* __restrict__ coords) {
    __shared__ float sc[4096];
    int axis = blockIdx.y;
    int t = threadIdx.x;
    int node = blockIdx.x * 64 + (t >> 2);
    int part = t & 3;
    float ci = coords[node * 3 + axis];
    int cnt = 0;
    for (int c0 = 0; c0 < NNODE; c0 += 4096) {
        __syncthreads();
        for (int i = t; i < 4096; i += 256) sc[i] = coords[(c0 + i) * 3 + axis];
        __syncthreads();
        int jb = part * 1024;
#pragma unroll 8
        for (int m = 0; m < 1024; m++) {
            int j = jb + m;
            float cj = sc[j];
            int jg = c0 + j;
            cnt += (int)((cj < ci) || (cj == ci && jg < node));
        }
    }
    cnt += __shfl_down_sync(0xffffffffu, cnt, 2, 4);
    cnt += __shfl_down_sync(0xffffffffu, cnt, 1, 4);
    if (part == 0) g_rank[axis][node] = cnt;
}

// ------------------------- bucket keys + stable sort per (nh,h) -------------------------
__global__ void bucket_k(const float* __restrict__ regions) {
    extern __shared__ int sk[];                  // 16384 ints
    __shared__ int red[1024];
    int row = blockIdx.x;                        // nh*8 + h
    int t = threadIdx.x;
    int nh = row >> 3, h = row & 7;
    float qe = 16384.0f / regions[nh * 16 + h];
    float qp = 16384.0f / regions[nh * 16 + 8 + h];
    int lmax = 0;
    for (int i = t; i < NNODE; i += 1024) {
        int re = (int)floorf((float)g_rank[0][i] / qe) + 1;
        int rp = (int)floorf((float)g_rank[1][i] / qp) + 1;
        sk[i] = (rp << 16) | re;
        lmax = max(lmax, re);
    }
    red[t] = lmax;
    __syncthreads();
    for (int s = 512; s > 0; s >>= 1) {
        if (t < s) red[t] = max(red[t], red[t + s]);
        __syncthreads();
    }
    int nb = (int)ceilf(log2f((float)red[0] + 1.0f));
    __syncthreads();
    for (int i = t; i < NNODE; i += 1024) {
        int v = sk[i];
        int key = ((v >> 16) << nb) | (v & 0xffff);
        sk[i] = (key << 14) | i;                 // stability via idx in low bits
    }
    __syncthreads();
    for (int k = 2; k <= NNODE; k <<= 1) {
        for (int j = k >> 1; j > 0; j >>= 1) {
            for (int i = t; i < NNODE; i += 1024) {
                int ixj = i ^ j;
                if (ixj > i) {
                    int a = sk[i], b = sk[ixj];
                    bool asc = ((i & k) == 0);
                    if ((a > b) == asc) { sk[i] = b; sk[ixj] = a; }
                }
            }
            __syncthreads();
        }
    }
    for (int i = t; i < NNODE; i += 1024) g_order[row * NNODE + i] = sk[i] & 16383;
}

// ------------------------- RPE distance weights (all 4 layers) -------------------------
__global__ void w2all_k(const float* __restrict__ wrpe) {   // [4][512][16]
    __shared__ float sq[128];
    int l = blockIdx.x;
    const float* w = wrpe + (size_t)l * 512 * 16;
    int t = threadIdx.x;                 // 128 threads
    int h = t >> 4, m = t & 15;
    float s = 0.f;
    for (int d = 0; d < 64; d++) s += w[(h * 64 + d) * 16 + m];
    float om = s * (1.0f / 64.0f);
    sq[t] = om * om;
    __syncthreads();
    if (t < 16) {
        int hh = t >> 1, c = t & 1;
        float ww = 0.f;
        for (int kk = 0; kk < 8; kk++) ww += sq[hh * 16 + c * 8 + kk];
        g_W2[l * 16 + t] = ww;
    }
}

// ------------------------- LayerNorm over 64 (one warp per row) -------------------------
__global__ void ln64_k(const float* __restrict__ in, float* __restrict__ out,
                       const float* __restrict__ g, const float* __restrict__ b) {
    int w = threadIdx.x >> 5, lane = threadIdx.x & 31;
    int row = blockIdx.x * 8 + w;
    const float* x = in + (size_t)row * 64;
    float a = x[lane], c = x[lane + 32];
    float sum = a + c;
    for (int o = 16; o; o >>= 1) sum += __shfl_xor_sync(0xffffffffu, sum, o);
    float mu = sum * (1.0f / 64.0f);
    float da = a - mu, dc = c - mu;
    float vs = da * da + dc * dc;
    for (int o = 16; o; o >>= 1) vs += __shfl_xor_sync(0xffffffffu, vs, o);
    float rs = rsqrtf(vs * (1.0f / 64.0f) + 1e-5f);
    out[(size_t)row * 64 + lane]      = da * rs * g[lane] + b[lane];
    out[(size_t)row * 64 + lane + 32] = dc * rs * g[lane + 32] + b[lane + 32];
}

// ------------------------- LayerNorm over 256 + tanh -------------------------
__global__ void ln256t_k(const float* __restrict__ in, float* __restrict__ out,
                         const float* __restrict__ g, const float* __restrict__ b) {
    __shared__ float red[256];
    int row = blockIdx.x, t = threadIdx.x;
    float x = in[(size_t)row * 256 + t];
    red[t] = x;
    __syncthreads();
    for (int s = 128; s; s >>= 1) { if (t < s) red[t] += red[t + s]; __syncthreads(); }
    float mu = red[0] * (1.0f / 256.0f);
    __syncthreads();
    float d = x - mu;
    red[t] = d * d;
    __syncthreads();
    for (int s = 128; s; s >>= 1) { if (t < s) red[t] += red[t + s]; __syncthreads(); }
    float rs = rsqrtf(red[0] * (1.0f / 256.0f) + 1e-5f);
    out[(size_t)row * 256 + t] = tanhf(d * rs * g[t] + b[t]);
}

// ------------------------- scalar FFMA SGEMM (exact; small shapes) -------------------------
#define FMA16(av, bv, acc)                                                         \
    acc[0][0]+=av.x*bv.x; acc[0][1]+=av.x*bv.y; acc[0][2]+=av.x*bv.z; acc[0][3]+=av.x*bv.w; \
    acc[1][0]+=av.y*bv.x; acc[1][1]+=av.y*bv.y; acc[1][2]+=av.y*bv.z; acc[1][3]+=av.y*bv.w; \
    acc[2][0]+=av.z*bv.x; acc[2][1]+=av.z*bv.y; acc[2][2]+=av.z*bv.z; acc[2][3]+=av.z*bv.w; \
    acc[3][0]+=av.w*bv.x; acc[3][1]+=av.w*bv.y; acc[3][2]+=av.w*bv.z; acc[3][3]+=av.w*bv.w;

__global__ void __launch_bounds__(256) gemm_k(
    const float* __restrict__ A, const float* __restrict__ B, float* __restrict__ C,
    float* __restrict__ C2, int ldc2,
    const float* __restrict__ bias, const float* __restrict__ resid,
    int M, int N, int K, float alpha, int act)
{
    __shared__ float As[16][68];
    __shared__ float Bs[16][68];
    int tid = threadIdx.x;
    int row0 = blockIdx.x * 64, col0 = blockIdx.y * 64;
    int tm = tid >> 4, tn = tid & 15;
    int arow = tid >> 2, ac = tid & 3;
    int bk = tid >> 4, bn = tid & 15;
    float acc[4][4] = {};
    for (int k0 = 0; k0 < K; k0 += 16) {
        float4 a = *(const float4*)&A[(size_t)(row0 + arow) * K + k0 + ac * 4];
        As[ac * 4 + 0][arow] = a.x; As[ac * 4 + 1][arow] = a.y;
        As[ac * 4 + 2][arow] = a.z; As[ac * 4 + 3][arow] = a.w;
        int bcol = col0 + bn * 4;
        float4 bv = make_float4(0.f, 0.f, 0.f, 0.f);
        if (bcol < N) bv = *(const float4*)&B[(size_t)(k0 + bk) * N + bcol];
        *(float4*)&Bs[bk][bn * 4] = bv;
        __syncthreads();
#pragma unroll
        for (int kk = 0; kk < 16; kk++) {
            float4 av = *(const float4*)&As[kk][tm * 4];
            float4 bw = *(const float4*)&Bs[kk][tn * 4];
            FMA16(av, bw, acc)
        }
        __syncthreads();
    }
#pragma unroll
    for (int ii = 0; ii < 4; ii++) {
        int r = row0 + tm * 4 + ii;
#pragma unroll
        for (int jj = 0; jj < 4; jj++) {
            int ccol = col0 + tn * 4 + jj;
            if (ccol < N) {
                float vv = alpha * acc[ii][jj];
                if (bias) vv += bias[ccol];
                if (act == 1) vv = fmaxf(vv, 0.f);
                else if (act == 2) vv = tanhf(vv);
                if (resid) vv += resid[(size_t)r * N + ccol];
                C[(size_t)r * N + ccol] = vv;
                if (C2) C2[(size_t)r * ldc2 + ccol] = vv;
            }
        }
    }
}

// ------------------------- fused QKV tf32 GEMM: grid (256, 24) -------------------------
__global__ void __launch_bounds__(256) qkv_k(
    const float* __restrict__ A,
    const float* __restrict__ wq, const float* __restrict__ wk, const float* __restrict__ wv,
    float* __restrict__ q, float* __restrict__ k, float* __restrict__ v)
{
    __shared__ unsigned As[64 * 68];
    __shared__ unsigned Bs[64 * 68];
    int tid = threadIdx.x;
    int sel = blockIdx.y >> 3, h = blockIdx.y & 7;
    const float* B = sel == 0 ? wq : (sel == 1 ? wk : wv);
    float* C = sel == 0 ? q : (sel == 1 ? k : v);
    float alpha = sel == 0 ? 0.125f : 1.0f;
    int row0 = blockIdx.x * 64, col0 = h * 64;
    int wid = tid >> 5, lane = tid & 31;
    int g = lane >> 2, t = lane & 3;
    int r0 = (wid & 3) * 16, c0 = (wid >> 2) * 32;
    float acc[4][4] = {};
#pragma unroll
    for (int it = 0; it < 4; it++) {
        int idx = tid + it * 256;
        int r = idx >> 4, c4 = (idx & 15) * 4;
        float4 av = *(const float4*)&A[(size_t)(row0 + r) * 64 + c4];
        As[r * 68 + c4 + 0] = f2tf(av.x); As[r * 68 + c4 + 1] = f2tf(av.y);
        As[r * 68 + c4 + 2] = f2tf(av.z); As[r * 68 + c4 + 3] = f2tf(av.w);
        float4 bv = *(const float4*)&B[(size_t)r * 512 + col0 + c4];
        Bs[r * 68 + c4 + 0] = f2tf(bv.x); Bs[r * 68 + c4 + 1] = f2tf(bv.y);
        Bs[r * 68 + c4 + 2] = f2tf(bv.z); Bs[r * 68 + c4 + 3] = f2tf(bv.w);
    }
    __syncthreads();
#pragma unroll
    for (int ks = 0; ks < 8; ks++) {
        int k0 = ks * 8;
        unsigned a0 = As[(r0 + g) * 68 + k0 + t];
        unsigned a1 = As[(r0 + g + 8) * 68 + k0 + t];
        unsigned a2 = As[(r0 + g) * 68 + k0 + t + 4];
        unsigned a3 = As[(r0 + g + 8) * 68 + k0 + t + 4];
#pragma unroll
        for (int nt = 0; nt < 4; nt++) {
            int n = c0 + nt * 8 + g;
            unsigned b0 = Bs[(k0 + t) * 68 + n];
            unsigned b1 = Bs[(k0 + t + 4) * 68 + n];
            mma_tf32(acc[nt], a0, a1, a2, a3, b0, b1);
        }
    }
#pragma unroll
    for (int nt = 0; nt < 4; nt++) {
#pragma unroll
        for (int cr = 0; cr < 4; cr++) {
            int r = row0 + r0 + g + (cr >> 1) * 8;
            int ccol = col0 + c0 + nt * 8 + 2 * t + (cr & 1);
            C[(size_t)r * 512 + ccol] = alpha * acc[nt][cr];
        }
    }
}

// ------------------------- out-projection with fused lse-combine (K=512) -------------------------
__global__ void __launch_bounds__(256) outproj_k(
    const float* __restrict__ ow, const float* __restrict__ ob, float* __restrict__ hbuf)
{
    __shared__ unsigned As[64 * 68];
    __shared__ unsigned Bs[64 * 68];
    __shared__ float w0s[64], w1s[64];
    int tid = threadIdx.x;
    int row0 = blockIdx.x * 64;
    int wid = tid >> 5, lane = tid & 31;
    int g = lane >> 2, t = lane & 3;
    int r0 = (wid & 3) * 16, c0 = (wid >> 2) * 32;
    float acc[4][4] = {};
    for (int h = 0; h < 8; h++) {
        __syncthreads();
        if (tid < 64) {
            int node = row0 + tid;
            float l0 = g_lser[h * NNODE + node];
            float l1 = g_lser[(8 + h) * NNODE + node];
            float m = fmaxf(l0, l1);
            float e0 = expf(l0 - m), e1 = expf(l1 - m);
            float inv = 1.0f / (e0 + e1);
            w0s[tid] = e0 * inv;
            w1s[tid] = e1 * inv;
        }
        __syncthreads();
#pragma unroll
        for (int it = 0; it < 4; it++) {
            int idx = tid + it * 256;
            int r = idx >> 4, c4 = (idx & 15) * 4;
            int node = row0 + r;
            float4 o0 = *(const float4*)&g_outr[((size_t)h * NNODE + node) * 64 + c4];
            float4 o1 = *(const float4*)&g_outr[((size_t)(8 + h) * NNODE + node) * 64 + c4];
            float w0 = w0s[r], w1 = w1s[r];
            As[r * 68 + c4 + 0] = f2tf(w0 * o0.x + w1 * o1.x);
            As[r * 68 + c4 + 1] = f2tf(w0 * o0.y + w1 * o1.y);
            As[r * 68 + c4 + 2] = f2tf(w0 * o0.z + w1 * o1.z);
            As[r * 68 + c4 + 3] = f2tf(w0 * o0.w + w1 * o1.w);
            float4 bv = *(const float4*)&ow[(size_t)(h * 64 + r) * 64 + c4];
            Bs[r * 68 + c4 + 0] = f2tf(bv.x); Bs[r * 68 + c4 + 1] = f2tf(bv.y);
            Bs[r * 68 + c4 + 2] = f2tf(bv.z); Bs[r * 68 + c4 + 3] = f2tf(bv.w);
        }
        __syncthreads();
#pragma unroll
        for (int ks = 0; ks < 8; ks++) {
            int k0 = ks * 8;
            unsigned a0 = As[(r0 + g) * 68 + k0 + t];
            unsigned a1 = As[(r0 + g + 8) * 68 + k0 + t];
            unsigned a2 = As[(r0 + g) * 68 + k0 + t + 4];
            unsigned a3 = As[(r0 + g + 8) * 68 + k0 + t + 4];
#pragma unroll
            for (int nt = 0; nt < 4; nt++) {
                int n = c0 + nt * 8 + g;
                unsigned b0 = Bs[(k0 + t) * 68 + n];
                unsigned b1 = Bs[(k0 + t + 4) * 68 + n];
                mma_tf32(acc[nt], a0, a1, a2, a3, b0, b1);
            }
        }
    }
#pragma unroll
    for (int nt = 0; nt < 4; nt++) {
#pragma unroll
        for (int cr = 0; cr < 4; cr++) {
            int r = row0 + r0 + g + (cr >> 1) * 8;
            int ccol = c0 + nt * 8 + 2 * t + (cr & 1);
            float vv = acc[nt][cr] + ob[ccol] + hbuf[(size_t)r * 64 + ccol];
            hbuf[(size_t)r * 64 + ccol] = vv;
        }
    }
}

// ------------------------- fused LN2 + FFN + residual + hist (exact FFMA) -------------------------
__global__ void __launch_bounds__(256) ffn_k(
    float* __restrict__ hbuf, const float* __restrict__ g, const float* __restrict__ b,
    const float* __restrict__ W1, const float* __restrict__ b1,
    const float* __restrict__ W2, const float* __restrict__ b2,
    float* __restrict__ hist)
{
    __shared__ float Xs[64 * 68];
    __shared__ float Ws[64 * 68];
    __shared__ float redA[64][4];
    int tid = threadIdx.x;
    int row0 = blockIdx.x * 64;
#pragma unroll
    for (int it = 0; it < 4; it++) {
        int idx = tid + it * 256;
        int r = idx >> 4, c4 = (idx & 15) * 4;
        *(float4*)&Xs[r * 68 + c4] = *(const float4*)&hbuf[(size_t)(row0 + r) * 64 + c4];
        *(float4*)&Ws[r * 68 + c4] = *(const float4*)&W1[(size_t)r * 64 + c4];
    }
    __syncthreads();
    // LayerNorm per row (4 threads/row)
    int tr = tid >> 2, tp = tid & 3;
    float s = 0.f;
    for (int c = tp * 16; c < tp * 16 + 16; c++) s += Xs[tr * 68 + c];
    redA[tr][tp] = s;
    __syncthreads();
    float mu = (redA[tr][0] + redA[tr][1] + redA[tr][2] + redA[tr][3]) * (1.0f / 64.0f);
    __syncthreads();
    float vs = 0.f;
    for (int c = tp * 16; c < tp * 16 + 16; c++) {
        float d = Xs[tr * 68 + c] - mu;
        vs += d * d;
    }
    redA[tr][tp] = vs;
    __syncthreads();
    float var = (redA[tr][0] + redA[tr][1] + redA[tr][2] + redA[tr][3]) * (1.0f / 64.0f);
    float rs = rsqrtf(var + 1e-5f);
    for (int c = tp * 16; c < tp * 16 + 16; c++)
        Xs[tr * 68 + c] = (Xs[tr * 68 + c] - mu) * rs * g[c] + b[c];
    __syncthreads();
    // gemm1: T1 = relu(Xs @ W1 + b1)
    int tm = tid >> 4, tn = tid & 15;
    float acc[4][4] = {};
#pragma unroll 8
    for (int kk = 0; kk < 64; kk++) {
        float4 bv = *(const float4*)&Ws[kk * 68 + tn * 4];
        float4 av = make_float4(Xs[(tm * 4 + 0) * 68 + kk], Xs[(tm * 4 + 1) * 68 + kk],
                                Xs[(tm * 4 + 2) * 68 + kk], Xs[(tm * 4 + 3) * 68 + kk]);
        FMA16(av, bv, acc)
    }
    __syncthreads();
#pragma unroll
    for (int ii = 0; ii < 4; ii++)
#pragma unroll
        for (int jj = 0; jj < 4; jj++)
            Xs[(tm * 4 + ii) * 68 + tn * 4 + jj] = fmaxf(acc[ii][jj] + b1[tn * 4 + jj], 0.f);
#pragma unroll
    for (int it = 0; it < 4; it++) {
        int idx = tid + it * 256;
        int r = idx >> 4, c4 = (idx & 15) * 4;
        *(float4*)&Ws[r * 68 + c4] = *(const float4*)&W2[(size_t)r * 64 + c4];
    }
    __syncthreads();
    // gemm2: out = T1 @ W2 + b2 + h
    float acc2[4][4] = {};
#pragma unroll 8
    for (int kk = 0; kk < 64; kk++) {
        float4 bv = *(const float4*)&Ws[kk * 68 + tn * 4];
        float4 av = make_float4(Xs[(tm * 4 + 0) * 68 + kk], Xs[(tm * 4 + 1) * 68 + kk],
                                Xs[(tm * 4 + 2) * 68 + kk], Xs[(tm * 4 + 3) * 68 + kk]);
        FMA16(av, bv, acc2)
    }
#pragma unroll
    for (int ii = 0; ii < 4; ii++) {
        int r = row0 + tm * 4 + ii;
#pragma unroll
        for (int jj = 0; jj < 4; jj++) {
            int c = tn * 4 + jj;
            float vv = acc2[ii][jj] + b2[c] + hbuf[(size_t)r * 64 + c];
            hbuf[(size_t)r * 64 + c] = vv;
            hist[(size_t)r * 320 + c] = vv;
        }
    }
}

// ------------------------- attention: one 64x64 bucket per block, tf32 mma -------------------------
__global__ void __launch_bounds__(256) attn_k(
    const float* __restrict__ q, const float* __restrict__ k, const float* __restrict__ v,
    const float* __restrict__ coords, const float* __restrict__ W2row)
{
    extern __shared__ unsigned sh[];
    unsigned* Qs = sh;                 // [64][68] tf32 Q[i][k]; reused as S/P [j][i]
    unsigned* Ks = sh + 64 * 68;       // [64][68] tf32 K[j][k]
    unsigned* Vs = sh + 2 * 64 * 68;   // [64][68] tf32 V[j][d]
    __shared__ int   nd[64];
    __shared__ float cx[64], cy[64], redm[4][64], reds[4][64];

    int tid = threadIdx.x;
    int blk = blockIdx.x, h = blockIdx.y, nh = blockIdx.z;
    int row = nh * 8 + h;
    const int* ord = g_order + row * NNODE + blk * 64;
    if (tid < 64) {
        int nn = ord[tid];
        nd[tid] = nn;
        cx[tid] = coords[nn * 3 + 0];
        cy[tid] = coords[nn * 3 + 1];
    }
    __syncthreads();
    for (int idx = tid; idx < 4096; idx += 256) {
        int i = idx >> 6, d = idx & 63;
        int base = nd[i] * HDIM + h * 64 + d;
        Qs[i * 68 + d] = f2tf(q[base]);
        Ks[i * 68 + d] = f2tf(k[base]);
        Vs[i * 68 + d] = f2tf(v[base]);
    }
    __syncthreads();

    int wid = tid >> 5, lane = tid & 31;
    int g = lane >> 2, t = lane & 3;
    int r0 = (wid & 3) * 16, c0 = (wid >> 2) * 32;

    float acc[4][4] = {};
#pragma unroll
    for (int ks = 0; ks < 8; ks++) {
        int k0 = ks * 8;
        unsigned a0 = Qs[(r0 + g) * 68 + k0 + t];
        unsigned a1 = Qs[(r0 + g + 8) * 68 + k0 + t];
        unsigned a2 = Qs[(r0 + g) * 68 + k0 + t + 4];
        unsigned a3 = Qs[(r0 + g + 8) * 68 + k0 + t + 4];
#pragma unroll
        for (int nt = 0; nt < 4; nt++) {
            int j = c0 + nt * 8 + g;
            unsigned b0 = Ks[j * 68 + k0 + t];
            unsigned b1 = Ks[j * 68 + k0 + t + 4];
            mma_tf32(acc[nt], a0, a1, a2, a3, b0, b1);
        }
    }
    float W0 = W2row[h * 2 + 0], W1 = W2row[h * 2 + 1];
    __syncthreads();

    float* Ss = (float*)Qs;
#pragma unroll
    for (int nt = 0; nt < 4; nt++) {
        int j0 = c0 + nt * 8 + 2 * t;
#pragma unroll
        for (int cr = 0; cr < 4; cr++) {
            int i = r0 + g + (cr >> 1) * 8;
            int j = j0 + (cr & 1);
            float dx = cx[i] - cx[j], dy = cy[i] - cy[j];
            Ss[j * 68 + i] = acc[nt][cr] - W0 * dx * dx - W1 * dy * dy;
        }
    }
    __syncthreads();

    int ci = tid & 63, seg = tid >> 6;
    float ml = -3.0e38f;
#pragma unroll
    for (int jj = 0; jj < 16; jj++) ml = fmaxf(ml, Ss[(seg * 16 + jj) * 68 + ci]);
    redm[seg][ci] = ml;
    __syncthreads();
    float mm = fmaxf(fmaxf(redm[0][ci], redm[1][ci]), fmaxf(redm[2][ci], redm[3][ci]));
    float ev[16];
    float sl = 0.f;
#pragma unroll
    for (int jj = 0; jj < 16; jj++) {
        float e = expf(Ss[(seg * 16 + jj) * 68 + ci] - mm);
        ev[jj] = e;
        sl += e;
    }
    reds[seg][ci] = sl;
    __syncthreads();
    float ssum = reds[0][ci] + reds[1][ci] + reds[2][ci] + reds[3][ci];
    float inv = 1.0f / ssum;
    if (seg == 0) g_lser[row * NNODE + nd[ci]] = mm + logf(ssum);
    unsigned* Ps = Qs;
#pragma unroll
    for (int jj = 0; jj < 16; jj++)
        Ps[(seg * 16 + jj) * 68 + ci] = f2tf(ev[jj] * inv);
    __syncthreads();

    float oacc[4][4] = {};
#pragma unroll
    for (int ks = 0; ks < 8; ks++) {
        int k0 = ks * 8;
        unsigned a0 = Ps[(k0 + t) * 68 + r0 + g];
        unsigned a1 = Ps[(k0 + t) * 68 + r0 + g + 8];
        unsigned a2 = Ps[(k0 + t + 4) * 68 + r0 + g];
        unsigned a3 = Ps[(k0 + t + 4) * 68 + r0 + g + 8];
#pragma unroll
        for (int nt = 0; nt < 4; nt++) {
            int n = c0 + nt * 8 + g;
            unsigned b0 = Vs[(k0 + t) * 68 + n];
            unsigned b1 = Vs[(k0 + t + 4) * 68 + n];
            mma_tf32(oacc[nt], a0, a1, a2, a3, b0, b1);
        }
    }
#pragma unroll
    for (int nt = 0; nt < 4; nt++) {
        int d0 = c0 + nt * 8 + 2 * t;
        int iA = r0 + g, iB = r0 + g + 8;
        *(float2*)&g_outr[((size_t)row * NNODE + nd[iA]) * 64 + d0] =
            make_float2(oacc[nt][0], oacc[nt][1]);
        *(float2*)&g_outr[((size_t)row * NNODE + nd[iB]) * 64 + d0] =
            make_float2(oacc[nt][2], oacc[nt][3]);
    }
}

// ------------------------- reductions + final projection -------------------------
__global__ void red1_k(const float* __restrict__ t) {   // t: [16384][32]
    __shared__ float sm[256];
    int blk = blockIdx.x, tid = threadIdx.x;
    int col = tid & 31, r0 = tid >> 5;
    float s = 0.f;
    for (int r = r0; r < 128; r += 8) s += t[(size_t)(blk * 128 + r) * 32 + col];
    sm[tid] = s;
    __syncthreads();
    for (int s2 = 4; s2; s2 >>= 1) {
        if (r0 < s2) sm[tid] += sm[tid + s2 * 32];
        __syncthreads();
    }
    if (r0 == 0) g_part[blk * 32 + col] = sm[col];
}

__global__ void red2_k(const float* __restrict__ pw, const float* __restrict__ pb,
                       float* __restrict__ out) {
    __shared__ float mean[32];
    int t = threadIdx.x;
    if (t < 32) {
        float s = 0.f;
        for (int b = 0; b < 128; b++) s += g_part[b * 32 + t];
        mean[t] = s * (1.0f / 16384.0f);
    }
    __syncthreads();
    if (t < 32) {
        float s = pb[t];
        for (int c = 0; c < 32; c++) s += mean[c] * pw[c * 32 + t];
        out[t] = s;
    }
}

// ------------------------- host orchestration -------------------------
extern "C" void kernel_launch(void* const* d_in, const int* in_sizes, int n_in,
                              void* d_out, int out_size)
{
    const float* x      = (const float*)d_in[0];
    const float* coords = (const float*)d_in[1];
    const float* regions= (const float*)d_in[3];
    const float* fe_w1  = (const float*)d_in[4];
    const float* fe_b1  = (const float*)d_in[5];
    const float* fe_w2  = (const float*)d_in[6];
    const float* fe_b2  = (const float*)d_in[7];
    const float* ln1_g  = (const float*)d_in[8];
    const float* ln1_b  = (const float*)d_in[9];
    const float* wq     = (const float*)d_in[10];
    const float* wk     = (const float*)d_in[11];
    const float* wv     = (const float*)d_in[12];
    const float* wrpe   = (const float*)d_in[13];
    const float* ow     = (const float*)d_in[14];
    const float* ob     = (const float*)d_in[15];
    const float* ln2_g  = (const float*)d_in[16];
    const float* ln2_b  = (const float*)d_in[17];
    const float* f1w    = (const float*)d_in[18];
    const float* f1b    = (const float*)d_in[19];
    const float* f2w    = (const float*)d_in[20];
    const float* f2b    = (const float*)d_in[21];
    const float* Wcat   = (const float*)d_in[22];
    const float* m1w    = (const float*)d_in[23];
    const float* m1b    = (const float*)d_in[24];
    const float* mlng   = (const float*)d_in[25];
    const float* mlnb   = (const float*)d_in[26];
    const float* m2w    = (const float*)d_in[27];
    const float* m2b    = (const float*)d_in[28];
    const float* pw     = (const float*)d_in[29];
    const float* pb     = (const float*)d_in[30];
    float* out = (float*)d_out;

    cudaFuncSetAttribute(bucket_k, cudaFuncAttributeMaxDynamicSharedMemorySize, 65536);
    cudaFuncSetAttribute(attn_k,   cudaFuncAttributeMaxDynamicSharedMemorySize, 52224);

    float *p_h, *p_xn, *p_tmp, *p_hist, *p_q, *p_k, *p_v;
    float *p_t0, *p_u, *p_u2, *p_t, *p_w2;
    cudaGetSymbolAddress((void**)&p_h,    g_h);
    cudaGetSymbolAddress((void**)&p_xn,   g_xn);
    cudaGetSymbolAddress((void**)&p_tmp,  g_tmp);
    cudaGetSymbolAddress((void**)&p_hist, g_hist);
    cudaGetSymbolAddress((void**)&p_q,    g_q);
    cudaGetSymbolAddress((void**)&p_k,    g_k);
    cudaGetSymbolAddress((void**)&p_v,    g_v);
    cudaGetSymbolAddress((void**)&p_t0,   g_t0);
    cudaGetSymbolAddress((void**)&p_u,    g_u);
    cudaGetSymbolAddress((void**)&p_u2,   g_u2);
    cudaGetSymbolAddress((void**)&p_t,    g_t);
    cudaGetSymbolAddress((void**)&p_w2,   g_W2);

    const int M = NNODE;
    rank_k<<<dim3(256, 2), 256>>>(coords);
    bucket_k<<<16, 1024, 65536>>>(regions);
    w2all_k<<<4, 128>>>(wrpe);

    gemm_k<<<dim3(256, 1), 256>>>(x, fe_w1, p_tmp, nullptr, 0, fe_b1, nullptr, M, 64, 16, 1.f, 1);
    gemm_k<<<dim3(256, 1), 256>>>(p_tmp, fe_w2, p_h, p_hist, 320, fe_b2, nullptr, M, 64, 64, 1.f, 0);

    for (int l = 0; l < 4; l++) {
        ln64_k<<<2048, 256>>>(p_h, p_xn, ln1_g + l * 64, ln1_b + l * 64);
        qkv_k<<<dim3(256, 24), 256>>>(p_xn,
                                      wq + (size_t)l * 64 * 512,
                                      wk + (size_t)l * 64 * 512,
                                      wv + (size_t)l * 64 * 512,
                                      p_q, p_k, p_v);
        attn_k<<<dim3(256, 8, 2), 256, 52224>>>(p_q, p_k, p_v, coords, p_w2 + l * 16);
        outproj_k<<<256, 256>>>(ow + (size_t)l * 512 * 64, ob + l * 64, p_h);
        ffn_k<<<256, 256>>>(p_h, ln2_g + l * 64, ln2_b + l * 64,
                            f1w + (size_t)l * 64 * 64, f1b + l * 64,
                            f2w + (size_t)l * 64 * 64, f2b + l * 64,
                            p_hist + (l + 1) * 64);
    }

    gemm_k<<<dim3(256, 1), 256>>>(p_hist, Wcat, p_t0, nullptr, 0, nullptr, nullptr, M, 32, 320, 1.f, 2);
    gemm_k<<<dim3(256, 4), 256>>>(p_t0, m1w, p_u, nullptr, 0, m1b, nullptr, M, 256, 32, 1.f, 0);
    ln256t_k<<<16384, 256>>>(p_u, p_u2, mlng, mlnb);
    gemm_k<<<dim3(256, 1), 256>>>(p_u2, m2w, p_t, nullptr, 0, m2b, p_t0, M, 32, 256, 1.f, 0);
    red1_k<<<128, 256>>>(p_t);
    red2_k<<<1, 256>>>(pw, pb, out);
}

// round 5
// speedup vs baseline: 1.4487x; 1.0814x over previous
#include <cuda_runtime.h>
#include <cuda_bf16.h>
#include <math.h>

#define NNODE 16384
#define HEADS 8
#define DIM   64
#define HDIM  512
#define KBINS 40960

// ------------------------- device scratch (no allocs allowed) -------------------------
__device__ int   g_rank[2][NNODE];
__device__ int   g_order[16 * NNODE];
__device__ float g_h[NNODE * DIM];
__device__ float g_tmp[NNODE * DIM];
__device__ float g_hist[NNODE * 320];
__device__ float g_q[NNODE * HDIM];
__device__ float g_k[NNODE * HDIM];
__device__ float g_v[NNODE * HDIM];
__device__ float g_outr[16 * NNODE * DIM];   // [nh*8+h][node][d]
__device__ float g_lser[16 * NNODE];
__device__ float g_W2[4 * 16];               // [layer][h][c]
__device__ float g_t0[NNODE * 32];
__device__ float g_u [NNODE * 256];
__device__ float g_u2[NNODE * 256];
__device__ float g_t [NNODE * 32];
__device__ float g_part[128 * 32];

// sorting scratch
__device__ int r_hist[2][NNODE];
__device__ int r_base[2][NNODE];
__device__ int r_cnt [2][NNODE];
__device__ int r_slot[2][NNODE];
__device__ int b_keys[16][NNODE];
__device__ int b_hist[16][KBINS];
__device__ int b_base[16][KBINS];
__device__ int b_cnt [16][KBINS];
__device__ int b_slot[16][NNODE];
__device__ int g_maxre[16];

// ------------------------- tf32 helpers -------------------------
__device__ __forceinline__ unsigned f2tf(float f) {
    unsigned u;
    asm("cvt.rna.tf32.f32 %0, %1;" : "=r"(u) : "f"(f));
    return u;
}

__device__ __forceinline__ void mma_tf32(float c[4], unsigned a0, unsigned a1,
                                         unsigned a2, unsigned a3,
                                         unsigned b0, unsigned b1) {
    asm volatile(
        "mma.sync.aligned.m16n8k8.row.col.f32.tf32.tf32.f32 "
        "{%0,%1,%2,%3}, {%4,%5,%6,%7}, {%8,%9}, {%0,%1,%2,%3};"
        : "+f"(c[0]), "+f"(c[1]), "+f"(c[2]), "+f"(c[3])
        : "r"(a0), "r"(a1), "r"(a2), "r"(a3), "r"(b0), "r"(b1));
}

// ------------------------- zero all counting scratch -------------------------
__global__ void zero_k() {
    int gid = blockIdx.x * 256 + threadIdx.x;
    int stride = gridDim.x * 256;
    for (int i = gid; i < 2 * NNODE; i += stride) { ((int*)r_hist)[i] = 0; ((int*)r_cnt)[i] = 0; }
    for (int i = gid; i < 16 * KBINS; i += stride) { ((int*)b_hist)[i] = 0; ((int*)b_cnt)[i] = 0; }
    if (gid < 16) g_maxre[gid] = 0;
}

// ------------------------- coordinate ranks via counting -------------------------
__device__ __forceinline__ int coord_bin(float c) {
    int u = (int)(c * 16384.0f);
    return min(16383, max(0, u));
}

__global__ void rank_hist_k(const float* __restrict__ coords) {
    int axis = blockIdx.y;
    int i = blockIdx.x * 256 + threadIdx.x;
    int u = coord_bin(coords[i * 3 + axis]);
    atomicAdd(&r_hist[axis][u], 1);
}

// generic per-row exclusive scan (1024 threads/block)
__global__ void __launch_bounds__(1024) scan_k(const int* __restrict__ hist,
                                               int* __restrict__ base,
                                               int nbins, int rowstride) {
    __shared__ int ss[1024];
    int row = blockIdx.x;
    const int* h = hist + (size_t)row * rowstride;
    int* bs = base + (size_t)row * rowstride;
    int t = threadIdx.x;
    int chunk = (nbins + 1023) >> 10;
    int b0 = t * chunk;
    int s = 0;
    for (int m = 0; m < chunk; m++) { int idx = b0 + m; if (idx < nbins) s += h[idx]; }
    ss[t] = s;
    __syncthreads();
    for (int d = 1; d < 1024; d <<= 1) {
        int v = (t >= d) ? ss[t - d] : 0;
        __syncthreads();
        ss[t] += v;
        __syncthreads();
    }
    int run = (t > 0) ? ss[t - 1] : 0;
    for (int m = 0; m < chunk; m++) {
        int idx = b0 + m;
        if (idx < nbins) { bs[idx] = run; run += h[idx]; }
    }
}

__global__ void rank_place_k(const float* __restrict__ coords) {
    int axis = blockIdx.y;
    int i = blockIdx.x * 256 + threadIdx.x;
    int u = coord_bin(coords[i * 3 + axis]);
    int slot = r_base[axis][u] + atomicAdd(&r_cnt[axis][u], 1);
    r_slot[axis][slot] = i;
}

__global__ void rank_rank_k(const float* __restrict__ coords) {
    int axis = blockIdx.y;
    int i = blockIdx.x * 256 + threadIdx.x;
    float ci = coords[i * 3 + axis];
    int u = coord_bin(ci);
    int b = r_base[axis][u], n = r_hist[axis][u];
    int r = 0;
    for (int m = 0; m < n; m++) {
        int j = r_slot[axis][b + m];
        float cj = coords[j * 3 + axis];
        r += (int)((cj < ci) || (cj == ci && j < i));
    }
    g_rank[axis][i] = b + r;
}

// ------------------------- bucket order via counting sort -------------------------
__global__ void key1_k(const float* __restrict__ regions) {
    __shared__ int smax[256];
    int row = blockIdx.y;
    int nh = row >> 3, h = row & 7;
    float qe = 16384.0f / regions[nh * 16 + h];
    float qp = 16384.0f / regions[nh * 16 + 8 + h];
    int i = blockIdx.x * 256 + threadIdx.x;
    int re = (int)floorf((float)g_rank[0][i] / qe) + 1;
    int rp = (int)floorf((float)g_rank[1][i] / qp) + 1;
    b_keys[row][i] = (rp << 16) | re;
    smax[threadIdx.x] = re;
    __syncthreads();
    for (int s = 128; s > 0; s >>= 1) {
        if (threadIdx.x < s) smax[threadIdx.x] = max(smax[threadIdx.x], smax[threadIdx.x + s]);
        __syncthreads();
    }
    if (threadIdx.x == 0) atomicMax(&g_maxre[row], smax[0]);
}

__global__ void key2_k() {
    int row = blockIdx.y;
    int i = blockIdx.x * 256 + threadIdx.x;
    int nb = (int)ceilf(log2f((float)g_maxre[row] + 1.0f));
    int v = b_keys[row][i];
    int key = ((v >> 16) << nb) | (v & 0xffff);
    b_keys[row][i] = key;
    atomicAdd(&b_hist[row][key], 1);
}

__global__ void bucket_place_k() {
    int row = blockIdx.y;
    int i = blockIdx.x * 256 + threadIdx.x;
    int key = b_keys[row][i];
    int slot = b_base[row][key] + atomicAdd(&b_cnt[row][key], 1);
    b_slot[row][slot] = i;
}

__global__ void bucket_pos_k() {
    int row = blockIdx.y;
    int i = blockIdx.x * 256 + threadIdx.x;
    int key = b_keys[row][i];
    int b = b_base[row][key], n = b_hist[row][key];
    int r = 0;
    for (int m = 0; m < n; m++) r += (int)(b_slot[row][b + m] < i);
    g_order[row * NNODE + b + r] = i;
}

// ------------------------- RPE distance weights (all 4 layers) -------------------------
__global__ void w2all_k(const float* __restrict__ wrpe) {   // [4][512][16]
    __shared__ float sq[128];
    int l = blockIdx.x;
    const float* w = wrpe + (size_t)l * 512 * 16;
    int t = threadIdx.x;                 // 128 threads
    int h = t >> 4, m = t & 15;
    float s = 0.f;
    for (int d = 0; d < 64; d++) s += w[(h * 64 + d) * 16 + m];
    float om = s * (1.0f / 64.0f);
    sq[t] = om * om;
    __syncthreads();
    if (t < 16) {
        int hh = t >> 1, c = t & 1;
        float ww = 0.f;
        for (int kk = 0; kk < 8; kk++) ww += sq[hh * 16 + c * 8 + kk];
        g_W2[l * 16 + t] = ww;
    }
}

// ------------------------- LayerNorm over 256 + tanh -------------------------
__global__ void ln256t_k(const float* __restrict__ in, float* __restrict__ out,
                         const float* __restrict__ g, const float* __restrict__ b) {
    __shared__ float red[256];
    int row = blockIdx.x, t = threadIdx.x;
    float x = in[(size_t)row * 256 + t];
    red[t] = x;
    __syncthreads();
    for (int s = 128; s; s >>= 1) { if (t < s) red[t] += red[t + s]; __syncthreads(); }
    float mu = red[0] * (1.0f / 256.0f);
    __syncthreads();
    float d = x - mu;
    red[t] = d * d;
    __syncthreads();
    for (int s = 128; s; s >>= 1) { if (t < s) red[t] += red[t + s]; __syncthreads(); }
    float rs = rsqrtf(red[0] * (1.0f / 256.0f) + 1e-5f);
    out[(size_t)row * 256 + t] = tanhf(d * rs * g[t] + b[t]);
}

// ------------------------- scalar FFMA SGEMM (exact; small shapes) -------------------------
#define FMA16(av, bv, acc)                                                         \
    acc[0][0]+=av.x*bv.x; acc[0][1]+=av.x*bv.y; acc[0][2]+=av.x*bv.z; acc[0][3]+=av.x*bv.w; \
    acc[1][0]+=av.y*bv.x; acc[1][1]+=av.y*bv.y; acc[1][2]+=av.y*bv.z; acc[1][3]+=av.y*bv.w; \
    acc[2][0]+=av.z*bv.x; acc[2][1]+=av.z*bv.y; acc[2][2]+=av.z*bv.z; acc[2][3]+=av.z*bv.w; \
    acc[3][0]+=av.w*bv.x; acc[3][1]+=av.w*bv.y; acc[3][2]+=av.w*bv.z; acc[3][3]+=av.w*bv.w;

__global__ void __launch_bounds__(256) gemm_k(
    const float* __restrict__ A, const float* __restrict__ B, float* __restrict__ C,
    float* __restrict__ C2, int ldc2,
    const float* __restrict__ bias, const float* __restrict__ resid,
    int M, int N, int K, float alpha, int act)
{
    __shared__ float As[16][68];
    __shared__ float Bs[16][68];
    int tid = threadIdx.x;
    int row0 = blockIdx.x * 64, col0 = blockIdx.y * 64;
    int tm = tid >> 4, tn = tid & 15;
    int arow = tid >> 2, ac = tid & 3;
    int bk = tid >> 4, bn = tid & 15;
    float acc[4][4] = {};
    for (int k0 = 0; k0 < K; k0 += 16) {
        float4 a = *(const float4*)&A[(size_t)(row0 + arow) * K + k0 + ac * 4];
        As[ac * 4 + 0][arow] = a.x; As[ac * 4 + 1][arow] = a.y;
        As[ac * 4 + 2][arow] = a.z; As[ac * 4 + 3][arow] = a.w;
        int bcol = col0 + bn * 4;
        float4 bv = make_float4(0.f, 0.f, 0.f, 0.f);
        if (bcol < N) bv = *(const float4*)&B[(size_t)(k0 + bk) * N + bcol];
        *(float4*)&Bs[bk][bn * 4] = bv;
        __syncthreads();
#pragma unroll
        for (int kk = 0; kk < 16; kk++) {
            float4 av = *(const float4*)&As[kk][tm * 4];
            float4 bw = *(const float4*)&Bs[kk][tn * 4];
            FMA16(av, bw, acc)
        }
        __syncthreads();
    }
#pragma unroll
    for (int ii = 0; ii < 4; ii++) {
        int r = row0 + tm * 4 + ii;
#pragma unroll
        for (int jj = 0; jj < 4; jj++) {
            int ccol = col0 + tn * 4 + jj;
            if (ccol < N) {
                float vv = alpha * acc[ii][jj];
                if (bias) vv += bias[ccol];
                if (act == 1) vv = fmaxf(vv, 0.f);
                else if (act == 2) vv = tanhf(vv);
                if (resid) vv += resid[(size_t)r * N + ccol];
                C[(size_t)r * N + ccol] = vv;
                if (C2) C2[(size_t)r * ldc2 + ccol] = vv;
            }
        }
    }
}

// ------------------------- fused LN1 + QKV tf32 GEMM: grid (256, 24) -------------------------
__global__ void __launch_bounds__(256) qkv_k(
    const float* __restrict__ hin,
    const float* __restrict__ lng, const float* __restrict__ lnb,
    const float* __restrict__ wq, const float* __restrict__ wk, const float* __restrict__ wv,
    float* __restrict__ q, float* __restrict__ k, float* __restrict__ v)
{
    __shared__ unsigned As[64 * 68];
    __shared__ unsigned Bs[64 * 68];
    __shared__ float redA[64][4];
    float* AsF = (float*)As;
    int tid = threadIdx.x;
    int sel = blockIdx.y >> 3, hh = blockIdx.y & 7;
    const float* B = sel == 0 ? wq : (sel == 1 ? wk : wv);
    float* C = sel == 0 ? q : (sel == 1 ? k : v);
    float alpha = sel == 0 ? 0.125f : 1.0f;
    int row0 = blockIdx.x * 64, col0 = hh * 64;
    int wid = tid >> 5, lane = tid & 31;
    int g = lane >> 2, t = lane & 3;
    int r0 = (wid & 3) * 16, c0 = (wid >> 2) * 32;

    // stage h tile as float
#pragma unroll
    for (int it = 0; it < 4; it++) {
        int idx = tid + it * 256;
        int r = idx >> 4, c4 = (idx & 15) * 4;
        *(float4*)&AsF[r * 68 + c4] = *(const float4*)&hin[(size_t)(row0 + r) * 64 + c4];
    }
    __syncthreads();
    // LayerNorm per row
    int tr = tid >> 2, tp = tid & 3;
    float s = 0.f;
    for (int c = tp * 16; c < tp * 16 + 16; c++) s += AsF[tr * 68 + c];
    redA[tr][tp] = s;
    __syncthreads();
    float mu = (redA[tr][0] + redA[tr][1] + redA[tr][2] + redA[tr][3]) * (1.0f / 64.0f);
    __syncthreads();
    float vs = 0.f;
    for (int c = tp * 16; c < tp * 16 + 16; c++) {
        float d = AsF[tr * 68 + c] - mu;
        vs += d * d;
    }
    redA[tr][tp] = vs;
    __syncthreads();
    float var = (redA[tr][0] + redA[tr][1] + redA[tr][2] + redA[tr][3]) * (1.0f / 64.0f);
    float rs = rsqrtf(var + 1e-5f);
    for (int c = tp * 16; c < tp * 16 + 16; c++)
        AsF[tr * 68 + c] = (AsF[tr * 68 + c] - mu) * rs * lng[c] + lnb[c];
    __syncthreads();
    // convert normalized tile to tf32 in place + stage B
    for (int e = tid; e < 4096; e += 256) {
        int r = e >> 6, c = e & 63;
        As[r * 68 + c] = f2tf(AsF[r * 68 + c]);
    }
#pragma unroll
    for (int it = 0; it < 4; it++) {
        int idx = tid + it * 256;
        int r = idx >> 4, c4 = (idx & 15) * 4;
        float4 bv = *(const float4*)&B[(size_t)r * 512 + col0 + c4];
        Bs[r * 68 + c4 + 0] = f2tf(bv.x); Bs[r * 68 + c4 + 1] = f2tf(bv.y);
        Bs[r * 68 + c4 + 2] = f2tf(bv.z); Bs[r * 68 + c4 + 3] = f2tf(bv.w);
    }
    __syncthreads();
    float acc[4][4] = {};
#pragma unroll
    for (int ks = 0; ks < 8; ks++) {
        int k0 = ks * 8;
        unsigned a0 = As[(r0 + g) * 68 + k0 + t];
        unsigned a1 = As[(r0 + g + 8) * 68 + k0 + t];
        unsigned a2 = As[(r0 + g) * 68 + k0 + t + 4];
        unsigned a3 = As[(r0 + g + 8) * 68 + k0 + t + 4];
#pragma unroll
        for (int nt = 0; nt < 4; nt++) {
            int n = c0 + nt * 8 + g;
            unsigned b0 = Bs[(k0 + t) * 68 + n];
            unsigned b1 = Bs[(k0 + t + 4) * 68 + n];
            mma_tf32(acc[nt], a0, a1, a2, a3, b0, b1);
        }
    }
#pragma unroll
    for (int nt = 0; nt < 4; nt++) {
#pragma unroll
        for (int cr = 0; cr < 4; cr++) {
            int r = row0 + r0 + g + (cr >> 1) * 8;
            int ccol = col0 + c0 + nt * 8 + 2 * t + (cr & 1);
            C[(size_t)r * 512 + ccol] = alpha * acc[nt][cr];
        }
    }
}

// ------------------------- out-projection with fused lse-combine (K=512) -------------------------
__global__ void __launch_bounds__(256) outproj_k(
    const float* __restrict__ ow, const float* __restrict__ ob, float* __restrict__ hbuf)
{
    __shared__ unsigned As[64 * 68];
    __shared__ unsigned Bs[64 * 68];
    __shared__ float w0s[64], w1s[64];
    int tid = threadIdx.x;
    int row0 = blockIdx.x * 64;
    int wid = tid >> 5, lane = tid & 31;
    int g = lane >> 2, t = lane & 3;
    int r0 = (wid & 3) * 16, c0 = (wid >> 2) * 32;
    float acc[4][4] = {};
    for (int h = 0; h < 8; h++) {
        __syncthreads();
        if (tid < 64) {
            int node = row0 + tid;
            float l0 = g_lser[h * NNODE + node];
            float l1 = g_lser[(8 + h) * NNODE + node];
            float m = fmaxf(l0, l1);
            float e0 = expf(l0 - m), e1 = expf(l1 - m);
            float inv = 1.0f / (e0 + e1);
            w0s[tid] = e0 * inv;
            w1s[tid] = e1 * inv;
        }
        __syncthreads();
#pragma unroll
        for (int it = 0; it < 4; it++) {
            int idx = tid + it * 256;
            int r = idx >> 4, c4 = (idx & 15) * 4;
            int node = row0 + r;
            float4 o0 = *(const float4*)&g_outr[((size_t)h * NNODE + node) * 64 + c4];
            float4 o1 = *(const float4*)&g_outr[((size_t)(8 + h) * NNODE + node) * 64 + c4];
            float w0 = w0s[r], w1 = w1s[r];
            As[r * 68 + c4 + 0] = f2tf(w0 * o0.x + w1 * o1.x);
            As[r * 68 + c4 + 1] = f2tf(w0 * o0.y + w1 * o1.y);
            As[r * 68 + c4 + 2] = f2tf(w0 * o0.z + w1 * o1.z);
            As[r * 68 + c4 + 3] = f2tf(w0 * o0.w + w1 * o1.w);
            float4 bv = *(const float4*)&ow[(size_t)(h * 64 + r) * 64 + c4];
            Bs[r * 68 + c4 + 0] = f2tf(bv.x); Bs[r * 68 + c4 + 1] = f2tf(bv.y);
            Bs[r * 68 + c4 + 2] = f2tf(bv.z); Bs[r * 68 + c4 + 3] = f2tf(bv.w);
        }
        __syncthreads();
#pragma unroll
        for (int ks = 0; ks < 8; ks++) {
            int k0 = ks * 8;
            unsigned a0 = As[(r0 + g) * 68 + k0 + t];
            unsigned a1 = As[(r0 + g + 8) * 68 + k0 + t];
            unsigned a2 = As[(r0 + g) * 68 + k0 + t + 4];
            unsigned a3 = As[(r0 + g + 8) * 68 + k0 + t + 4];
#pragma unroll
            for (int nt = 0; nt < 4; nt++) {
                int n = c0 + nt * 8 + g;
                unsigned b0 = Bs[(k0 + t) * 68 + n];
                unsigned b1 = Bs[(k0 + t + 4) * 68 + n];
                mma_tf32(acc[nt], a0, a1, a2, a3, b0, b1);
            }
        }
    }
#pragma unroll
    for (int nt = 0; nt < 4; nt++) {
#pragma unroll
        for (int cr = 0; cr < 4; cr++) {
            int r = row0 + r0 + g + (cr >> 1) * 8;
            int ccol = c0 + nt * 8 + 2 * t + (cr & 1);
            float vv = acc[nt][cr] + ob[ccol] + hbuf[(size_t)r * 64 + ccol];
            hbuf[(size_t)r * 64 + ccol] = vv;
        }
    }
}

// ------------------------- fused LN2 + FFN + residual + hist (exact FFMA) -------------------------
__global__ void __launch_bounds__(256) ffn_k(
    float* __restrict__ hbuf, const float* __restrict__ g, const float* __restrict__ b,
    const float* __restrict__ W1, const float* __restrict__ b1,
    const float* __restrict__ W2, const float* __restrict__ b2,
    float* __restrict__ hist)
{
    __shared__ float Xs[64 * 68];
    __shared__ float Ws[64 * 68];
    __shared__ float redA[64][4];
    int tid = threadIdx.x;
    int row0 = blockIdx.x * 64;
#pragma unroll
    for (int it = 0; it < 4; it++) {
        int idx = tid + it * 256;
        int r = idx >> 4, c4 = (idx & 15) * 4;
        *(float4*)&Xs[r * 68 + c4] = *(const float4*)&hbuf[(size_t)(row0 + r) * 64 + c4];
        *(float4*)&Ws[r * 68 + c4] = *(const float4*)&W1[(size_t)r * 64 + c4];
    }
    __syncthreads();
    int tr = tid >> 2, tp = tid & 3;
    float s = 0.f;
    for (int c = tp * 16; c < tp * 16 + 16; c++) s += Xs[tr * 68 + c];
    redA[tr][tp] = s;
    __syncthreads();
    float mu = (redA[tr][0] + redA[tr][1] + redA[tr][2] + redA[tr][3]) * (1.0f / 64.0f);
    __syncthreads();
    float vs = 0.f;
    for (int c = tp * 16; c < tp * 16 + 16; c++) {
        float d = Xs[tr * 68 + c] - mu;
        vs += d * d;
    }
    redA[tr][tp] = vs;
    __syncthreads();
    float var = (redA[tr][0] + redA[tr][1] + redA[tr][2] + redA[tr][3]) * (1.0f / 64.0f);
    float rs = rsqrtf(var + 1e-5f);
    for (int c = tp * 16; c < tp * 16 + 16; c++)
        Xs[tr * 68 + c] = (Xs[tr * 68 + c] - mu) * rs * g[c] + b[c];
    __syncthreads();
    int tm = tid >> 4, tn = tid & 15;
    float acc[4][4] = {};
#pragma unroll 8
    for (int kk = 0; kk < 64; kk++) {
        float4 bv = *(const float4*)&Ws[kk * 68 + tn * 4];
        float4 av = make_float4(Xs[(tm * 4 + 0) * 68 + kk], Xs[(tm * 4 + 1) * 68 + kk],
                                Xs[(tm * 4 + 2) * 68 + kk], Xs[(tm * 4 + 3) * 68 + kk]);
        FMA16(av, bv, acc)
    }
    __syncthreads();
#pragma unroll
    for (int ii = 0; ii < 4; ii++)
#pragma unroll
        for (int jj = 0; jj < 4; jj++)
            Xs[(tm * 4 + ii) * 68 + tn * 4 + jj] = fmaxf(acc[ii][jj] + b1[tn * 4 + jj], 0.f);
#pragma unroll
    for (int it = 0; it < 4; it++) {
        int idx = tid + it * 256;
        int r = idx >> 4, c4 = (idx & 15) * 4;
        *(float4*)&Ws[r * 68 + c4] = *(const float4*)&W2[(size_t)r * 64 + c4];
    }
    __syncthreads();
    float acc2[4][4] = {};
#pragma unroll 8
    for (int kk = 0; kk < 64; kk++) {
        float4 bv = *(const float4*)&Ws[kk * 68 + tn * 4];
        float4 av = make_float4(Xs[(tm * 4 + 0) * 68 + kk], Xs[(tm * 4 + 1) * 68 + kk],
                                Xs[(tm * 4 + 2) * 68 + kk], Xs[(tm * 4 + 3) * 68 + kk]);
        FMA16(av, bv, acc2)
    }
#pragma unroll
    for (int ii = 0; ii < 4; ii++) {
        int r = row0 + tm * 4 + ii;
#pragma unroll
        for (int jj = 0; jj < 4; jj++) {
            int c = tn * 4 + jj;
            float vv = acc2[ii][jj] + b2[c] + hbuf[(size_t)r * 64 + c];
            hbuf[(size_t)r * 64 + c] = vv;
            hist[(size_t)r * 320 + c] = vv;
        }
    }
}

// ------------------------- attention: one 64x64 bucket per block, tf32 mma -------------------------
__global__ void __launch_bounds__(256) attn_k(
    const float* __restrict__ q, const float* __restrict__ k, const float* __restrict__ v,
    const float* __restrict__ coords, const float* __restrict__ W2row)
{
    extern __shared__ unsigned sh[];
    unsigned* Qs = sh;
    unsigned* Ks = sh + 64 * 68;
    unsigned* Vs = sh + 2 * 64 * 68;
    __shared__ int   nd[64];
    __shared__ float cx[64], cy[64], redm[4][64], reds[4][64];

    int tid = threadIdx.x;
    int blk = blockIdx.x, h = blockIdx.y, nh = blockIdx.z;
    int row = nh * 8 + h;
    const int* ord = g_order + row * NNODE + blk * 64;
    if (tid < 64) {
        int nn = ord[tid];
        nd[tid] = nn;
        cx[tid] = coords[nn * 3 + 0];
        cy[tid] = coords[nn * 3 + 1];
    }
    __syncthreads();
    for (int idx = tid; idx < 4096; idx += 256) {
        int i = idx >> 6, d = idx & 63;
        int base = nd[i] * HDIM + h * 64 + d;
        Qs[i * 68 + d] = f2tf(q[base]);
        Ks[i * 68 + d] = f2tf(k[base]);
        Vs[i * 68 + d] = f2tf(v[base]);
    }
    __syncthreads();

    int wid = tid >> 5, lane = tid & 31;
    int g = lane >> 2, t = lane & 3;
    int r0 = (wid & 3) * 16, c0 = (wid >> 2) * 32;

    float acc[4][4] = {};
#pragma unroll
    for (int ks = 0; ks < 8; ks++) {
        int k0 = ks * 8;
        unsigned a0 = Qs[(r0 + g) * 68 + k0 + t];
        unsigned a1 = Qs[(r0 + g + 8) * 68 + k0 + t];
        unsigned a2 = Qs[(r0 + g) * 68 + k0 + t + 4];
        unsigned a3 = Qs[(r0 + g + 8) * 68 + k0 + t + 4];
#pragma unroll
        for (int nt = 0; nt < 4; nt++) {
            int j = c0 + nt * 8 + g;
            unsigned b0 = Ks[j * 68 + k0 + t];
            unsigned b1 = Ks[j * 68 + k0 + t + 4];
            mma_tf32(acc[nt], a0, a1, a2, a3, b0, b1);
        }
    }
    float W0 = W2row[h * 2 + 0], W1 = W2row[h * 2 + 1];
    __syncthreads();

    float* Ss = (float*)Qs;
#pragma unroll
    for (int nt = 0; nt < 4; nt++) {
        int j0 = c0 + nt * 8 + 2 * t;
#pragma unroll
        for (int cr = 0; cr < 4; cr++) {
            int i = r0 + g + (cr >> 1) * 8;
            int j = j0 + (cr & 1);
            float dx = cx[i] - cx[j], dy = cy[i] - cy[j];
            Ss[j * 68 + i] = acc[nt][cr] - W0 * dx * dx - W1 * dy * dy;
        }
    }
    __syncthreads();

    int ci = tid & 63, seg = tid >> 6;
    float ml = -3.0e38f;
#pragma unroll
    for (int jj = 0; jj < 16; jj++) ml = fmaxf(ml, Ss[(seg * 16 + jj) * 68 + ci]);
    redm[seg][ci] = ml;
    __syncthreads();
    float mm = fmaxf(fmaxf(redm[0][ci], redm[1][ci]), fmaxf(redm[2][ci], redm[3][ci]));
    float ev[16];
    float sl = 0.f;
#pragma unroll
    for (int jj = 0; jj < 16; jj++) {
        float e = expf(Ss[(seg * 16 + jj) * 68 + ci] - mm);
        ev[jj] = e;
        sl += e;
    }
    reds[seg][ci] = sl;
    __syncthreads();
    float ssum = reds[0][ci] + reds[1][ci] + reds[2][ci] + reds[3][ci];
    float inv = 1.0f / ssum;
    if (seg == 0) g_lser[row * NNODE + nd[ci]] = mm + logf(ssum);
    unsigned* Ps = Qs;
#pragma unroll
    for (int jj = 0; jj < 16; jj++)
        Ps[(seg * 16 + jj) * 68 + ci] = f2tf(ev[jj] * inv);
    __syncthreads();

    float oacc[4][4] = {};
#pragma unroll
    for (int ks = 0; ks < 8; ks++) {
        int k0 = ks * 8;
        unsigned a0 = Ps[(k0 + t) * 68 + r0 + g];
        unsigned a1 = Ps[(k0 + t) * 68 + r0 + g + 8];
        unsigned a2 = Ps[(k0 + t + 4) * 68 + r0 + g];
        unsigned a3 = Ps[(k0 + t + 4) * 68 + r0 + g + 8];
#pragma unroll
        for (int nt = 0; nt < 4; nt++) {
            int n = c0 + nt * 8 + g;
            unsigned b0 = Vs[(k0 + t) * 68 + n];
            unsigned b1 = Vs[(k0 + t + 4) * 68 + n];
            mma_tf32(oacc[nt], a0, a1, a2, a3, b0, b1);
        }
    }
#pragma unroll
    for (int nt = 0; nt < 4; nt++) {
        int d0 = c0 + nt * 8 + 2 * t;
        int iA = r0 + g, iB = r0 + g + 8;
        *(float2*)&g_outr[((size_t)row * NNODE + nd[iA]) * 64 + d0] =
            make_float2(oacc[nt][0], oacc[nt][1]);
        *(float2*)&g_outr[((size_t)row * NNODE + nd[iB]) * 64 + d0] =
            make_float2(oacc[nt][2], oacc[nt][3]);
    }
}

// ------------------------- reductions + final projection -------------------------
__global__ void red1_k(const float* __restrict__ t) {
    __shared__ float sm[256];
    int blk = blockIdx.x, tid = threadIdx.x;
    int col = tid & 31, r0 = tid >> 5;
    float s = 0.f;
    for (int r = r0; r < 128; r += 8) s += t[(size_t)(blk * 128 + r) * 32 + col];
    sm[tid] = s;
    __syncthreads();
    for (int s2 = 4; s2; s2 >>= 1) {
        if (r0 < s2) sm[tid] += sm[tid + s2 * 32];
        __syncthreads();
    }
    if (r0 == 0) g_part[blk * 32 + col] = sm[col];
}

__global__ void red2_k(const float* __restrict__ pw, const float* __restrict__ pb,
                       float* __restrict__ out) {
    __shared__ float mean[32];
    int t = threadIdx.x;
    if (t < 32) {
        float s = 0.f;
        for (int b = 0; b < 128; b++) s += g_part[b * 32 + t];
        mean[t] = s * (1.0f / 16384.0f);
    }
    __syncthreads();
    if (t < 32) {
        float s = pb[t];
        for (int c = 0; c < 32; c++) s += mean[c] * pw[c * 32 + t];
        out[t] = s;
    }
}

// ------------------------- host orchestration -------------------------
extern "C" void kernel_launch(void* const* d_in, const int* in_sizes, int n_in,
                              void* d_out, int out_size)
{
    const float* x      = (const float*)d_in[0];
    const float* coords = (const float*)d_in[1];
    const float* regions= (const float*)d_in[3];
    const float* fe_w1  = (const float*)d_in[4];
    const float* fe_b1  = (const float*)d_in[5];
    const float* fe_w2  = (const float*)d_in[6];
    const float* fe_b2  = (const float*)d_in[7];
    const float* ln1_g  = (const float*)d_in[8];
    const float* ln1_b  = (const float*)d_in[9];
    const float* wq     = (const float*)d_in[10];
    const float* wk     = (const float*)d_in[11];
    const float* wv     = (const float*)d_in[12];
    const float* wrpe   = (const float*)d_in[13];
    const float* ow     = (const float*)d_in[14];
    const float* ob     = (const float*)d_in[15];
    const float* ln2_g  = (const float*)d_in[16];
    const float* ln2_b  = (const float*)d_in[17];
    const float* f1w    = (const float*)d_in[18];
    const float* f1b    = (const float*)d_in[19];
    const float* f2w    = (const float*)d_in[20];
    const float* f2b    = (const float*)d_in[21];
    const float* Wcat   = (const float*)d_in[22];
    const float* m1w    = (const float*)d_in[23];
    const float* m1b    = (const float*)d_in[24];
    const float* mlng   = (const float*)d_in[25];
    const float* mlnb   = (const float*)d_in[26];
    const float* m2w    = (const float*)d_in[27];
    const float* m2b    = (const float*)d_in[28];
    const float* pw     = (const float*)d_in[29];
    const float* pb     = (const float*)d_in[30];
    float* out = (float*)d_out;

    cudaFuncSetAttribute(attn_k, cudaFuncAttributeMaxDynamicSharedMemorySize, 52224);

    float *p_h, *p_tmp, *p_hist, *p_q, *p_k, *p_v;
    float *p_t0, *p_u, *p_u2, *p_t, *p_w2;
    int *p_rhist, *p_rbase, *p_bhist, *p_bbase;
    cudaGetSymbolAddress((void**)&p_h,    g_h);
    cudaGetSymbolAddress((void**)&p_tmp,  g_tmp);
    cudaGetSymbolAddress((void**)&p_hist, g_hist);
    cudaGetSymbolAddress((void**)&p_q,    g_q);
    cudaGetSymbolAddress((void**)&p_k,    g_k);
    cudaGetSymbolAddress((void**)&p_v,    g_v);
    cudaGetSymbolAddress((void**)&p_t0,   g_t0);
    cudaGetSymbolAddress((void**)&p_u,    g_u);
    cudaGetSymbolAddress((void**)&p_u2,   g_u2);
    cudaGetSymbolAddress((void**)&p_t,    g_t);
    cudaGetSymbolAddress((void**)&p_w2,   g_W2);
    cudaGetSymbolAddress((void**)&p_rhist, r_hist);
    cudaGetSymbolAddress((void**)&p_rbase, r_base);
    cudaGetSymbolAddress((void**)&p_bhist, b_hist);
    cudaGetSymbolAddress((void**)&p_bbase, b_base);

    const int M = NNODE;

    // ---- bucket ordering via counting sorts ----
    zero_k<<<512, 256>>>();
    rank_hist_k<<<dim3(64, 2), 256>>>(coords);
    scan_k<<<2, 1024>>>(p_rhist, p_rbase, NNODE, NNODE);
    rank_place_k<<<dim3(64, 2), 256>>>(coords);
    rank_rank_k<<<dim3(64, 2), 256>>>(coords);
    key1_k<<<dim3(64, 16), 256>>>(regions);
    key2_k<<<dim3(64, 16), 256>>>();
    scan_k<<<16, 1024>>>(p_bhist, p_bbase, KBINS, KBINS);
    bucket_place_k<<<dim3(64, 16), 256>>>();
    bucket_pos_k<<<dim3(64, 16), 256>>>();
    w2all_k<<<4, 128>>>(wrpe);

    // feat encoder (exact FFMA)
    gemm_k<<<dim3(256, 1), 256>>>(x, fe_w1, p_tmp, nullptr, 0, fe_b1, nullptr, M, 64, 16, 1.f, 1);
    gemm_k<<<dim3(256, 1), 256>>>(p_tmp, fe_w2, p_h, p_hist, 320, fe_b2, nullptr, M, 64, 64, 1.f, 0);

    for (int l = 0; l < 4; l++) {
        qkv_k<<<dim3(256, 24), 256>>>(p_h, ln1_g + l * 64, ln1_b + l * 64,
                                      wq + (size_t)l * 64 * 512,
                                      wk + (size_t)l * 64 * 512,
                                      wv + (size_t)l * 64 * 512,
                                      p_q, p_k, p_v);
        attn_k<<<dim3(256, 8, 2), 256, 52224>>>(p_q, p_k, p_v, coords, p_w2 + l * 16);
        outproj_k<<<256, 256>>>(ow + (size_t)l * 512 * 64, ob + l * 64, p_h);
        ffn_k<<<256, 256>>>(p_h, ln2_g + l * 64, ln2_b + l * 64,
                            f1w + (size_t)l * 64 * 64, f1b + l * 64,
                            f2w + (size_t)l * 64 * 64, f2b + l * 64,
                            p_hist + (l + 1) * 64);
    }

    gemm_k<<<dim3(256, 1), 256>>>(p_hist, Wcat, p_t0, nullptr, 0, nullptr, nullptr, M, 32, 320, 1.f, 2);
    gemm_k<<<dim3(256, 4), 256>>>(p_t0, m1w, p_u, nullptr, 0, m1b, nullptr, M, 256, 32, 1.f, 0);
    ln256t_k<<<16384, 256>>>(p_u, p_u2, mlng, mlnb);
    gemm_k<<<dim3(256, 1), 256>>>(p_u2, m2w, p_t, nullptr, 0, m2b, p_t0, M, 32, 256, 1.f, 0);
    red1_k<<<128, 256>>>(p_t);
    red2_k<<<1, 256>>>(pw, pb, out);
}

// round 7
// speedup vs baseline: 1.9808x; 1.3672x over previous
#include <cuda_runtime.h>
#include <cuda_bf16.h>
#include <math.h>

#define NNODE 16384
#define HEADS 8
#define DIM   64
#define HDIM  512
#define KBINS 40960

// ------------------------- device scratch (no allocs allowed) -------------------------
__device__ int   g_rank[2][NNODE];
__device__ int   g_order[16 * NNODE];
__device__ float g_h[NNODE * DIM];
__device__ float g_hist[NNODE * 320];
__device__ float g_outr[16 * NNODE * DIM];   // [nh*8+h][node][d]
__device__ float g_lser[16 * NNODE];
__device__ float g_W2[4 * 16];               // [layer][h][c]
__device__ float g_M[4 * 8 * 64 * 64];       // [layer][head][d][e] = sum_c Wq[d,c]Wk[e,c]/8
__device__ float g_t0[NNODE * 32];
__device__ float g_u [NNODE * 256];
__device__ float g_u2[NNODE * 256];
__device__ float g_t [NNODE * 32];
__device__ float g_part[128 * 32];

// sorting scratch
__device__ int r_hist[2][NNODE];
__device__ int r_base[2][NNODE];
__device__ int r_cnt [2][NNODE];
__device__ int r_slot[2][NNODE];
__device__ int b_keys[16][NNODE];
__device__ int b_hist[16][KBINS];
__device__ int b_base[16][KBINS];
__device__ int b_cnt [16][KBINS];
__device__ int b_slot[16][NNODE];
__device__ int g_maxre[16];

// ------------------------- tf32 helpers -------------------------
__device__ __forceinline__ unsigned f2tf(float f) {
    unsigned u;
    asm("cvt.rna.tf32.f32 %0, %1;" : "=r"(u) : "f"(f));
    return u;
}

__device__ __forceinline__ void mma_tf32(float c[4], unsigned a0, unsigned a1,
                                         unsigned a2, unsigned a3,
                                         unsigned b0, unsigned b1) {
    asm volatile(
        "mma.sync.aligned.m16n8k8.row.col.f32.tf32.tf32.f32 "
        "{%0,%1,%2,%3}, {%4,%5,%6,%7}, {%8,%9}, {%0,%1,%2,%3};"
        : "+f"(c[0]), "+f"(c[1]), "+f"(c[2]), "+f"(c[3])
        : "r"(a0), "r"(a1), "r"(a2), "r"(a3), "r"(b0), "r"(b1));
}

// ------------------------- zero all counting scratch -------------------------
__global__ void zero_k() {
    int gid = blockIdx.x * 256 + threadIdx.x;
    int stride = gridDim.x * 256;
    for (int i = gid; i < 2 * NNODE; i += stride) { ((int*)r_hist)[i] = 0; ((int*)r_cnt)[i] = 0; }
    for (int i = gid; i < 16 * KBINS; i += stride) { ((int*)b_hist)[i] = 0; ((int*)b_cnt)[i] = 0; }
    if (gid < 16) g_maxre[gid] = 0;
}

// ------------------------- coordinate ranks via counting -------------------------
__device__ __forceinline__ int coord_bin(float c) {
    int u = (int)(c * 16384.0f);
    return min(16383, max(0, u));
}

__global__ void rank_hist_k(const float* __restrict__ coords) {
    int axis = blockIdx.y;
    int i = blockIdx.x * 256 + threadIdx.x;
    int u = coord_bin(coords[i * 3 + axis]);
    atomicAdd(&r_hist[axis][u], 1);
}

__global__ void __launch_bounds__(1024) scan_k(const int* __restrict__ hist,
                                               int* __restrict__ base,
                                               int nbins, int rowstride) {
    __shared__ int ss[1024];
    int row = blockIdx.x;
    const int* h = hist + (size_t)row * rowstride;
    int* bs = base + (size_t)row * rowstride;
    int t = threadIdx.x;
    int chunk = (nbins + 1023) >> 10;
    int b0 = t * chunk;
    int s = 0;
    for (int m = 0; m < chunk; m++) { int idx = b0 + m; if (idx < nbins) s += h[idx]; }
    ss[t] = s;
    __syncthreads();
    for (int d = 1; d < 1024; d <<= 1) {
        int v = (t >= d) ? ss[t - d] : 0;
        __syncthreads();
        ss[t] += v;
        __syncthreads();
    }
    int run = (t > 0) ? ss[t - 1] : 0;
    for (int m = 0; m < chunk; m++) {
        int idx = b0 + m;
        if (idx < nbins) { bs[idx] = run; run += h[idx]; }
    }
}

__global__ void rank_place_k(const float* __restrict__ coords) {
    int axis = blockIdx.y;
    int i = blockIdx.x * 256 + threadIdx.x;
    int u = coord_bin(coords[i * 3 + axis]);
    int slot = r_base[axis][u] + atomicAdd(&r_cnt[axis][u], 1);
    r_slot[axis][slot] = i;
}

__global__ void rank_rank_k(const float* __restrict__ coords) {
    int axis = blockIdx.y;
    int i = blockIdx.x * 256 + threadIdx.x;
    float ci = coords[i * 3 + axis];
    int u = coord_bin(ci);
    int b = r_base[axis][u], n = r_hist[axis][u];
    int r = 0;
    for (int m = 0; m < n; m++) {
        int j = r_slot[axis][b + m];
        float cj = coords[j * 3 + axis];
        r += (int)((cj < ci) || (cj == ci && j < i));
    }
    g_rank[axis][i] = b + r;
}

// ------------------------- bucket order via counting sort -------------------------
__global__ void key1_k(const float* __restrict__ regions) {
    __shared__ int smax[256];
    int row = blockIdx.y;
    int nh = row >> 3, h = row & 7;
    float qe = 16384.0f / regions[nh * 16 + h];
    float qp = 16384.0f / regions[nh * 16 + 8 + h];
    int i = blockIdx.x * 256 + threadIdx.x;
    int re = (int)floorf((float)g_rank[0][i] / qe) + 1;
    int rp = (int)floorf((float)g_rank[1][i] / qp) + 1;
    b_keys[row][i] = (rp << 16) | re;
    smax[threadIdx.x] = re;
    __syncthreads();
    for (int s = 128; s > 0; s >>= 1) {
        if (threadIdx.x < s) smax[threadIdx.x] = max(smax[threadIdx.x], smax[threadIdx.x + s]);
        __syncthreads();
    }
    if (threadIdx.x == 0) atomicMax(&g_maxre[row], smax[0]);
}

__global__ void key2_k() {
    int row = blockIdx.y;
    int i = blockIdx.x * 256 + threadIdx.x;
    int nb = (int)ceilf(log2f((float)g_maxre[row] + 1.0f));
    int v = b_keys[row][i];
    int key = ((v >> 16) << nb) | (v & 0xffff);
    b_keys[row][i] = key;
    atomicAdd(&b_hist[row][key], 1);
}

__global__ void bucket_place_k() {
    int row = blockIdx.y;
    int i = blockIdx.x * 256 + threadIdx.x;
    int key = b_keys[row][i];
    int slot = b_base[row][key] + atomicAdd(&b_cnt[row][key], 1);
    b_slot[row][slot] = i;
}

__global__ void bucket_pos_k() {
    int row = blockIdx.y;
    int i = blockIdx.x * 256 + threadIdx.x;
    int key = b_keys[row][i];
    int b = b_base[row][key], n = b_hist[row][key];
    int r = 0;
    for (int m = 0; m < n; m++) r += (int)(b_slot[row][b + m] < i);
    g_order[row * NNODE + b + r] = i;
}

// ------------------------- RPE distance weights (all 4 layers) -------------------------
__global__ void w2all_k(const float* __restrict__ wrpe) {   // [4][512][16]
    __shared__ float sq[128];
    int l = blockIdx.x;
    const float* w = wrpe + (size_t)l * 512 * 16;
    int t = threadIdx.x;
    int h = t >> 4, m = t & 15;
    float s = 0.f;
    for (int d = 0; d < 64; d++) s += w[(h * 64 + d) * 16 + m];
    float om = s * (1.0f / 64.0f);
    sq[t] = om * om;
    __syncthreads();
    if (t < 16) {
        int hh = t >> 1, c = t & 1;
        float ww = 0.f;
        for (int kk = 0; kk < 8; kk++) ww += sq[hh * 16 + c * 8 + kk];
        g_W2[l * 16 + t] = ww;
    }
}

// ------------------------- M_h[d][e] = sum_c Wq[d,c] Wk[e,c] / 8 (exact fp32, NT) -------------------------
#define FMA16(av, bv, acc)                                                         \
    acc[0][0]+=av.x*bv.x; acc[0][1]+=av.x*bv.y; acc[0][2]+=av.x*bv.z; acc[0][3]+=av.x*bv.w; \
    acc[1][0]+=av.y*bv.x; acc[1][1]+=av.y*bv.y; acc[1][2]+=av.y*bv.z; acc[1][3]+=av.y*bv.w; \
    acc[2][0]+=av.z*bv.x; acc[2][1]+=av.z*bv.y; acc[2][2]+=av.z*bv.z; acc[2][3]+=av.z*bv.w; \
    acc[3][0]+=av.w*bv.x; acc[3][1]+=av.w*bv.y; acc[3][2]+=av.w*bv.z; acc[3][3]+=av.w*bv.w;

__global__ void __launch_bounds__(256) mh_k(const float* __restrict__ wq,
                                            const float* __restrict__ wk) {
    __shared__ float Aq[64 * 68];   // [d][c]  Wq rows
    __shared__ float Bk[64 * 68];   // [e][c]  Wk rows
    int bx = blockIdx.x;            // l*8 + h
    int l = bx >> 3, h = bx & 7;
    int tid = threadIdx.x;
#pragma unroll
    for (int it = 0; it < 4; it++) {
        int idx = tid + it * 256;
        int d = idx >> 4, c4 = (idx & 15) * 4;
        *(float4*)&Aq[d * 68 + c4] = *(const float4*)&wq[((size_t)(l * 64 + d)) * 512 + h * 64 + c4];
        *(float4*)&Bk[d * 68 + c4] = *(const float4*)&wk[((size_t)(l * 64 + d)) * 512 + h * 64 + c4];
    }
    __syncthreads();
    int tm = tid >> 4, tn = tid & 15;
    float acc[4][4] = {};
#pragma unroll 4
    for (int c = 0; c < 64; c++) {   // contract over head columns c  (NT GEMM)
        float4 av = make_float4(Aq[(tm * 4 + 0) * 68 + c], Aq[(tm * 4 + 1) * 68 + c],
                                Aq[(tm * 4 + 2) * 68 + c], Aq[(tm * 4 + 3) * 68 + c]);
        float4 bv = make_float4(Bk[(tn * 4 + 0) * 68 + c], Bk[(tn * 4 + 1) * 68 + c],
                                Bk[(tn * 4 + 2) * 68 + c], Bk[(tn * 4 + 3) * 68 + c]);
        FMA16(av, bv, acc)
    }
#pragma unroll
    for (int ii = 0; ii < 4; ii++)
#pragma unroll
        for (int jj = 0; jj < 4; jj++)
            g_M[(size_t)bx * 4096 + (tm * 4 + ii) * 64 + tn * 4 + jj] = 0.125f * acc[ii][jj];
}

// ------------------------- fused feat encoder (exact FFMA) -------------------------
__global__ void __launch_bounds__(256) ffe_k(
    const float* __restrict__ x,
    const float* __restrict__ W1, const float* __restrict__ b1,
    const float* __restrict__ W2, const float* __restrict__ b2)
{
    __shared__ float Xs16[64 * 17];
    __shared__ float W1s[16 * 68];
    __shared__ float Ts[64 * 68];
    __shared__ float W2s[64 * 68];
    int tid = threadIdx.x;
    int row0 = blockIdx.x * 64;
    {
        int r = tid >> 2, c4 = (tid & 3) * 4;
        float4 xv = *(const float4*)&x[(size_t)(row0 + r) * 16 + c4];
        Xs16[r * 17 + c4 + 0] = xv.x; Xs16[r * 17 + c4 + 1] = xv.y;
        Xs16[r * 17 + c4 + 2] = xv.z; Xs16[r * 17 + c4 + 3] = xv.w;
    }
    if (tid < 16 * 16) {
        int r = tid >> 4, c4 = (tid & 15) * 4;
        *(float4*)&W1s[r * 68 + c4] = *(const float4*)&W1[(size_t)r * 64 + c4];
    }
#pragma unroll
    for (int it = 0; it < 4; it++) {
        int idx = tid + it * 256;
        int r = idx >> 4, c4 = (idx & 15) * 4;
        *(float4*)&W2s[r * 68 + c4] = *(const float4*)&W2[(size_t)r * 64 + c4];
    }
    __syncthreads();
    int tm = tid >> 4, tn = tid & 15;
    float acc[4][4] = {};
#pragma unroll
    for (int kk = 0; kk < 16; kk++) {
        float4 av = make_float4(Xs16[(tm * 4 + 0) * 17 + kk], Xs16[(tm * 4 + 1) * 17 + kk],
                                Xs16[(tm * 4 + 2) * 17 + kk], Xs16[(tm * 4 + 3) * 17 + kk]);
        float4 bv = *(const float4*)&W1s[kk * 68 + tn * 4];
        FMA16(av, bv, acc)
    }
#pragma unroll
    for (int ii = 0; ii < 4; ii++)
#pragma unroll
        for (int jj = 0; jj < 4; jj++)
            Ts[(tm * 4 + ii) * 68 + tn * 4 + jj] = fmaxf(acc[ii][jj] + b1[tn * 4 + jj], 0.f);
    __syncthreads();
    float acc2[4][4] = {};
#pragma unroll 8
    for (int kk = 0; kk < 64; kk++) {
        float4 av = make_float4(Ts[(tm * 4 + 0) * 68 + kk], Ts[(tm * 4 + 1) * 68 + kk],
                                Ts[(tm * 4 + 2) * 68 + kk], Ts[(tm * 4 + 3) * 68 + kk]);
        float4 bv = *(const float4*)&W2s[kk * 68 + tn * 4];
        FMA16(av, bv, acc2)
    }
#pragma unroll
    for (int ii = 0; ii < 4; ii++) {
        int r = row0 + tm * 4 + ii;
#pragma unroll
        for (int jj = 0; jj < 4; jj++) {
            int c = tn * 4 + jj;
            float vv = acc2[ii][jj] + b2[c];
            g_h[(size_t)r * 64 + c] = vv;
            g_hist[(size_t)r * 320 + c] = vv;
        }
    }
}

// ------------------------- fused attention: LN + X M X^T + softmax + (PX)Wv -------------------------
__global__ void __launch_bounds__(256) attn_k(
    const float* __restrict__ coords, const float* __restrict__ W2row,
    const float* __restrict__ lng, const float* __restrict__ lnb,
    const float* __restrict__ Mbase, const float* __restrict__ wv_l)
{
    extern __shared__ unsigned sh[];
    unsigned* Xs = sh;                 // X tf32 [64][68]; later Wv tf32
    unsigned* Ms = sh + 64 * 68;       // M tf32; later S float / P tf32
    unsigned* Ts = sh + 2 * 64 * 68;   // T tf32; later R tf32
    __shared__ int   nd[64];
    __shared__ float cx[64], cy[64], redm[4][64], reds[4][64], redA[64][4];

    int tid = threadIdx.x;
    int blk = blockIdx.x, h = blockIdx.y, nh = blockIdx.z;
    int row = nh * 8 + h;
    const int* ord = g_order + row * NNODE + blk * 64;
    if (tid < 64) {
        int nn = ord[tid];
        nd[tid] = nn;
        cx[tid] = coords[nn * 3 + 0];
        cy[tid] = coords[nn * 3 + 1];
    }
    __syncthreads();

    // gather h rows + load M
    float* Xf = (float*)Xs;
    const float* Mg = Mbase + (size_t)h * 4096;
    for (int idx = tid; idx < 4096; idx += 256) {
        int i = idx >> 6, d = idx & 63;
        Xf[i * 68 + d] = g_h[(size_t)nd[i] * 64 + d];
        Ms[i * 68 + d] = f2tf(Mg[i * 64 + d]);
    }
    __syncthreads();

    // exact LayerNorm per row, convert to tf32 in place
    int tr = tid >> 2, tp = tid & 3;
    {
        float s = 0.f;
        for (int c = tp * 16; c < tp * 16 + 16; c++) s += Xf[tr * 68 + c];
        redA[tr][tp] = s;
    }
    __syncthreads();
    float mu = (redA[tr][0] + redA[tr][1] + redA[tr][2] + redA[tr][3]) * (1.0f / 64.0f);
    __syncthreads();
    {
        float vs = 0.f;
        for (int c = tp * 16; c < tp * 16 + 16; c++) {
            float d = Xf[tr * 68 + c] - mu;
            vs += d * d;
        }
        redA[tr][tp] = vs;
    }
    __syncthreads();
    {
        float var = (redA[tr][0] + redA[tr][1] + redA[tr][2] + redA[tr][3]) * (1.0f / 64.0f);
        float rs = rsqrtf(var + 1e-5f);
        for (int c = tp * 16; c < tp * 16 + 16; c++) {
            float vv = (Xf[tr * 68 + c] - mu) * rs * lng[c] + lnb[c];
            Xs[tr * 68 + c] = f2tf(vv);
        }
    }
    __syncthreads();

    int wid = tid >> 5, lane = tid & 31;
    int g = lane >> 2, t = lane & 3;
    int r0 = (wid & 3) * 16, c0 = (wid >> 2) * 32;

    // phase 1: T = X @ M
    {
        float acc[4][4] = {};
#pragma unroll
        for (int ks = 0; ks < 8; ks++) {
            int k0 = ks * 8;
            unsigned a0 = Xs[(r0 + g) * 68 + k0 + t];
            unsigned a1 = Xs[(r0 + g + 8) * 68 + k0 + t];
            unsigned a2 = Xs[(r0 + g) * 68 + k0 + t + 4];
            unsigned a3 = Xs[(r0 + g + 8) * 68 + k0 + t + 4];
#pragma unroll
            for (int nt = 0; nt < 4; nt++) {
                int n = c0 + nt * 8 + g;
                unsigned b0 = Ms[(k0 + t) * 68 + n];
                unsigned b1 = Ms[(k0 + t + 4) * 68 + n];
                mma_tf32(acc[nt], a0, a1, a2, a3, b0, b1);
            }
        }
#pragma unroll
        for (int nt = 0; nt < 4; nt++)
#pragma unroll
            for (int cr = 0; cr < 4; cr++) {
                int r = r0 + g + (cr >> 1) * 8;
                int c = c0 + nt * 8 + 2 * t + (cr & 1);
                Ts[r * 68 + c] = f2tf(acc[nt][cr]);
            }
    }
    __syncthreads();

    // phase 2: S = T @ X^T  (+ RPE), write transposed into Ms
    float W0 = W2row[h * 2 + 0], W1 = W2row[h * 2 + 1];
    {
        float acc[4][4] = {};
#pragma unroll
        for (int ks = 0; ks < 8; ks++) {
            int k0 = ks * 8;
            unsigned a0 = Ts[(r0 + g) * 68 + k0 + t];
            unsigned a1 = Ts[(r0 + g + 8) * 68 + k0 + t];
            unsigned a2 = Ts[(r0 + g) * 68 + k0 + t + 4];
            unsigned a3 = Ts[(r0 + g + 8) * 68 + k0 + t + 4];
#pragma unroll
            for (int nt = 0; nt < 4; nt++) {
                int j = c0 + nt * 8 + g;
                unsigned b0 = Xs[j * 68 + k0 + t];
                unsigned b1 = Xs[j * 68 + k0 + t + 4];
                mma_tf32(acc[nt], a0, a1, a2, a3, b0, b1);
            }
        }
        float* Ss = (float*)Ms;
#pragma unroll
        for (int nt = 0; nt < 4; nt++) {
            int j0 = c0 + nt * 8 + 2 * t;
#pragma unroll
            for (int cr = 0; cr < 4; cr++) {
                int i = r0 + g + (cr >> 1) * 8;
                int j = j0 + (cr & 1);
                float dx = cx[i] - cx[j], dy = cy[i] - cy[j];
                Ss[j * 68 + i] = acc[nt][cr] - W0 * dx * dx - W1 * dy * dy;
            }
        }
    }
    __syncthreads();

    // softmax over j per query i (Ss layout [j][i])
    float* Ss = (float*)Ms;
    int ci = tid & 63, seg = tid >> 6;
    float ml = -3.0e38f;
#pragma unroll
    for (int jj = 0; jj < 16; jj++) ml = fmaxf(ml, Ss[(seg * 16 + jj) * 68 + ci]);
    redm[seg][ci] = ml;
    __syncthreads();
    float mm = fmaxf(fmaxf(redm[0][ci], redm[1][ci]), fmaxf(redm[2][ci], redm[3][ci]));
    float ev[16];
    float sl = 0.f;
#pragma unroll
    for (int jj = 0; jj < 16; jj++) {
        float e = expf(Ss[(seg * 16 + jj) * 68 + ci] - mm);
        ev[jj] = e;
        sl += e;
    }
    reds[seg][ci] = sl;
    __syncthreads();
    float ssum = reds[0][ci] + reds[1][ci] + reds[2][ci] + reds[3][ci];
    float inv = 1.0f / ssum;
    if (seg == 0) g_lser[row * NNODE + nd[ci]] = mm + logf(ssum);
    unsigned* Ps = Ms;
#pragma unroll
    for (int jj = 0; jj < 16; jj++)
        Ps[(seg * 16 + jj) * 68 + ci] = f2tf(ev[jj] * inv);
    __syncthreads();

    // phase 3: R = P @ X   (P stored transposed [j][i])
    float racc[4][4] = {};
#pragma unroll
    for (int ks = 0; ks < 8; ks++) {
        int k0 = ks * 8;
        unsigned a0 = Ps[(k0 + t) * 68 + r0 + g];
        unsigned a1 = Ps[(k0 + t) * 68 + r0 + g + 8];
        unsigned a2 = Ps[(k0 + t + 4) * 68 + r0 + g];
        unsigned a3 = Ps[(k0 + t + 4) * 68 + r0 + g + 8];
#pragma unroll
        for (int nt = 0; nt < 4; nt++) {
            int n = c0 + nt * 8 + g;
            unsigned b0 = Xs[(k0 + t) * 68 + n];
            unsigned b1 = Xs[(k0 + t + 4) * 68 + n];
            mma_tf32(racc[nt], a0, a1, a2, a3, b0, b1);
        }
    }
    __syncthreads();   // all reads of Xs done; Ts free

    // write R (tf32) into Ts; load Wv_h into Xs
#pragma unroll
    for (int nt = 0; nt < 4; nt++)
#pragma unroll
        for (int cr = 0; cr < 4; cr++) {
            int r = r0 + g + (cr >> 1) * 8;
            int c = c0 + nt * 8 + 2 * t + (cr & 1);
            Ts[r * 68 + c] = f2tf(racc[nt][cr]);
        }
    for (int idx = tid; idx < 4096; idx += 256) {
        int d = idx >> 6, e = idx & 63;
        Xs[d * 68 + e] = f2tf(wv_l[(size_t)d * 512 + h * 64 + e]);
    }
    __syncthreads();

    // phase 4: O = R @ Wv
    float oacc[4][4] = {};
#pragma unroll
    for (int ks = 0; ks < 8; ks++) {
        int k0 = ks * 8;
        unsigned a0 = Ts[(r0 + g) * 68 + k0 + t];
        unsigned a1 = Ts[(r0 + g + 8) * 68 + k0 + t];
        unsigned a2 = Ts[(r0 + g) * 68 + k0 + t + 4];
        unsigned a3 = Ts[(r0 + g + 8) * 68 + k0 + t + 4];
#pragma unroll
        for (int nt = 0; nt < 4; nt++) {
            int n = c0 + nt * 8 + g;
            unsigned b0 = Xs[(k0 + t) * 68 + n];
            unsigned b1 = Xs[(k0 + t + 4) * 68 + n];
            mma_tf32(oacc[nt], a0, a1, a2, a3, b0, b1);
        }
    }
#pragma unroll
    for (int nt = 0; nt < 4; nt++) {
        int d0 = c0 + nt * 8 + 2 * t;
        int iA = r0 + g, iB = r0 + g + 8;
        *(float2*)&g_outr[((size_t)row * NNODE + nd[iA]) * 64 + d0] =
            make_float2(oacc[nt][0], oacc[nt][1]);
        *(float2*)&g_outr[((size_t)row * NNODE + nd[iB]) * 64 + d0] =
            make_float2(oacc[nt][2], oacc[nt][3]);
    }
}

// ------------------------- out-projection with fused lse-combine (K=512) -------------------------
__global__ void __launch_bounds__(256) outproj_k(
    const float* __restrict__ ow, const float* __restrict__ ob, float* __restrict__ hbuf)
{
    __shared__ unsigned As[64 * 68];
    __shared__ unsigned Bs[64 * 68];
    __shared__ float w0s[64], w1s[64];
    int tid = threadIdx.x;
    int row0 = blockIdx.x * 64;
    int wid = tid >> 5, lane = tid & 31;
    int g = lane >> 2, t = lane & 3;
    int r0 = (wid & 3) * 16, c0 = (wid >> 2) * 32;
    float acc[4][4] = {};
    for (int h = 0; h < 8; h++) {
        __syncthreads();
        if (tid < 64) {
            int node = row0 + tid;
            float l0 = g_lser[h * NNODE + node];
            float l1 = g_lser[(8 + h) * NNODE + node];
            float m = fmaxf(l0, l1);
            float e0 = expf(l0 - m), e1 = expf(l1 - m);
            float inv = 1.0f / (e0 + e1);
            w0s[tid] = e0 * inv;
            w1s[tid] = e1 * inv;
        }
        __syncthreads();
#pragma unroll
        for (int it = 0; it < 4; it++) {
            int idx = tid + it * 256;
            int r = idx >> 4, c4 = (idx & 15) * 4;
            int node = row0 + r;
            float4 o0 = *(const float4*)&g_outr[((size_t)h * NNODE + node) * 64 + c4];
            float4 o1 = *(const float4*)&g_outr[((size_t)(8 + h) * NNODE + node) * 64 + c4];
            float w0 = w0s[r], w1 = w1s[r];
            As[r * 68 + c4 + 0] = f2tf(w0 * o0.x + w1 * o1.x);
            As[r * 68 + c4 + 1] = f2tf(w0 * o0.y + w1 * o1.y);
            As[r * 68 + c4 + 2] = f2tf(w0 * o0.z + w1 * o1.z);
            As[r * 68 + c4 + 3] = f2tf(w0 * o0.w + w1 * o1.w);
            float4 bv = *(const float4*)&ow[(size_t)(h * 64 + r) * 64 + c4];
            Bs[r * 68 + c4 + 0] = f2tf(bv.x); Bs[r * 68 + c4 + 1] = f2tf(bv.y);
            Bs[r * 68 + c4 + 2] = f2tf(bv.z); Bs[r * 68 + c4 + 3] = f2tf(bv.w);
        }
        __syncthreads();
#pragma unroll
        for (int ks = 0; ks < 8; ks++) {
            int k0 = ks * 8;
            unsigned a0 = As[(r0 + g) * 68 + k0 + t];
            unsigned a1 = As[(r0 + g + 8) * 68 + k0 + t];
            unsigned a2 = As[(r0 + g) * 68 + k0 + t + 4];
            unsigned a3 = As[(r0 + g + 8) * 68 + k0 + t + 4];
#pragma unroll
            for (int nt = 0; nt < 4; nt++) {
                int n = c0 + nt * 8 + g;
                unsigned b0 = Bs[(k0 + t) * 68 + n];
                unsigned b1 = Bs[(k0 + t + 4) * 68 + n];
                mma_tf32(acc[nt], a0, a1, a2, a3, b0, b1);
            }
        }
    }
#pragma unroll
    for (int nt = 0; nt < 4; nt++) {
#pragma unroll
        for (int cr = 0; cr < 4; cr++) {
            int r = row0 + r0 + g + (cr >> 1) * 8;
            int ccol = c0 + nt * 8 + 2 * t + (cr & 1);
            float vv = acc[nt][cr] + ob[ccol] + hbuf[(size_t)r * 64 + ccol];
            hbuf[(size_t)r * 64 + ccol] = vv;
        }
    }
}

// ------------------------- fused LN2 + FFN + residual + hist (exact FFMA) -------------------------
__global__ void __launch_bounds__(256) ffn_k(
    float* __restrict__ hbuf, const float* __restrict__ g, const float* __restrict__ b,
    const float* __restrict__ W1, const float* __restrict__ b1,
    const float* __restrict__ W2, const float* __restrict__ b2,
    float* __restrict__ hist)
{
    __shared__ float Xs[64 * 68];
    __shared__ float Ws[64 * 68];
    __shared__ float redA[64][4];
    int tid = threadIdx.x;
    int row0 = blockIdx.x * 64;
#pragma unroll
    for (int it = 0; it < 4; it++) {
        int idx = tid + it * 256;
        int r = idx >> 4, c4 = (idx & 15) * 4;
        *(float4*)&Xs[r * 68 + c4] = *(const float4*)&hbuf[(size_t)(row0 + r) * 64 + c4];
        *(float4*)&Ws[r * 68 + c4] = *(const float4*)&W1[(size_t)r * 64 + c4];
    }
    __syncthreads();
    int tr = tid >> 2, tp = tid & 3;
    float s = 0.f;
    for (int c = tp * 16; c < tp * 16 + 16; c++) s += Xs[tr * 68 + c];
    redA[tr][tp] = s;
    __syncthreads();
    float mu = (redA[tr][0] + redA[tr][1] + redA[tr][2] + redA[tr][3]) * (1.0f / 64.0f);
    __syncthreads();
    float vs = 0.f;
    for (int c = tp * 16; c < tp * 16 + 16; c++) {
        float d = Xs[tr * 68 + c] - mu;
        vs += d * d;
    }
    redA[tr][tp] = vs;
    __syncthreads();
    float var = (redA[tr][0] + redA[tr][1] + redA[tr][2] + redA[tr][3]) * (1.0f / 64.0f);
    float rs = rsqrtf(var + 1e-5f);
    for (int c = tp * 16; c < tp * 16 + 16; c++)
        Xs[tr * 68 + c] = (Xs[tr * 68 + c] - mu) * rs * g[c] + b[c];
    __syncthreads();
    int tm = tid >> 4, tn = tid & 15;
    float acc[4][4] = {};
#pragma unroll 8
    for (int kk = 0; kk < 64; kk++) {
        float4 bv = *(const float4*)&Ws[kk * 68 + tn * 4];
        float4 av = make_float4(Xs[(tm * 4 + 0) * 68 + kk], Xs[(tm * 4 + 1) * 68 + kk],
                                Xs[(tm * 4 + 2) * 68 + kk], Xs[(tm * 4 + 3) * 68 + kk]);
        FMA16(av, bv, acc)
    }
    __syncthreads();
#pragma unroll
    for (int ii = 0; ii < 4; ii++)
#pragma unroll
        for (int jj = 0; jj < 4; jj++)
            Xs[(tm * 4 + ii) * 68 + tn * 4 + jj] = fmaxf(acc[ii][jj] + b1[tn * 4 + jj], 0.f);
#pragma unroll
    for (int it = 0; it < 4; it++) {
        int idx = tid + it * 256;
        int r = idx >> 4, c4 = (idx & 15) * 4;
        *(float4*)&Ws[r * 68 + c4] = *(const float4*)&W2[(size_t)r * 64 + c4];
    }
    __syncthreads();
    float acc2[4][4] = {};
#pragma unroll 8
    for (int kk = 0; kk < 64; kk++) {
        float4 bv = *(const float4*)&Ws[kk * 68 + tn * 4];
        float4 av = make_float4(Xs[(tm * 4 + 0) * 68 + kk], Xs[(tm * 4 + 1) * 68 + kk],
                                Xs[(tm * 4 + 2) * 68 + kk], Xs[(tm * 4 + 3) * 68 + kk]);
        FMA16(av, bv, acc2)
    }
#pragma unroll
    for (int ii = 0; ii < 4; ii++) {
        int r = row0 + tm * 4 + ii;
#pragma unroll
        for (int jj = 0; jj < 4; jj++) {
            int c = tn * 4 + jj;
            float vv = acc2[ii][jj] + b2[c] + hbuf[(size_t)r * 64 + c];
            hbuf[(size_t)r * 64 + c] = vv;
            hist[(size_t)r * 320 + c] = vv;
        }
    }
}

// ------------------------- scalar FFMA SGEMM (head) -------------------------
__global__ void __launch_bounds__(256) gemm_k(
    const float* __restrict__ A, const float* __restrict__ B, float* __restrict__ C,
    const float* __restrict__ bias, const float* __restrict__ resid,
    int M, int N, int K, int act)
{
    __shared__ float As[16][68];
    __shared__ float Bs[16][68];
    int tid = threadIdx.x;
    int row0 = blockIdx.x * 64, col0 = blockIdx.y * 64;
    int tm = tid >> 4, tn = tid & 15;
    int arow = tid >> 2, ac = tid & 3;
    int bk = tid >> 4, bn = tid & 15;
    float acc[4][4] = {};
    for (int k0 = 0; k0 < K; k0 += 16) {
        float4 a = *(const float4*)&A[(size_t)(row0 + arow) * K + k0 + ac * 4];
        As[ac * 4 + 0][arow] = a.x; As[ac * 4 + 1][arow] = a.y;
        As[ac * 4 + 2][arow] = a.z; As[ac * 4 + 3][arow] = a.w;
        int bcol = col0 + bn * 4;
        float4 bv = make_float4(0.f, 0.f, 0.f, 0.f);
        if (bcol < N) bv = *(const float4*)&B[(size_t)(k0 + bk) * N + bcol];
        *(float4*)&Bs[bk][bn * 4] = bv;
        __syncthreads();
#pragma unroll
        for (int kk = 0; kk < 16; kk++) {
            float4 av = *(const float4*)&As[kk][tm * 4];
            float4 bw = *(const float4*)&Bs[kk][tn * 4];
            FMA16(av, bw, acc)
        }
        __syncthreads();
    }
#pragma unroll
    for (int ii = 0; ii < 4; ii++) {
        int r = row0 + tm * 4 + ii;
#pragma unroll
        for (int jj = 0; jj < 4; jj++) {
            int ccol = col0 + tn * 4 + jj;
            if (ccol < N) {
                float vv = acc[ii][jj];
                if (bias) vv += bias[ccol];
                if (act == 1) vv = fmaxf(vv, 0.f);
                else if (act == 2) vv = tanhf(vv);
                if (resid) vv += resid[(size_t)r * N + ccol];
                C[(size_t)r * N + ccol] = vv;
            }
        }
    }
}

// ------------------------- LayerNorm 256 + tanh, warp per row -------------------------
__global__ void ln256w_k(const float* __restrict__ in, float* __restrict__ out,
                         const float* __restrict__ g, const float* __restrict__ b) {
    int w = threadIdx.x >> 5, lane = threadIdx.x & 31;
    int row = blockIdx.x * 8 + w;
    const float* xr = in + (size_t)row * 256;
    float x[8];
    float s = 0.f;
#pragma unroll
    for (int m = 0; m < 8; m++) { x[m] = xr[lane + 32 * m]; s += x[m]; }
    for (int o = 16; o; o >>= 1) s += __shfl_xor_sync(0xffffffffu, s, o);
    float mu = s * (1.0f / 256.0f);
    float vs = 0.f;
#pragma unroll
    for (int m = 0; m < 8; m++) { float d = x[m] - mu; vs += d * d; }
    for (int o = 16; o; o >>= 1) vs += __shfl_xor_sync(0xffffffffu, vs, o);
    float rs = rsqrtf(vs * (1.0f / 256.0f) + 1e-5f);
#pragma unroll
    for (int m = 0; m < 8; m++) {
        int c = lane + 32 * m;
        out[(size_t)row * 256 + c] = tanhf((x[m] - mu) * rs * g[c] + b[c]);
    }
}

// ------------------------- reductions + final projection -------------------------
__global__ void red1_k(const float* __restrict__ t) {
    __shared__ float sm[256];
    int blk = blockIdx.x, tid = threadIdx.x;
    int col = tid & 31, r0 = tid >> 5;
    float s = 0.f;
    for (int r = r0; r < 128; r += 8) s += t[(size_t)(blk * 128 + r) * 32 + col];
    sm[tid] = s;
    __syncthreads();
    for (int s2 = 4; s2; s2 >>= 1) {
        if (r0 < s2) sm[tid] += sm[tid + s2 * 32];
        __syncthreads();
    }
    if (r0 == 0) g_part[blk * 32 + col] = sm[col];
}

__global__ void red2_k(const float* __restrict__ pw, const float* __restrict__ pb,
                       float* __restrict__ out) {
    __shared__ float mean[32];
    int t = threadIdx.x;
    if (t < 32) {
        float s = 0.f;
        for (int b = 0; b < 128; b++) s += g_part[b * 32 + t];
        mean[t] = s * (1.0f / 16384.0f);
    }
    __syncthreads();
    if (t < 32) {
        float s = pb[t];
        for (int c = 0; c < 32; c++) s += mean[c] * pw[c * 32 + t];
        out[t] = s;
    }
}

// ------------------------- host orchestration -------------------------
extern "C" void kernel_launch(void* const* d_in, const int* in_sizes, int n_in,
                              void* d_out, int out_size)
{
    const float* x      = (const float*)d_in[0];
    const float* coords = (const float*)d_in[1];
    const float* regions= (const float*)d_in[3];
    const float* fe_w1  = (const float*)d_in[4];
    const float* fe_b1  = (const float*)d_in[5];
    const float* fe_w2  = (const float*)d_in[6];
    const float* fe_b2  = (const float*)d_in[7];
    const float* ln1_g  = (const float*)d_in[8];
    const float* ln1_b  = (const float*)d_in[9];
    const float* wq     = (const float*)d_in[10];
    const float* wk     = (const float*)d_in[11];
    const float* wv     = (const float*)d_in[12];
    const float* wrpe   = (const float*)d_in[13];
    const float* ow     = (const float*)d_in[14];
    const float* ob     = (const float*)d_in[15];
    const float* ln2_g  = (const float*)d_in[16];
    const float* ln2_b  = (const float*)d_in[17];
    const float* f1w    = (const float*)d_in[18];
    const float* f1b    = (const float*)d_in[19];
    const float* f2w    = (const float*)d_in[20];
    const float* f2b    = (const float*)d_in[21];
    const float* Wcat   = (const float*)d_in[22];
    const float* m1w    = (const float*)d_in[23];
    const float* m1b    = (const float*)d_in[24];
    const float* mlng   = (const float*)d_in[25];
    const float* mlnb   = (const float*)d_in[26];
    const float* m2w    = (const float*)d_in[27];
    const float* m2b    = (const float*)d_in[28];
    const float* pw     = (const float*)d_in[29];
    const float* pb     = (const float*)d_in[30];
    float* out = (float*)d_out;

    cudaFuncSetAttribute(attn_k, cudaFuncAttributeMaxDynamicSharedMemorySize, 52224);

    float *p_h, *p_hist, *p_t0, *p_u, *p_u2, *p_t, *p_w2, *p_M;
    int *p_rhist, *p_rbase, *p_bhist, *p_bbase;
    cudaGetSymbolAddress((void**)&p_h,    g_h);
    cudaGetSymbolAddress((void**)&p_hist, g_hist);
    cudaGetSymbolAddress((void**)&p_t0,   g_t0);
    cudaGetSymbolAddress((void**)&p_u,    g_u);
    cudaGetSymbolAddress((void**)&p_u2,   g_u2);
    cudaGetSymbolAddress((void**)&p_t,    g_t);
    cudaGetSymbolAddress((void**)&p_w2,   g_W2);
    cudaGetSymbolAddress((void**)&p_M,    g_M);
    cudaGetSymbolAddress((void**)&p_rhist, r_hist);
    cudaGetSymbolAddress((void**)&p_rbase, r_base);
    cudaGetSymbolAddress((void**)&p_bhist, b_hist);
    cudaGetSymbolAddress((void**)&p_bbase, b_base);

    const int M = NNODE;

    // ---- bucket ordering via counting sorts ----
    zero_k<<<512, 256>>>();
    rank_hist_k<<<dim3(64, 2), 256>>>(coords);
    scan_k<<<2, 1024>>>(p_rhist, p_rbase, NNODE, NNODE);
    rank_place_k<<<dim3(64, 2), 256>>>(coords);
    rank_rank_k<<<dim3(64, 2), 256>>>(coords);
    key1_k<<<dim3(64, 16), 256>>>(regions);
    key2_k<<<dim3(64, 16), 256>>>();
    scan_k<<<16, 1024>>>(p_bhist, p_bbase, KBINS, KBINS);
    bucket_place_k<<<dim3(64, 16), 256>>>();
    bucket_pos_k<<<dim3(64, 16), 256>>>();
    w2all_k<<<4, 128>>>(wrpe);
    mh_k<<<32, 256>>>(wq, wk);

    // feat encoder (exact FFMA, fused)
    ffe_k<<<256, 256>>>(x, fe_w1, fe_b1, fe_w2, fe_b2);

    for (int l = 0; l < 4; l++) {
        attn_k<<<dim3(256, 8, 2), 256, 52224>>>(coords, p_w2 + l * 16,
                                                ln1_g + l * 64, ln1_b + l * 64,
                                                p_M + (size_t)l * 8 * 4096,
                                                wv + (size_t)l * 64 * 512);
        outproj_k<<<256, 256>>>(ow + (size_t)l * 512 * 64, ob + l * 64, p_h);
        ffn_k<<<256, 256>>>(p_h, ln2_g + l * 64, ln2_b + l * 64,
                            f1w + (size_t)l * 64 * 64, f1b + l * 64,
                            f2w + (size_t)l * 64 * 64, f2b + l * 64,
                            p_hist + (l + 1) * 64);
    }

    gemm_k<<<dim3(256, 1), 256>>>(p_hist, Wcat, p_t0, nullptr, nullptr, M, 32, 320, 2);
    gemm_k<<<dim3(256, 4), 256>>>(p_t0, m1w, p_u, m1b, nullptr, M, 256, 32, 0);
    ln256w_k<<<2048, 256>>>(p_u, p_u2, mlng, mlnb);
    gemm_k<<<dim3(256, 1), 256>>>(p_u2, m2w, p_t, m2b, p_t0, M, 32, 256, 0);
    red1_k<<<128, 256>>>(p_t);
    red2_k<<<1, 256>>>(pw, pb, out);
}

// round 8
// speedup vs baseline: 2.0810x; 1.0506x over previous
#include <cuda_runtime.h>
#include <cuda_bf16.h>
#include <math.h>

#define NNODE 16384
#define HEADS 8
#define DIM   64
#define HDIM  512
#define KBINS 40960

// ------------------------- device scratch (no allocs allowed) -------------------------
__device__ int   g_rank[2][NNODE];
__device__ int   g_order[16 * NNODE];
__device__ float g_h[NNODE * DIM];
__device__ float g_xn[NNODE * DIM];          // LN1(h) for the upcoming layer
__device__ float g_hist[NNODE * 320];
__device__ float g_outr[16 * NNODE * DIM];   // [nh*8+h][node][d]
__device__ float g_lser[16 * NNODE];
__device__ float g_W2[4 * 16];               // [layer][h][c]
__device__ float g_M[4 * 8 * 64 * 64];       // [layer][head][d][e] = sum_c Wq[d,c]Wk[e,c]/8
__device__ float g_t0[NNODE * 32];
__device__ float g_u [NNODE * 256];
__device__ float g_u2[NNODE * 256];
__device__ float g_t [NNODE * 32];
__device__ float g_part[128 * 32];

// sorting scratch
__device__ int r_hist[2][NNODE];
__device__ int r_base[2][NNODE];
__device__ int r_cnt [2][NNODE];
__device__ int r_slot[2][NNODE];
__device__ int b_keys[16][NNODE];
__device__ int b_hist[16][KBINS];
__device__ int b_base[16][KBINS];
__device__ int b_cnt [16][KBINS];
__device__ int b_slot[16][NNODE];
__device__ int g_maxre[16];

// ------------------------- tf32 helpers -------------------------
__device__ __forceinline__ unsigned f2tf(float f) {
    unsigned u;
    asm("cvt.rna.tf32.f32 %0, %1;" : "=r"(u) : "f"(f));
    return u;
}

__device__ __forceinline__ void mma_tf32(float c[4], unsigned a0, unsigned a1,
                                         unsigned a2, unsigned a3,
                                         unsigned b0, unsigned b1) {
    asm volatile(
        "mma.sync.aligned.m16n8k8.row.col.f32.tf32.tf32.f32 "
        "{%0,%1,%2,%3}, {%4,%5,%6,%7}, {%8,%9}, {%0,%1,%2,%3};"
        : "+f"(c[0]), "+f"(c[1]), "+f"(c[2]), "+f"(c[3])
        : "r"(a0), "r"(a1), "r"(a2), "r"(a3), "r"(b0), "r"(b1));
}

// ------------------------- zero all counting scratch -------------------------
__global__ void zero_k() {
    int gid = blockIdx.x * 256 + threadIdx.x;
    int stride = gridDim.x * 256;
    for (int i = gid; i < 2 * NNODE; i += stride) { ((int*)r_hist)[i] = 0; ((int*)r_cnt)[i] = 0; }
    for (int i = gid; i < 16 * KBINS; i += stride) { ((int*)b_hist)[i] = 0; ((int*)b_cnt)[i] = 0; }
    if (gid < 16) g_maxre[gid] = 0;
}

// ------------------------- coordinate ranks via counting -------------------------
__device__ __forceinline__ int coord_bin(float c) {
    int u = (int)(c * 16384.0f);
    return min(16383, max(0, u));
}

__global__ void rank_hist_k(const float* __restrict__ coords) {
    int axis = blockIdx.y;
    int i = blockIdx.x * 256 + threadIdx.x;
    int u = coord_bin(coords[i * 3 + axis]);
    atomicAdd(&r_hist[axis][u], 1);
}

__global__ void __launch_bounds__(1024) scan_k(const int* __restrict__ hist,
                                               int* __restrict__ base,
                                               int nbins, int rowstride) {
    __shared__ int ss[1024];
    int row = blockIdx.x;
    const int* h = hist + (size_t)row * rowstride;
    int* bs = base + (size_t)row * rowstride;
    int t = threadIdx.x;
    int chunk = (nbins + 1023) >> 10;
    int b0 = t * chunk;
    int s = 0;
    for (int m = 0; m < chunk; m++) { int idx = b0 + m; if (idx < nbins) s += h[idx]; }
    ss[t] = s;
    __syncthreads();
    for (int d = 1; d < 1024; d <<= 1) {
        int v = (t >= d) ? ss[t - d] : 0;
        __syncthreads();
        ss[t] += v;
        __syncthreads();
    }
    int run = (t > 0) ? ss[t - 1] : 0;
    for (int m = 0; m < chunk; m++) {
        int idx = b0 + m;
        if (idx < nbins) { bs[idx] = run; run += h[idx]; }
    }
}

__global__ void rank_place_k(const float* __restrict__ coords) {
    int axis = blockIdx.y;
    int i = blockIdx.x * 256 + threadIdx.x;
    int u = coord_bin(coords[i * 3 + axis]);
    int slot = r_base[axis][u] + atomicAdd(&r_cnt[axis][u], 1);
    r_slot[axis][slot] = i;
}

__global__ void rank_rank_k(const float* __restrict__ coords) {
    int axis = blockIdx.y;
    int i = blockIdx.x * 256 + threadIdx.x;
    float ci = coords[i * 3 + axis];
    int u = coord_bin(ci);
    int b = r_base[axis][u], n = r_hist[axis][u];
    int r = 0;
    for (int m = 0; m < n; m++) {
        int j = r_slot[axis][b + m];
        float cj = coords[j * 3 + axis];
        r += (int)((cj < ci) || (cj == ci && j < i));
    }
    g_rank[axis][i] = b + r;
}

// ------------------------- bucket order via counting sort -------------------------
__global__ void key1_k(const float* __restrict__ regions) {
    __shared__ int smax[256];
    int row = blockIdx.y;
    int nh = row >> 3, h = row & 7;
    float qe = 16384.0f / regions[nh * 16 + h];
    float qp = 16384.0f / regions[nh * 16 + 8 + h];
    int i = blockIdx.x * 256 + threadIdx.x;
    int re = (int)floorf((float)g_rank[0][i] / qe) + 1;
    int rp = (int)floorf((float)g_rank[1][i] / qp) + 1;
    b_keys[row][i] = (rp << 16) | re;
    smax[threadIdx.x] = re;
    __syncthreads();
    for (int s = 128; s > 0; s >>= 1) {
        if (threadIdx.x < s) smax[threadIdx.x] = max(smax[threadIdx.x], smax[threadIdx.x + s]);
        __syncthreads();
    }
    if (threadIdx.x == 0) atomicMax(&g_maxre[row], smax[0]);
}

__global__ void key2_k() {
    int row = blockIdx.y;
    int i = blockIdx.x * 256 + threadIdx.x;
    int nb = (int)ceilf(log2f((float)g_maxre[row] + 1.0f));
    int v = b_keys[row][i];
    int key = ((v >> 16) << nb) | (v & 0xffff);
    b_keys[row][i] = key;
    atomicAdd(&b_hist[row][key], 1);
}

__global__ void bucket_place_k() {
    int row = blockIdx.y;
    int i = blockIdx.x * 256 + threadIdx.x;
    int key = b_keys[row][i];
    int slot = b_base[row][key] + atomicAdd(&b_cnt[row][key], 1);
    b_slot[row][slot] = i;
}

__global__ void bucket_pos_k() {
    int row = blockIdx.y;
    int i = blockIdx.x * 256 + threadIdx.x;
    int key = b_keys[row][i];
    int b = b_base[row][key], n = b_hist[row][key];
    int r = 0;
    for (int m = 0; m < n; m++) r += (int)(b_slot[row][b + m] < i);
    g_order[row * NNODE + b + r] = i;
}

// ------------------------- RPE distance weights (all 4 layers) -------------------------
__global__ void w2all_k(const float* __restrict__ wrpe) {   // [4][512][16]
    __shared__ float sq[128];
    int l = blockIdx.x;
    const float* w = wrpe + (size_t)l * 512 * 16;
    int t = threadIdx.x;
    int h = t >> 4, m = t & 15;
    float s = 0.f;
    for (int d = 0; d < 64; d++) s += w[(h * 64 + d) * 16 + m];
    float om = s * (1.0f / 64.0f);
    sq[t] = om * om;
    __syncthreads();
    if (t < 16) {
        int hh = t >> 1, c = t & 1;
        float ww = 0.f;
        for (int kk = 0; kk < 8; kk++) ww += sq[hh * 16 + c * 8 + kk];
        g_W2[l * 16 + t] = ww;
    }
}

// ------------------------- M_h[d][e] = sum_c Wq[d,c] Wk[e,c] / 8 (exact fp32, NT) -------------------------
#define FMA16(av, bv, acc)                                                         \
    acc[0][0]+=av.x*bv.x; acc[0][1]+=av.x*bv.y; acc[0][2]+=av.x*bv.z; acc[0][3]+=av.x*bv.w; \
    acc[1][0]+=av.y*bv.x; acc[1][1]+=av.y*bv.y; acc[1][2]+=av.y*bv.z; acc[1][3]+=av.y*bv.w; \
    acc[2][0]+=av.z*bv.x; acc[2][1]+=av.z*bv.y; acc[2][2]+=av.z*bv.z; acc[2][3]+=av.z*bv.w; \
    acc[3][0]+=av.w*bv.x; acc[3][1]+=av.w*bv.y; acc[3][2]+=av.w*bv.z; acc[3][3]+=av.w*bv.w;

__global__ void __launch_bounds__(256) mh_k(const float* __restrict__ wq,
                                            const float* __restrict__ wk) {
    __shared__ float Aq[64 * 68];   // [d][c]
    __shared__ float Bk[64 * 68];   // [e][c]
    int bx = blockIdx.x;            // l*8 + h
    int l = bx >> 3, h = bx & 7;
    int tid = threadIdx.x;
#pragma unroll
    for (int it = 0; it < 4; it++) {
        int idx = tid + it * 256;
        int d = idx >> 4, c4 = (idx & 15) * 4;
        *(float4*)&Aq[d * 68 + c4] = *(const float4*)&wq[((size_t)(l * 64 + d)) * 512 + h * 64 + c4];
        *(float4*)&Bk[d * 68 + c4] = *(const float4*)&wk[((size_t)(l * 64 + d)) * 512 + h * 64 + c4];
    }
    __syncthreads();
    int tm = tid >> 4, tn = tid & 15;
    float acc[4][4] = {};
#pragma unroll 4
    for (int c = 0; c < 64; c++) {   // contract over head columns c (NT)
        float4 av = make_float4(Aq[(tm * 4 + 0) * 68 + c], Aq[(tm * 4 + 1) * 68 + c],
                                Aq[(tm * 4 + 2) * 68 + c], Aq[(tm * 4 + 3) * 68 + c]);
        float4 bv = make_float4(Bk[(tn * 4 + 0) * 68 + c], Bk[(tn * 4 + 1) * 68 + c],
                                Bk[(tn * 4 + 2) * 68 + c], Bk[(tn * 4 + 3) * 68 + c]);
        FMA16(av, bv, acc)
    }
#pragma unroll
    for (int ii = 0; ii < 4; ii++)
#pragma unroll
        for (int jj = 0; jj < 4; jj++)
            g_M[(size_t)bx * 4096 + (tm * 4 + ii) * 64 + tn * 4 + jj] = 0.125f * acc[ii][jj];
}

// ------------------------- shared LN helper (64-wide rows staged in smem) -------------------------
__device__ __forceinline__ void ln64_smem(float* Xs, float (*redA)[4],
                                          const float* g, const float* b,
                                          float* dst, int row0, int tid) {
    // Xs[r*68+c] holds h rows; writes LN to dst[(row0+r)*64+c]. 256 threads, 4/row.
    int tr = tid >> 2, tp = tid & 3;
    float s = 0.f;
    for (int c = tp * 16; c < tp * 16 + 16; c++) s += Xs[tr * 68 + c];
    redA[tr][tp] = s;
    __syncthreads();
    float mu = (redA[tr][0] + redA[tr][1] + redA[tr][2] + redA[tr][3]) * (1.0f / 64.0f);
    __syncthreads();
    float vs = 0.f;
    for (int c = tp * 16; c < tp * 16 + 16; c++) {
        float d = Xs[tr * 68 + c] - mu;
        vs += d * d;
    }
    redA[tr][tp] = vs;
    __syncthreads();
    float var = (redA[tr][0] + redA[tr][1] + redA[tr][2] + redA[tr][3]) * (1.0f / 64.0f);
    float rs = rsqrtf(var + 1e-5f);
    for (int c = tp * 16; c < tp * 16 + 16; c++)
        dst[(size_t)(row0 + tr) * 64 + c] = (Xs[tr * 68 + c] - mu) * rs * g[c] + b[c];
}

// ------------------------- fused feat encoder + LN1(layer0) (exact FFMA) -------------------------
__global__ void __launch_bounds__(256) ffe_k(
    const float* __restrict__ x,
    const float* __restrict__ W1, const float* __restrict__ b1,
    const float* __restrict__ W2, const float* __restrict__ b2,
    const float* __restrict__ lng, const float* __restrict__ lnb)
{
    __shared__ float Xs16[64 * 17];
    __shared__ float W1s[16 * 68];
    __shared__ float Ts[64 * 68];
    __shared__ float W2s[64 * 68];
    __shared__ float redA[64][4];
    int tid = threadIdx.x;
    int row0 = blockIdx.x * 64;
    {
        int r = tid >> 2, c4 = (tid & 3) * 4;
        float4 xv = *(const float4*)&x[(size_t)(row0 + r) * 16 + c4];
        Xs16[r * 17 + c4 + 0] = xv.x; Xs16[r * 17 + c4 + 1] = xv.y;
        Xs16[r * 17 + c4 + 2] = xv.z; Xs16[r * 17 + c4 + 3] = xv.w;
    }
    if (tid < 16 * 16) {
        int r = tid >> 4, c4 = (tid & 15) * 4;
        *(float4*)&W1s[r * 68 + c4] = *(const float4*)&W1[(size_t)r * 64 + c4];
    }
#pragma unroll
    for (int it = 0; it < 4; it++) {
        int idx = tid + it * 256;
        int r = idx >> 4, c4 = (idx & 15) * 4;
        *(float4*)&W2s[r * 68 + c4] = *(const float4*)&W2[(size_t)r * 64 + c4];
    }
    __syncthreads();
    int tm = tid >> 4, tn = tid & 15;
    float acc[4][4] = {};
#pragma unroll
    for (int kk = 0; kk < 16; kk++) {
        float4 av = make_float4(Xs16[(tm * 4 + 0) * 17 + kk], Xs16[(tm * 4 + 1) * 17 + kk],
                                Xs16[(tm * 4 + 2) * 17 + kk], Xs16[(tm * 4 + 3) * 17 + kk]);
        float4 bv = *(const float4*)&W1s[kk * 68 + tn * 4];
        FMA16(av, bv, acc)
    }
#pragma unroll
    for (int ii = 0; ii < 4; ii++)
#pragma unroll
        for (int jj = 0; jj < 4; jj++)
            Ts[(tm * 4 + ii) * 68 + tn * 4 + jj] = fmaxf(acc[ii][jj] + b1[tn * 4 + jj], 0.f);
    __syncthreads();
    float acc2[4][4] = {};
#pragma unroll 8
    for (int kk = 0; kk < 64; kk++) {
        float4 av = make_float4(Ts[(tm * 4 + 0) * 68 + kk], Ts[(tm * 4 + 1) * 68 + kk],
                                Ts[(tm * 4 + 2) * 68 + kk], Ts[(tm * 4 + 3) * 68 + kk]);
        float4 bv = *(const float4*)&W2s[kk * 68 + tn * 4];
        FMA16(av, bv, acc2)
    }
    __syncthreads();
#pragma unroll
    for (int ii = 0; ii < 4; ii++) {
        int r = row0 + tm * 4 + ii;
#pragma unroll
        for (int jj = 0; jj < 4; jj++) {
            int c = tn * 4 + jj;
            float vv = acc2[ii][jj] + b2[c];
            g_h[(size_t)r * 64 + c] = vv;
            g_hist[(size_t)r * 320 + c] = vv;
            W2s[(tm * 4 + ii) * 68 + c] = vv;   // stage for LN
        }
    }
    __syncthreads();
    ln64_smem(W2s, redA, lng, lnb, (float*)g_xn, row0, tid);
}

// ------------------------- fused attention on pre-normalized X -------------------------
__global__ void __launch_bounds__(256) attn_k(
    const float* __restrict__ coords, const float* __restrict__ W2row,
    const float* __restrict__ Mbase, const float* __restrict__ wv_l)
{
    extern __shared__ unsigned sh[];
    unsigned* Xs = sh;                 // X tf32 [64][68]; later Wv tf32
    unsigned* Ms = sh + 64 * 68;       // M tf32; later S float / P tf32
    unsigned* Ts = sh + 2 * 64 * 68;   // T tf32; later R tf32
    __shared__ int   nd[64];
    __shared__ float cx[64], cy[64], redm[4][64], reds[4][64];

    int tid = threadIdx.x;
    int blk = blockIdx.x, h = blockIdx.y, nh = blockIdx.z;
    int row = nh * 8 + h;
    const int* ord = g_order + row * NNODE + blk * 64;
    if (tid < 64) {
        int nn = ord[tid];
        nd[tid] = nn;
        cx[tid] = coords[nn * 3 + 0];
        cy[tid] = coords[nn * 3 + 1];
    }
    __syncthreads();

    // gather pre-normalized rows (convert to tf32 on load) + load M
    const float* Mg = Mbase + (size_t)h * 4096;
    for (int idx = tid; idx < 4096; idx += 256) {
        int i = idx >> 6, d = idx & 63;
        Xs[i * 68 + d] = f2tf(g_xn[(size_t)nd[i] * 64 + d]);
        Ms[i * 68 + d] = f2tf(Mg[i * 64 + d]);
    }
    __syncthreads();

    int wid = tid >> 5, lane = tid & 31;
    int g = lane >> 2, t = lane & 3;
    int r0 = (wid & 3) * 16, c0 = (wid >> 2) * 32;

    // phase 1: T = X @ M
    {
        float acc[4][4] = {};
#pragma unroll
        for (int ks = 0; ks < 8; ks++) {
            int k0 = ks * 8;
            unsigned a0 = Xs[(r0 + g) * 68 + k0 + t];
            unsigned a1 = Xs[(r0 + g + 8) * 68 + k0 + t];
            unsigned a2 = Xs[(r0 + g) * 68 + k0 + t + 4];
            unsigned a3 = Xs[(r0 + g + 8) * 68 + k0 + t + 4];
#pragma unroll
            for (int nt = 0; nt < 4; nt++) {
                int n = c0 + nt * 8 + g;
                unsigned b0 = Ms[(k0 + t) * 68 + n];
                unsigned b1 = Ms[(k0 + t + 4) * 68 + n];
                mma_tf32(acc[nt], a0, a1, a2, a3, b0, b1);
            }
        }
#pragma unroll
        for (int nt = 0; nt < 4; nt++)
#pragma unroll
            for (int cr = 0; cr < 4; cr++) {
                int r = r0 + g + (cr >> 1) * 8;
                int c = c0 + nt * 8 + 2 * t + (cr & 1);
                Ts[r * 68 + c] = f2tf(acc[nt][cr]);
            }
    }
    __syncthreads();

    // phase 2: S = T @ X^T  (+ RPE), write transposed into Ms
    float W0 = W2row[h * 2 + 0], W1 = W2row[h * 2 + 1];
    {
        float acc[4][4] = {};
#pragma unroll
        for (int ks = 0; ks < 8; ks++) {
            int k0 = ks * 8;
            unsigned a0 = Ts[(r0 + g) * 68 + k0 + t];
            unsigned a1 = Ts[(r0 + g + 8) * 68 + k0 + t];
            unsigned a2 = Ts[(r0 + g) * 68 + k0 + t + 4];
            unsigned a3 = Ts[(r0 + g + 8) * 68 + k0 + t + 4];
#pragma unroll
            for (int nt = 0; nt < 4; nt++) {
                int j = c0 + nt * 8 + g;
                unsigned b0 = Xs[j * 68 + k0 + t];
                unsigned b1 = Xs[j * 68 + k0 + t + 4];
                mma_tf32(acc[nt], a0, a1, a2, a3, b0, b1);
            }
        }
        float* Ss = (float*)Ms;
#pragma unroll
        for (int nt = 0; nt < 4; nt++) {
            int j0 = c0 + nt * 8 + 2 * t;
#pragma unroll
            for (int cr = 0; cr < 4; cr++) {
                int i = r0 + g + (cr >> 1) * 8;
                int j = j0 + (cr & 1);
                float dx = cx[i] - cx[j], dy = cy[i] - cy[j];
                Ss[j * 68 + i] = acc[nt][cr] - W0 * dx * dx - W1 * dy * dy;
            }
        }
    }
    __syncthreads();

    // softmax over j per query i (Ss layout [j][i]) — fast exp/log
    float* Ss = (float*)Ms;
    int ci = tid & 63, seg = tid >> 6;
    float ml = -3.0e38f;
#pragma unroll
    for (int jj = 0; jj < 16; jj++) ml = fmaxf(ml, Ss[(seg * 16 + jj) * 68 + ci]);
    redm[seg][ci] = ml;
    __syncthreads();
    float mm = fmaxf(fmaxf(redm[0][ci], redm[1][ci]), fmaxf(redm[2][ci], redm[3][ci]));
    float ev[16];
    float sl = 0.f;
#pragma unroll
    for (int jj = 0; jj < 16; jj++) {
        float e = __expf(Ss[(seg * 16 + jj) * 68 + ci] - mm);
        ev[jj] = e;
        sl += e;
    }
    reds[seg][ci] = sl;
    __syncthreads();
    float ssum = reds[0][ci] + reds[1][ci] + reds[2][ci] + reds[3][ci];
    float inv = 1.0f / ssum;
    if (seg == 0) g_lser[row * NNODE + nd[ci]] = mm + __logf(ssum);
    unsigned* Ps = Ms;
#pragma unroll
    for (int jj = 0; jj < 16; jj++)
        Ps[(seg * 16 + jj) * 68 + ci] = f2tf(ev[jj] * inv);
    __syncthreads();

    // phase 3: R = P @ X
    float racc[4][4] = {};
#pragma unroll
    for (int ks = 0; ks < 8; ks++) {
        int k0 = ks * 8;
        unsigned a0 = Ps[(k0 + t) * 68 + r0 + g];
        unsigned a1 = Ps[(k0 + t) * 68 + r0 + g + 8];
        unsigned a2 = Ps[(k0 + t + 4) * 68 + r0 + g];
        unsigned a3 = Ps[(k0 + t + 4) * 68 + r0 + g + 8];
#pragma unroll
        for (int nt = 0; nt < 4; nt++) {
            int n = c0 + nt * 8 + g;
            unsigned b0 = Xs[(k0 + t) * 68 + n];
            unsigned b1 = Xs[(k0 + t + 4) * 68 + n];
            mma_tf32(racc[nt], a0, a1, a2, a3, b0, b1);
        }
    }
    __syncthreads();

    // write R (tf32) into Ts; load Wv_h into Xs
#pragma unroll
    for (int nt = 0; nt < 4; nt++)
#pragma unroll
        for (int cr = 0; cr < 4; cr++) {
            int r = r0 + g + (cr >> 1) * 8;
            int c = c0 + nt * 8 + 2 * t + (cr & 1);
            Ts[r * 68 + c] = f2tf(racc[nt][cr]);
        }
    for (int idx = tid; idx < 4096; idx += 256) {
        int d = idx >> 6, e = idx & 63;
        Xs[d * 68 + e] = f2tf(wv_l[(size_t)d * 512 + h * 64 + e]);
    }
    __syncthreads();

    // phase 4: O = R @ Wv
    float oacc[4][4] = {};
#pragma unroll
    for (int ks = 0; ks < 8; ks++) {
        int k0 = ks * 8;
        unsigned a0 = Ts[(r0 + g) * 68 + k0 + t];
        unsigned a1 = Ts[(r0 + g + 8) * 68 + k0 + t];
        unsigned a2 = Ts[(r0 + g) * 68 + k0 + t + 4];
        unsigned a3 = Ts[(r0 + g + 8) * 68 + k0 + t + 4];
#pragma unroll
        for (int nt = 0; nt < 4; nt++) {
            int n = c0 + nt * 8 + g;
            unsigned b0 = Xs[(k0 + t) * 68 + n];
            unsigned b1 = Xs[(k0 + t + 4) * 68 + n];
            mma_tf32(oacc[nt], a0, a1, a2, a3, b0, b1);
        }
    }
#pragma unroll
    for (int nt = 0; nt < 4; nt++) {
        int d0 = c0 + nt * 8 + 2 * t;
        int iA = r0 + g, iB = r0 + g + 8;
        *(float2*)&g_outr[((size_t)row * NNODE + nd[iA]) * 64 + d0] =
            make_float2(oacc[nt][0], oacc[nt][1]);
        *(float2*)&g_outr[((size_t)row * NNODE + nd[iB]) * 64 + d0] =
            make_float2(oacc[nt][2], oacc[nt][3]);
    }
}

// ------------------------- out-projection with fused lse-combine (K=512) -------------------------
__global__ void __launch_bounds__(256) outproj_k(
    const float* __restrict__ ow, const float* __restrict__ ob, float* __restrict__ hbuf)
{
    __shared__ unsigned As[64 * 68];
    __shared__ unsigned Bs[64 * 68];
    __shared__ float w0s[64], w1s[64];
    int tid = threadIdx.x;
    int row0 = blockIdx.x * 64;
    int wid = tid >> 5, lane = tid & 31;
    int g = lane >> 2, t = lane & 3;
    int r0 = (wid & 3) * 16, c0 = (wid >> 2) * 32;
    float acc[4][4] = {};
    for (int h = 0; h < 8; h++) {
        __syncthreads();
        if (tid < 64) {
            int node = row0 + tid;
            float l0 = g_lser[h * NNODE + node];
            float l1 = g_lser[(8 + h) * NNODE + node];
            float m = fmaxf(l0, l1);
            float e0 = __expf(l0 - m), e1 = __expf(l1 - m);
            float inv = 1.0f / (e0 + e1);
            w0s[tid] = e0 * inv;
            w1s[tid] = e1 * inv;
        }
        __syncthreads();
#pragma unroll
        for (int it = 0; it < 4; it++) {
            int idx = tid + it * 256;
            int r = idx >> 4, c4 = (idx & 15) * 4;
            int node = row0 + r;
            float4 o0 = *(const float4*)&g_outr[((size_t)h * NNODE + node) * 64 + c4];
            float4 o1 = *(const float4*)&g_outr[((size_t)(8 + h) * NNODE + node) * 64 + c4];
            float w0 = w0s[r], w1 = w1s[r];
            As[r * 68 + c4 + 0] = f2tf(w0 * o0.x + w1 * o1.x);
            As[r * 68 + c4 + 1] = f2tf(w0 * o0.y + w1 * o1.y);
            As[r * 68 + c4 + 2] = f2tf(w0 * o0.z + w1 * o1.z);
            As[r * 68 + c4 + 3] = f2tf(w0 * o0.w + w1 * o1.w);
            float4 bv = *(const float4*)&ow[(size_t)(h * 64 + r) * 64 + c4];
            Bs[r * 68 + c4 + 0] = f2tf(bv.x); Bs[r * 68 + c4 + 1] = f2tf(bv.y);
            Bs[r * 68 + c4 + 2] = f2tf(bv.z); Bs[r * 68 + c4 + 3] = f2tf(bv.w);
        }
        __syncthreads();
#pragma unroll
        for (int ks = 0; ks < 8; ks++) {
            int k0 = ks * 8;
            unsigned a0 = As[(r0 + g) * 68 + k0 + t];
            unsigned a1 = As[(r0 + g + 8) * 68 + k0 + t];
            unsigned a2 = As[(r0 + g) * 68 + k0 + t + 4];
            unsigned a3 = As[(r0 + g + 8) * 68 + k0 + t + 4];
#pragma unroll
            for (int nt = 0; nt < 4; nt++) {
                int n = c0 + nt * 8 + g;
                unsigned b0 = Bs[(k0 + t) * 68 + n];
                unsigned b1 = Bs[(k0 + t + 4) * 68 + n];
                mma_tf32(acc[nt], a0, a1, a2, a3, b0, b1);
            }
        }
    }
#pragma unroll
    for (int nt = 0; nt < 4; nt++) {
#pragma unroll
        for (int cr = 0; cr < 4; cr++) {
            int r = row0 + r0 + g + (cr >> 1) * 8;
            int ccol = c0 + nt * 8 + 2 * t + (cr & 1);
            float vv = acc[nt][cr] + ob[ccol] + hbuf[(size_t)r * 64 + ccol];
            hbuf[(size_t)r * 64 + ccol] = vv;
        }
    }
}

// ------------------------- fused LN2 + FFN + residual + hist + LN1(next) -------------------------
__global__ void __launch_bounds__(256) ffn_k(
    float* __restrict__ hbuf, const float* __restrict__ g, const float* __restrict__ b,
    const float* __restrict__ W1, const float* __restrict__ b1,
    const float* __restrict__ W2, const float* __restrict__ b2,
    float* __restrict__ hist,
    const float* __restrict__ lnn_g, const float* __restrict__ lnn_b)
{
    __shared__ float Xs[64 * 68];
    __shared__ float Ws[64 * 68];
    __shared__ float redA[64][4];
    int tid = threadIdx.x;
    int row0 = blockIdx.x * 64;
#pragma unroll
    for (int it = 0; it < 4; it++) {
        int idx = tid + it * 256;
        int r = idx >> 4, c4 = (idx & 15) * 4;
        *(float4*)&Xs[r * 68 + c4] = *(const float4*)&hbuf[(size_t)(row0 + r) * 64 + c4];
        *(float4*)&Ws[r * 68 + c4] = *(const float4*)&W1[(size_t)r * 64 + c4];
    }
    __syncthreads();
    int tr = tid >> 2, tp = tid & 3;
    float s = 0.f;
    for (int c = tp * 16; c < tp * 16 + 16; c++) s += Xs[tr * 68 + c];
    redA[tr][tp] = s;
    __syncthreads();
    float mu = (redA[tr][0] + redA[tr][1] + redA[tr][2] + redA[tr][3]) * (1.0f / 64.0f);
    __syncthreads();
    float vs = 0.f;
    for (int c = tp * 16; c < tp * 16 + 16; c++) {
        float d = Xs[tr * 68 + c] - mu;
        vs += d * d;
    }
    redA[tr][tp] = vs;
    __syncthreads();
    float var = (redA[tr][0] + redA[tr][1] + redA[tr][2] + redA[tr][3]) * (1.0f / 64.0f);
    float rs = rsqrtf(var + 1e-5f);
    for (int c = tp * 16; c < tp * 16 + 16; c++)
        Xs[tr * 68 + c] = (Xs[tr * 68 + c] - mu) * rs * g[c] + b[c];
    __syncthreads();
    int tm = tid >> 4, tn = tid & 15;
    float acc[4][4] = {};
#pragma unroll 8
    for (int kk = 0; kk < 64; kk++) {
        float4 bv = *(const float4*)&Ws[kk * 68 + tn * 4];
        float4 av = make_float4(Xs[(tm * 4 + 0) * 68 + kk], Xs[(tm * 4 + 1) * 68 + kk],
                                Xs[(tm * 4 + 2) * 68 + kk], Xs[(tm * 4 + 3) * 68 + kk]);
        FMA16(av, bv, acc)
    }
    __syncthreads();
#pragma unroll
    for (int ii = 0; ii < 4; ii++)
#pragma unroll
        for (int jj = 0; jj < 4; jj++)
            Xs[(tm * 4 + ii) * 68 + tn * 4 + jj] = fmaxf(acc[ii][jj] + b1[tn * 4 + jj], 0.f);
#pragma unroll
    for (int it = 0; it < 4; it++) {
        int idx = tid + it * 256;
        int r = idx >> 4, c4 = (idx & 15) * 4;
        *(float4*)&Ws[r * 68 + c4] = *(const float4*)&W2[(size_t)r * 64 + c4];
    }
    __syncthreads();
    float acc2[4][4] = {};
#pragma unroll 8
    for (int kk = 0; kk < 64; kk++) {
        float4 bv = *(const float4*)&Ws[kk * 68 + tn * 4];
        float4 av = make_float4(Xs[(tm * 4 + 0) * 68 + kk], Xs[(tm * 4 + 1) * 68 + kk],
                                Xs[(tm * 4 + 2) * 68 + kk], Xs[(tm * 4 + 3) * 68 + kk]);
        FMA16(av, bv, acc2)
    }
    __syncthreads();
#pragma unroll
    for (int ii = 0; ii < 4; ii++) {
        int r = row0 + tm * 4 + ii;
#pragma unroll
        for (int jj = 0; jj < 4; jj++) {
            int c = tn * 4 + jj;
            float vv = acc2[ii][jj] + b2[c] + hbuf[(size_t)r * 64 + c];
            hbuf[(size_t)r * 64 + c] = vv;
            hist[(size_t)r * 320 + c] = vv;
            Ws[(tm * 4 + ii) * 68 + c] = vv;   // stage for next-layer LN
        }
    }
    if (lnn_g) {
        __syncthreads();
        ln64_smem(Ws, redA, lnn_g, lnn_b, (float*)g_xn, row0, tid);
    }
}

// ------------------------- scalar FFMA SGEMM (head) -------------------------
__global__ void __launch_bounds__(256) gemm_k(
    const float* __restrict__ A, const float* __restrict__ B, float* __restrict__ C,
    const float* __restrict__ bias, const float* __restrict__ resid,
    int M, int N, int K, int act)
{
    __shared__ float As[16][68];
    __shared__ float Bs[16][68];
    int tid = threadIdx.x;
    int row0 = blockIdx.x * 64, col0 = blockIdx.y * 64;
    int tm = tid >> 4, tn = tid & 15;
    int arow = tid >> 2, ac = tid & 3;
    int bk = tid >> 4, bn = tid & 15;
    float acc[4][4] = {};
    for (int k0 = 0; k0 < K; k0 += 16) {
        float4 a = *(const float4*)&A[(size_t)(row0 + arow) * K + k0 + ac * 4];
        As[ac * 4 + 0][arow] = a.x; As[ac * 4 + 1][arow] = a.y;
        As[ac * 4 + 2][arow] = a.z; As[ac * 4 + 3][arow] = a.w;
        int bcol = col0 + bn * 4;
        float4 bv = make_float4(0.f, 0.f, 0.f, 0.f);
        if (bcol < N) bv = *(const float4*)&B[(size_t)(k0 + bk) * N + bcol];
        *(float4*)&Bs[bk][bn * 4] = bv;
        __syncthreads();
#pragma unroll
        for (int kk = 0; kk < 16; kk++) {
            float4 av = *(const float4*)&As[kk][tm * 4];
            float4 bw = *(const float4*)&Bs[kk][tn * 4];
            FMA16(av, bw, acc)
        }
        __syncthreads();
    }
#pragma unroll
    for (int ii = 0; ii < 4; ii++) {
        int r = row0 + tm * 4 + ii;
#pragma unroll
        for (int jj = 0; jj < 4; jj++) {
            int ccol = col0 + tn * 4 + jj;
            if (ccol < N) {
                float vv = acc[ii][jj];
                if (bias) vv += bias[ccol];
                if (act == 1) vv = fmaxf(vv, 0.f);
                else if (act == 2) vv = tanhf(vv);
                if (resid) vv += resid[(size_t)r * N + ccol];
                C[(size_t)r * N + ccol] = vv;
            }
        }
    }
}

// ------------------------- LayerNorm 256 + tanh, warp per row -------------------------
__global__ void ln256w_k(const float* __restrict__ in, float* __restrict__ out,
                         const float* __restrict__ g, const float* __restrict__ b) {
    int w = threadIdx.x >> 5, lane = threadIdx.x & 31;
    int row = blockIdx.x * 8 + w;
    const float* xr = in + (size_t)row * 256;
    float x[8];
    float s = 0.f;
#pragma unroll
    for (int m = 0; m < 8; m++) { x[m] = xr[lane + 32 * m]; s += x[m]; }
    for (int o = 16; o; o >>= 1) s += __shfl_xor_sync(0xffffffffu, s, o);
    float mu = s * (1.0f / 256.0f);
    float vs = 0.f;
#pragma unroll
    for (int m = 0; m < 8; m++) { float d = x[m] - mu; vs += d * d; }
    for (int o = 16; o; o >>= 1) vs += __shfl_xor_sync(0xffffffffu, vs, o);
    float rs = rsqrtf(vs * (1.0f / 256.0f) + 1e-5f);
#pragma unroll
    for (int m = 0; m < 8; m++) {
        int c = lane + 32 * m;
        out[(size_t)row * 256 + c] = tanhf((x[m] - mu) * rs * g[c] + b[c]);
    }
}

// ------------------------- reductions + final projection -------------------------
__global__ void red1_k(const float* __restrict__ t) {
    __shared__ float sm[256];
    int blk = blockIdx.x, tid = threadIdx.x;
    int col = tid & 31, r0 = tid >> 5;
    float s = 0.f;
    for (int r = r0; r < 128; r += 8) s += t[(size_t)(blk * 128 + r) * 32 + col];
    sm[tid] = s;
    __syncthreads();
    for (int s2 = 4; s2; s2 >>= 1) {
        if (r0 < s2) sm[tid] += sm[tid + s2 * 32];
        __syncthreads();
    }
    if (r0 == 0) g_part[blk * 32 + col] = sm[col];
}

__global__ void red2_k(const float* __restrict__ pw, const float* __restrict__ pb,
                       float* __restrict__ out) {
    __shared__ float mean[32];
    int t = threadIdx.x;
    if (t < 32) {
        float s = 0.f;
        for (int b = 0; b < 128; b++) s += g_part[b * 32 + t];
        mean[t] = s * (1.0f / 16384.0f);
    }
    __syncthreads();
    if (t < 32) {
        float s = pb[t];
        for (int c = 0; c < 32; c++) s += mean[c] * pw[c * 32 + t];
        out[t] = s;
    }
}

// ------------------------- host orchestration -------------------------
extern "C" void kernel_launch(void* const* d_in, const int* in_sizes, int n_in,
                              void* d_out, int out_size)
{
    const float* x      = (const float*)d_in[0];
    const float* coords = (const float*)d_in[1];
    const float* regions= (const float*)d_in[3];
    const float* fe_w1  = (const float*)d_in[4];
    const float* fe_b1  = (const float*)d_in[5];
    const float* fe_w2  = (const float*)d_in[6];
    const float* fe_b2  = (const float*)d_in[7];
    const float* ln1_g  = (const float*)d_in[8];
    const float* ln1_b  = (const float*)d_in[9];
    const float* wq     = (const float*)d_in[10];
    const float* wk     = (const float*)d_in[11];
    const float* wv     = (const float*)d_in[12];
    const float* wrpe   = (const float*)d_in[13];
    const float* ow     = (const float*)d_in[14];
    const float* ob     = (const float*)d_in[15];
    const float* ln2_g  = (const float*)d_in[16];
    const float* ln2_b  = (const float*)d_in[17];
    const float* f1w    = (const float*)d_in[18];
    const float* f1b    = (const float*)d_in[19];
    const float* f2w    = (const float*)d_in[20];
    const float* f2b    = (const float*)d_in[21];
    const float* Wcat   = (const float*)d_in[22];
    const float* m1w    = (const float*)d_in[23];
    const float* m1b    = (const float*)d_in[24];
    const float* mlng   = (const float*)d_in[25];
    const float* mlnb   = (const float*)d_in[26];
    const float* m2w    = (const float*)d_in[27];
    const float* m2b    = (const float*)d_in[28];
    const float* pw     = (const float*)d_in[29];
    const float* pb     = (const float*)d_in[30];
    float* out = (float*)d_out;

    cudaFuncSetAttribute(attn_k, cudaFuncAttributeMaxDynamicSharedMemorySize, 52224);

    float *p_h, *p_hist, *p_t0, *p_u, *p_u2, *p_t, *p_w2, *p_M;
    int *p_rhist, *p_rbase, *p_bhist, *p_bbase;
    cudaGetSymbolAddress((void**)&p_h,    g_h);
    cudaGetSymbolAddress((void**)&p_hist, g_hist);
    cudaGetSymbolAddress((void**)&p_t0,   g_t0);
    cudaGetSymbolAddress((void**)&p_u,    g_u);
    cudaGetSymbolAddress((void**)&p_u2,   g_u2);
    cudaGetSymbolAddress((void**)&p_t,    g_t);
    cudaGetSymbolAddress((void**)&p_w2,   g_W2);
    cudaGetSymbolAddress((void**)&p_M,    g_M);
    cudaGetSymbolAddress((void**)&p_rhist, r_hist);
    cudaGetSymbolAddress((void**)&p_rbase, r_base);
    cudaGetSymbolAddress((void**)&p_bhist, b_hist);
    cudaGetSymbolAddress((void**)&p_bbase, b_base);

    const int M = NNODE;

    // ---- bucket ordering via counting sorts ----
    zero_k<<<512, 256>>>();
    rank_hist_k<<<dim3(64, 2), 256>>>(coords);
    scan_k<<<2, 1024>>>(p_rhist, p_rbase, NNODE, NNODE);
    rank_place_k<<<dim3(64, 2), 256>>>(coords);
    rank_rank_k<<<dim3(64, 2), 256>>>(coords);
    key1_k<<<dim3(64, 16), 256>>>(regions);
    key2_k<<<dim3(64, 16), 256>>>();
    scan_k<<<16, 1024>>>(p_bhist, p_bbase, KBINS, KBINS);
    bucket_place_k<<<dim3(64, 16), 256>>>();
    bucket_pos_k<<<dim3(64, 16), 256>>>();
    w2all_k<<<4, 128>>>(wrpe);
    mh_k<<<32, 256>>>(wq, wk);

    // feat encoder + LN1(layer 0)
    ffe_k<<<256, 256>>>(x, fe_w1, fe_b1, fe_w2, fe_b2, ln1_g, ln1_b);

    for (int l = 0; l < 4; l++) {
        attn_k<<<dim3(256, 8, 2), 256, 52224>>>(coords, p_w2 + l * 16,
                                                p_M + (size_t)l * 8 * 4096,
                                                wv + (size_t)l * 64 * 512);
        outproj_k<<<256, 256>>>(ow + (size_t)l * 512 * 64, ob + l * 64, p_h);
        const float* nlg = (l < 3) ? (ln1_g + (l + 1) * 64) : nullptr;
        const float* nlb = (l < 3) ? (ln1_b + (l + 1) * 64) : nullptr;
        ffn_k<<<256, 256>>>(p_h, ln2_g + l * 64, ln2_b + l * 64,
                            f1w + (size_t)l * 64 * 64, f1b + l * 64,
                            f2w + (size_t)l * 64 * 64, f2b + l * 64,
                            p_hist + (l + 1) * 64, nlg, nlb);
    }

    gemm_k<<<dim3(256, 1), 256>>>(p_hist, Wcat, p_t0, nullptr, nullptr, M, 32, 320, 2);
    gemm_k<<<dim3(256, 4), 256>>>(p_t0, m1w, p_u, m1b, nullptr, M, 256, 32, 0);
    ln256w_k<<<2048, 256>>>(p_u, p_u2, mlng, mlnb);
    gemm_k<<<dim3(256, 1), 256>>>(p_u2, m2w, p_t, m2b, p_t0, M, 32, 256, 0);
    red1_k<<<128, 256>>>(p_t);
    red2_k<<<1, 256>>>(pw, pb, out);
}

// round 9
// speedup vs baseline: 2.2719x; 1.0917x over previous
#include <cuda_runtime.h>
#include <cuda_bf16.h>
#include <math.h>

#define NNODE 16384
#define HEADS 8
#define DIM   64
#define HDIM  512
#define KBINS 40960

// ------------------------- device scratch (no allocs allowed) -------------------------
__device__ int   g_rank[2][NNODE];
__device__ int   g_order[16 * NNODE];
__device__ float g_h[NNODE * DIM];
__device__ float g_xn[NNODE * DIM];          // LN1(h) for the upcoming layer
__device__ float g_T[NNODE * HDIM];          // T = Xn @ M_h  (per layer)
__device__ float g_hist[NNODE * 320];
__device__ float g_outr[16 * NNODE * DIM];   // R = P@X  [nh*8+h][node][d]
__device__ float g_lser[16 * NNODE];
__device__ float g_W2[4 * 16];               // [layer][h][c]
__device__ float g_M[4 * 8 * 64 * 64];       // [layer][head][d][e] = sum_c Wq[d,c]Wk[e,c]/8
__device__ float g_G[4 * 8 * 64 * 64];       // [layer][head][d][e] = Wv_h @ Ow_h (exact)
__device__ float g_t0[NNODE * 32];
__device__ float g_u [NNODE * 256];
__device__ float g_u2[NNODE * 256];
__device__ float g_t [NNODE * 32];
__device__ float g_part[128 * 32];

// sorting scratch
__device__ int r_hist[2][NNODE];
__device__ int r_base[2][NNODE];
__device__ int r_cnt [2][NNODE];
__device__ int r_slot[2][NNODE];
__device__ int b_keys[16][NNODE];
__device__ int b_hist[16][KBINS];
__device__ int b_base[16][KBINS];
__device__ int b_cnt [16][KBINS];
__device__ int b_slot[16][NNODE];
__device__ int g_maxre[16];

// ------------------------- tf32 helpers -------------------------
__device__ __forceinline__ unsigned f2tf(float f) {
    unsigned u;
    asm("cvt.rna.tf32.f32 %0, %1;" : "=r"(u) : "f"(f));
    return u;
}

__device__ __forceinline__ void mma_tf32(float c[4], unsigned a0, unsigned a1,
                                         unsigned a2, unsigned a3,
                                         unsigned b0, unsigned b1) {
    asm volatile(
        "mma.sync.aligned.m16n8k8.row.col.f32.tf32.tf32.f32 "
        "{%0,%1,%2,%3}, {%4,%5,%6,%7}, {%8,%9}, {%0,%1,%2,%3};"
        : "+f"(c[0]), "+f"(c[1]), "+f"(c[2]), "+f"(c[3])
        : "r"(a0), "r"(a1), "r"(a2), "r"(a3), "r"(b0), "r"(b1));
}

// ------------------------- zero all counting scratch -------------------------
__global__ void zero_k() {
    int gid = blockIdx.x * 256 + threadIdx.x;
    int stride = gridDim.x * 256;
    for (int i = gid; i < 2 * NNODE; i += stride) { ((int*)r_hist)[i] = 0; ((int*)r_cnt)[i] = 0; }
    for (int i = gid; i < 16 * KBINS; i += stride) { ((int*)b_hist)[i] = 0; ((int*)b_cnt)[i] = 0; }
    if (gid < 16) g_maxre[gid] = 0;
}

// ------------------------- coordinate ranks via counting -------------------------
__device__ __forceinline__ int coord_bin(float c) {
    int u = (int)(c * 16384.0f);
    return min(16383, max(0, u));
}

__global__ void rank_hist_k(const float* __restrict__ coords) {
    int axis = blockIdx.y;
    int i = blockIdx.x * 256 + threadIdx.x;
    int u = coord_bin(coords[i * 3 + axis]);
    atomicAdd(&r_hist[axis][u], 1);
}

__global__ void __launch_bounds__(1024) scan_k(const int* __restrict__ hist,
                                               int* __restrict__ base,
                                               int nbins, int rowstride) {
    __shared__ int ss[1024];
    int row = blockIdx.x;
    const int* h = hist + (size_t)row * rowstride;
    int* bs = base + (size_t)row * rowstride;
    int t = threadIdx.x;
    int chunk = (nbins + 1023) >> 10;
    int b0 = t * chunk;
    int s = 0;
    for (int m = 0; m < chunk; m++) { int idx = b0 + m; if (idx < nbins) s += h[idx]; }
    ss[t] = s;
    __syncthreads();
    for (int d = 1; d < 1024; d <<= 1) {
        int v = (t >= d) ? ss[t - d] : 0;
        __syncthreads();
        ss[t] += v;
        __syncthreads();
    }
    int run = (t > 0) ? ss[t - 1] : 0;
    for (int m = 0; m < chunk; m++) {
        int idx = b0 + m;
        if (idx < nbins) { bs[idx] = run; run += h[idx]; }
    }
}

__global__ void rank_place_k(const float* __restrict__ coords) {
    int axis = blockIdx.y;
    int i = blockIdx.x * 256 + threadIdx.x;
    int u = coord_bin(coords[i * 3 + axis]);
    int slot = r_base[axis][u] + atomicAdd(&r_cnt[axis][u], 1);
    r_slot[axis][slot] = i;
}

__global__ void rank_rank_k(const float* __restrict__ coords) {
    int axis = blockIdx.y;
    int i = blockIdx.x * 256 + threadIdx.x;
    float ci = coords[i * 3 + axis];
    int u = coord_bin(ci);
    int b = r_base[axis][u], n = r_hist[axis][u];
    int r = 0;
    for (int m = 0; m < n; m++) {
        int j = r_slot[axis][b + m];
        float cj = coords[j * 3 + axis];
        r += (int)((cj < ci) || (cj == ci && j < i));
    }
    g_rank[axis][i] = b + r;
}

// ------------------------- bucket order via counting sort -------------------------
__global__ void key1_k(const float* __restrict__ regions) {
    __shared__ int smax[256];
    int row = blockIdx.y;
    int nh = row >> 3, h = row & 7;
    float qe = 16384.0f / regions[nh * 16 + h];
    float qp = 16384.0f / regions[nh * 16 + 8 + h];
    int i = blockIdx.x * 256 + threadIdx.x;
    int re = (int)floorf((float)g_rank[0][i] / qe) + 1;
    int rp = (int)floorf((float)g_rank[1][i] / qp) + 1;
    b_keys[row][i] = (rp << 16) | re;
    smax[threadIdx.x] = re;
    __syncthreads();
    for (int s = 128; s > 0; s >>= 1) {
        if (threadIdx.x < s) smax[threadIdx.x] = max(smax[threadIdx.x], smax[threadIdx.x + s]);
        __syncthreads();
    }
    if (threadIdx.x == 0) atomicMax(&g_maxre[row], smax[0]);
}

__global__ void key2_k() {
    int row = blockIdx.y;
    int i = blockIdx.x * 256 + threadIdx.x;
    int nb = (int)ceilf(log2f((float)g_maxre[row] + 1.0f));
    int v = b_keys[row][i];
    int key = ((v >> 16) << nb) | (v & 0xffff);
    b_keys[row][i] = key;
    atomicAdd(&b_hist[row][key], 1);
}

__global__ void bucket_place_k() {
    int row = blockIdx.y;
    int i = blockIdx.x * 256 + threadIdx.x;
    int key = b_keys[row][i];
    int slot = b_base[row][key] + atomicAdd(&b_cnt[row][key], 1);
    b_slot[row][slot] = i;
}

__global__ void bucket_pos_k() {
    int row = blockIdx.y;
    int i = blockIdx.x * 256 + threadIdx.x;
    int key = b_keys[row][i];
    int b = b_base[row][key], n = b_hist[row][key];
    int r = 0;
    for (int m = 0; m < n; m++) r += (int)(b_slot[row][b + m] < i);
    g_order[row * NNODE + b + r] = i;
}

// ------------------------- RPE distance weights (all 4 layers) -------------------------
__global__ void w2all_k(const float* __restrict__ wrpe) {   // [4][512][16]
    __shared__ float sq[128];
    int l = blockIdx.x;
    const float* w = wrpe + (size_t)l * 512 * 16;
    int t = threadIdx.x;
    int h = t >> 4, m = t & 15;
    float s = 0.f;
    for (int d = 0; d < 64; d++) s += w[(h * 64 + d) * 16 + m];
    float om = s * (1.0f / 64.0f);
    sq[t] = om * om;
    __syncthreads();
    if (t < 16) {
        int hh = t >> 1, c = t & 1;
        float ww = 0.f;
        for (int kk = 0; kk < 8; kk++) ww += sq[hh * 16 + c * 8 + kk];
        g_W2[l * 16 + t] = ww;
    }
}

// ------------------------- M_h[d][e] = sum_c Wq[d,c] Wk[e,c] / 8 (exact fp32, NT) -------------------------
#define FMA16(av, bv, acc)                                                         \
    acc[0][0]+=av.x*bv.x; acc[0][1]+=av.x*bv.y; acc[0][2]+=av.x*bv.z; acc[0][3]+=av.x*bv.w; \
    acc[1][0]+=av.y*bv.x; acc[1][1]+=av.y*bv.y; acc[1][2]+=av.y*bv.z; acc[1][3]+=av.y*bv.w; \
    acc[2][0]+=av.z*bv.x; acc[2][1]+=av.z*bv.y; acc[2][2]+=av.z*bv.z; acc[2][3]+=av.z*bv.w; \
    acc[3][0]+=av.w*bv.x; acc[3][1]+=av.w*bv.y; acc[3][2]+=av.w*bv.z; acc[3][3]+=av.w*bv.w;

__global__ void __launch_bounds__(256) mh_k(const float* __restrict__ wq,
                                            const float* __restrict__ wk) {
    __shared__ float Aq[64 * 68];   // [d][c]
    __shared__ float Bk[64 * 68];   // [e][c]
    int bx = blockIdx.x;            // l*8 + h
    int l = bx >> 3, h = bx & 7;
    int tid = threadIdx.x;
#pragma unroll
    for (int it = 0; it < 4; it++) {
        int idx = tid + it * 256;
        int d = idx >> 4, c4 = (idx & 15) * 4;
        *(float4*)&Aq[d * 68 + c4] = *(const float4*)&wq[((size_t)(l * 64 + d)) * 512 + h * 64 + c4];
        *(float4*)&Bk[d * 68 + c4] = *(const float4*)&wk[((size_t)(l * 64 + d)) * 512 + h * 64 + c4];
    }
    __syncthreads();
    int tm = tid >> 4, tn = tid & 15;
    float acc[4][4] = {};
#pragma unroll 4
    for (int c = 0; c < 64; c++) {   // contract over head columns c (NT)
        float4 av = make_float4(Aq[(tm * 4 + 0) * 68 + c], Aq[(tm * 4 + 1) * 68 + c],
                                Aq[(tm * 4 + 2) * 68 + c], Aq[(tm * 4 + 3) * 68 + c]);
        float4 bv = make_float4(Bk[(tn * 4 + 0) * 68 + c], Bk[(tn * 4 + 1) * 68 + c],
                                Bk[(tn * 4 + 2) * 68 + c], Bk[(tn * 4 + 3) * 68 + c]);
        FMA16(av, bv, acc)
    }
#pragma unroll
    for (int ii = 0; ii < 4; ii++)
#pragma unroll
        for (int jj = 0; jj < 4; jj++)
            g_M[(size_t)bx * 4096 + (tm * 4 + ii) * 64 + tn * 4 + jj] = 0.125f * acc[ii][jj];
}

// ------------------------- G_h[d][e] = sum_c Wv[d, h*64+c] * Ow[h*64+c, e] (exact, NN) -------------------------
__global__ void __launch_bounds__(256) gw_k(const float* __restrict__ wv,
                                            const float* __restrict__ ow) {
    __shared__ float Av[64 * 68];   // [d][c]
    __shared__ float Bo[64 * 68];   // [c][e]
    int bx = blockIdx.x;            // l*8 + h
    int l = bx >> 3, h = bx & 7;
    int tid = threadIdx.x;
#pragma unroll
    for (int it = 0; it < 4; it++) {
        int idx = tid + it * 256;
        int r = idx >> 4, c4 = (idx & 15) * 4;
        *(float4*)&Av[r * 68 + c4] = *(const float4*)&wv[((size_t)(l * 64 + r)) * 512 + h * 64 + c4];
        *(float4*)&Bo[r * 68 + c4] = *(const float4*)&ow[((size_t)(l * 512 + h * 64 + r)) * 64 + c4];
    }
    __syncthreads();
    int tm = tid >> 4, tn = tid & 15;
    float acc[4][4] = {};
#pragma unroll 4
    for (int c = 0; c < 64; c++) {
        float4 av = make_float4(Av[(tm * 4 + 0) * 68 + c], Av[(tm * 4 + 1) * 68 + c],
                                Av[(tm * 4 + 2) * 68 + c], Av[(tm * 4 + 3) * 68 + c]);
        float4 bv = *(const float4*)&Bo[c * 68 + tn * 4];
        FMA16(av, bv, acc)
    }
#pragma unroll
    for (int ii = 0; ii < 4; ii++)
#pragma unroll
        for (int jj = 0; jj < 4; jj++)
            g_G[(size_t)bx * 4096 + (tm * 4 + ii) * 64 + tn * 4 + jj] = acc[ii][jj];
}

// ------------------------- shared LN helper (64-wide rows staged in smem) -------------------------
__device__ __forceinline__ void ln64_smem(float* Xs, float (*redA)[4],
                                          const float* g, const float* b,
                                          float* dst, int row0, int tid) {
    int tr = tid >> 2, tp = tid & 3;
    float s = 0.f;
    for (int c = tp * 16; c < tp * 16 + 16; c++) s += Xs[tr * 68 + c];
    redA[tr][tp] = s;
    __syncthreads();
    float mu = (redA[tr][0] + redA[tr][1] + redA[tr][2] + redA[tr][3]) * (1.0f / 64.0f);
    __syncthreads();
    float vs = 0.f;
    for (int c = tp * 16; c < tp * 16 + 16; c++) {
        float d = Xs[tr * 68 + c] - mu;
        vs += d * d;
    }
    redA[tr][tp] = vs;
    __syncthreads();
    float var = (redA[tr][0] + redA[tr][1] + redA[tr][2] + redA[tr][3]) * (1.0f / 64.0f);
    float rs = rsqrtf(var + 1e-5f);
    for (int c = tp * 16; c < tp * 16 + 16; c++)
        dst[(size_t)(row0 + tr) * 64 + c] = (Xs[tr * 68 + c] - mu) * rs * g[c] + b[c];
}

// ------------------------- fused feat encoder + LN1(layer0) (exact FFMA) -------------------------
__global__ void __launch_bounds__(256) ffe_k(
    const float* __restrict__ x,
    const float* __restrict__ W1, const float* __restrict__ b1,
    const float* __restrict__ W2, const float* __restrict__ b2,
    const float* __restrict__ lng, const float* __restrict__ lnb)
{
    __shared__ float Xs16[64 * 17];
    __shared__ float W1s[16 * 68];
    __shared__ float Ts[64 * 68];
    __shared__ float W2s[64 * 68];
    __shared__ float redA[64][4];
    int tid = threadIdx.x;
    int row0 = blockIdx.x * 64;
    {
        int r = tid >> 2, c4 = (tid & 3) * 4;
        float4 xv = *(const float4*)&x[(size_t)(row0 + r) * 16 + c4];
        Xs16[r * 17 + c4 + 0] = xv.x; Xs16[r * 17 + c4 + 1] = xv.y;
        Xs16[r * 17 + c4 + 2] = xv.z; Xs16[r * 17 + c4 + 3] = xv.w;
    }
    if (tid < 16 * 16) {
        int r = tid >> 4, c4 = (tid & 15) * 4;
        *(float4*)&W1s[r * 68 + c4] = *(const float4*)&W1[(size_t)r * 64 + c4];
    }
#pragma unroll
    for (int it = 0; it < 4; it++) {
        int idx = tid + it * 256;
        int r = idx >> 4, c4 = (idx & 15) * 4;
        *(float4*)&W2s[r * 68 + c4] = *(const float4*)&W2[(size_t)r * 64 + c4];
    }
    __syncthreads();
    int tm = tid >> 4, tn = tid & 15;
    float acc[4][4] = {};
#pragma unroll
    for (int kk = 0; kk < 16; kk++) {
        float4 av = make_float4(Xs16[(tm * 4 + 0) * 17 + kk], Xs16[(tm * 4 + 1) * 17 + kk],
                                Xs16[(tm * 4 + 2) * 17 + kk], Xs16[(tm * 4 + 3) * 17 + kk]);
        float4 bv = *(const float4*)&W1s[kk * 68 + tn * 4];
        FMA16(av, bv, acc)
    }
#pragma unroll
    for (int ii = 0; ii < 4; ii++)
#pragma unroll
        for (int jj = 0; jj < 4; jj++)
            Ts[(tm * 4 + ii) * 68 + tn * 4 + jj] = fmaxf(acc[ii][jj] + b1[tn * 4 + jj], 0.f);
    __syncthreads();
    float acc2[4][4] = {};
#pragma unroll 8
    for (int kk = 0; kk < 64; kk++) {
        float4 av = make_float4(Ts[(tm * 4 + 0) * 68 + kk], Ts[(tm * 4 + 1) * 68 + kk],
                                Ts[(tm * 4 + 2) * 68 + kk], Ts[(tm * 4 + 3) * 68 + kk]);
        float4 bv = *(const float4*)&W2s[kk * 68 + tn * 4];
        FMA16(av, bv, acc2)
    }
    __syncthreads();
#pragma unroll
    for (int ii = 0; ii < 4; ii++) {
        int r = row0 + tm * 4 + ii;
#pragma unroll
        for (int jj = 0; jj < 4; jj++) {
            int c = tn * 4 + jj;
            float vv = acc2[ii][jj] + b2[c];
            g_h[(size_t)r * 64 + c] = vv;
            g_hist[(size_t)r * 320 + c] = vv;
            W2s[(tm * 4 + ii) * 68 + c] = vv;   // stage for LN
        }
    }
    __syncthreads();
    ln64_smem(W2s, redA, lng, lnb, (float*)g_xn, row0, tid);
}

// ------------------------- T = Xn @ M_h  (all nodes, per head) -------------------------
__global__ void __launch_bounds__(256) tq_k(const float* __restrict__ Mbase) {
    __shared__ unsigned As[64 * 68];
    __shared__ unsigned Bs[64 * 68];
    int tid = threadIdx.x;
    int row0 = blockIdx.x * 64, h = blockIdx.y;
    const float* Mg = Mbase + (size_t)h * 4096;
#pragma unroll
    for (int it = 0; it < 4; it++) {
        int idx = tid + it * 256;
        int r = idx >> 4, c4 = (idx & 15) * 4;
        float4 av = *(const float4*)&g_xn[(size_t)(row0 + r) * 64 + c4];
        As[r * 68 + c4 + 0] = f2tf(av.x); As[r * 68 + c4 + 1] = f2tf(av.y);
        As[r * 68 + c4 + 2] = f2tf(av.z); As[r * 68 + c4 + 3] = f2tf(av.w);
        float4 bv = *(const float4*)&Mg[r * 64 + c4];
        Bs[r * 68 + c4 + 0] = f2tf(bv.x); Bs[r * 68 + c4 + 1] = f2tf(bv.y);
        Bs[r * 68 + c4 + 2] = f2tf(bv.z); Bs[r * 68 + c4 + 3] = f2tf(bv.w);
    }
    __syncthreads();
    int wid = tid >> 5, lane = tid & 31;
    int g = lane >> 2, t = lane & 3;
    int r0 = (wid & 3) * 16, c0 = (wid >> 2) * 32;
    float acc[4][4] = {};
#pragma unroll
    for (int ks = 0; ks < 8; ks++) {
        int k0 = ks * 8;
        unsigned a0 = As[(r0 + g) * 68 + k0 + t];
        unsigned a1 = As[(r0 + g + 8) * 68 + k0 + t];
        unsigned a2 = As[(r0 + g) * 68 + k0 + t + 4];
        unsigned a3 = As[(r0 + g + 8) * 68 + k0 + t + 4];
#pragma unroll
        for (int nt = 0; nt < 4; nt++) {
            int n = c0 + nt * 8 + g;
            unsigned b0 = Bs[(k0 + t) * 68 + n];
            unsigned b1 = Bs[(k0 + t + 4) * 68 + n];
            mma_tf32(acc[nt], a0, a1, a2, a3, b0, b1);
        }
    }
#pragma unroll
    for (int nt = 0; nt < 4; nt++)
#pragma unroll
        for (int cr = 0; cr < 4; cr++) {
            int r = row0 + r0 + g + (cr >> 1) * 8;
            int c = c0 + nt * 8 + 2 * t + (cr & 1);
            g_T[(size_t)r * 512 + h * 64 + c] = acc[nt][cr];
        }
}

// ------------------------- attention: gather X,T; S=T X^T; softmax; R=P X -------------------------
__global__ void __launch_bounds__(256) attn_k(
    const float* __restrict__ coords, const float* __restrict__ W2row)
{
    extern __shared__ unsigned sh[];
    unsigned* Xs = sh;                 // X tf32 [64][68]
    unsigned* Ts = sh + 64 * 68;       // T tf32 [64][68]
    unsigned* Ss = sh + 2 * 64 * 68;   // S float / P tf32 [j][i]
    __shared__ int   nd[64];
    __shared__ float cx[64], cy[64], redm[4][64], reds[4][64];

    int tid = threadIdx.x;
    int blk = blockIdx.x, h = blockIdx.y, nh = blockIdx.z;
    int row = nh * 8 + h;
    const int* ord = g_order + row * NNODE + blk * 64;
    if (tid < 64) {
        int nn = ord[tid];
        nd[tid] = nn;
        cx[tid] = coords[nn * 3 + 0];
        cy[tid] = coords[nn * 3 + 1];
    }
    __syncthreads();

    for (int idx = tid; idx < 4096; idx += 256) {
        int i = idx >> 6, d = idx & 63;
        Xs[i * 68 + d] = f2tf(g_xn[(size_t)nd[i] * 64 + d]);
        Ts[i * 68 + d] = f2tf(g_T[(size_t)nd[i] * 512 + h * 64 + d]);
    }
    __syncthreads();

    int wid = tid >> 5, lane = tid & 31;
    int g = lane >> 2, t = lane & 3;
    int r0 = (wid & 3) * 16, c0 = (wid >> 2) * 32;

    // S = T @ X^T (+ RPE), write transposed into Ss
    float W0 = W2row[h * 2 + 0], W1 = W2row[h * 2 + 1];
    {
        float acc[4][4] = {};
#pragma unroll
        for (int ks = 0; ks < 8; ks++) {
            int k0 = ks * 8;
            unsigned a0 = Ts[(r0 + g) * 68 + k0 + t];
            unsigned a1 = Ts[(r0 + g + 8) * 68 + k0 + t];
            unsigned a2 = Ts[(r0 + g) * 68 + k0 + t + 4];
            unsigned a3 = Ts[(r0 + g + 8) * 68 + k0 + t + 4];
#pragma unroll
            for (int nt = 0; nt < 4; nt++) {
                int j = c0 + nt * 8 + g;
                unsigned b0 = Xs[j * 68 + k0 + t];
                unsigned b1 = Xs[j * 68 + k0 + t + 4];
                mma_tf32(acc[nt], a0, a1, a2, a3, b0, b1);
            }
        }
        float* Sf = (float*)Ss;
#pragma unroll
        for (int nt = 0; nt < 4; nt++) {
            int j0 = c0 + nt * 8 + 2 * t;
#pragma unroll
            for (int cr = 0; cr < 4; cr++) {
                int i = r0 + g + (cr >> 1) * 8;
                int j = j0 + (cr & 1);
                float dx = cx[i] - cx[j], dy = cy[i] - cy[j];
                Sf[j * 68 + i] = acc[nt][cr] - W0 * dx * dx - W1 * dy * dy;
            }
        }
    }
    __syncthreads();

    // softmax over j per query i (layout [j][i])
    float* Sf = (float*)Ss;
    int ci = tid & 63, seg = tid >> 6;
    float ml = -3.0e38f;
#pragma unroll
    for (int jj = 0; jj < 16; jj++) ml = fmaxf(ml, Sf[(seg * 16 + jj) * 68 + ci]);
    redm[seg][ci] = ml;
    __syncthreads();
    float mm = fmaxf(fmaxf(redm[0][ci], redm[1][ci]), fmaxf(redm[2][ci], redm[3][ci]));
    float ev[16];
    float sl = 0.f;
#pragma unroll
    for (int jj = 0; jj < 16; jj++) {
        float e = __expf(Sf[(seg * 16 + jj) * 68 + ci] - mm);
        ev[jj] = e;
        sl += e;
    }
    reds[seg][ci] = sl;
    __syncthreads();
    float ssum = reds[0][ci] + reds[1][ci] + reds[2][ci] + reds[3][ci];
    float inv = 1.0f / ssum;
    if (seg == 0) g_lser[row * NNODE + nd[ci]] = mm + __logf(ssum);
    unsigned* Ps = Ss;
#pragma unroll
    for (int jj = 0; jj < 16; jj++)
        Ps[(seg * 16 + jj) * 68 + ci] = f2tf(ev[jj] * inv);
    __syncthreads();

    // R = P @ X  (P stored transposed [j][i]); store straight to gmem
    float racc[4][4] = {};
#pragma unroll
    for (int ks = 0; ks < 8; ks++) {
        int k0 = ks * 8;
        unsigned a0 = Ps[(k0 + t) * 68 + r0 + g];
        unsigned a1 = Ps[(k0 + t) * 68 + r0 + g + 8];
        unsigned a2 = Ps[(k0 + t + 4) * 68 + r0 + g];
        unsigned a3 = Ps[(k0 + t + 4) * 68 + r0 + g + 8];
#pragma unroll
        for (int nt = 0; nt < 4; nt++) {
            int n = c0 + nt * 8 + g;
            unsigned b0 = Xs[(k0 + t) * 68 + n];
            unsigned b1 = Xs[(k0 + t + 4) * 68 + n];
            mma_tf32(racc[nt], a0, a1, a2, a3, b0, b1);
        }
    }
#pragma unroll
    for (int nt = 0; nt < 4; nt++) {
        int d0 = c0 + nt * 8 + 2 * t;
        int iA = r0 + g, iB = r0 + g + 8;
        *(float2*)&g_outr[((size_t)row * NNODE + nd[iA]) * 64 + d0] =
            make_float2(racc[nt][0], racc[nt][1]);
        *(float2*)&g_outr[((size_t)row * NNODE + nd[iB]) * 64 + d0] =
            make_float2(racc[nt][2], racc[nt][3]);
    }
}

// ------------------------- out-projection via G with fused lse-combine -------------------------
__global__ void __launch_bounds__(256) outproj_k(
    const float* __restrict__ gG, const float* __restrict__ ob, float* __restrict__ hbuf)
{
    __shared__ unsigned As[64 * 68];
    __shared__ unsigned Bs[64 * 68];
    __shared__ float w0s[64], w1s[64];
    int tid = threadIdx.x;
    int row0 = blockIdx.x * 64;
    int wid = tid >> 5, lane = tid & 31;
    int g = lane >> 2, t = lane & 3;
    int r0 = (wid & 3) * 16, c0 = (wid >> 2) * 32;
    float acc[4][4] = {};
    for (int h = 0; h < 8; h++) {
        __syncthreads();
        if (tid < 64) {
            int node = row0 + tid;
            float l0 = g_lser[h * NNODE + node];
            float l1 = g_lser[(8 + h) * NNODE + node];
            float m = fmaxf(l0, l1);
            float e0 = __expf(l0 - m), e1 = __expf(l1 - m);
            float inv = 1.0f / (e0 + e1);
            w0s[tid] = e0 * inv;
            w1s[tid] = e1 * inv;
        }
        __syncthreads();
#pragma unroll
        for (int it = 0; it < 4; it++) {
            int idx = tid + it * 256;
            int r = idx >> 4, c4 = (idx & 15) * 4;
            int node = row0 + r;
            float4 o0 = *(const float4*)&g_outr[((size_t)h * NNODE + node) * 64 + c4];
            float4 o1 = *(const float4*)&g_outr[((size_t)(8 + h) * NNODE + node) * 64 + c4];
            float w0 = w0s[r], w1 = w1s[r];
            As[r * 68 + c4 + 0] = f2tf(w0 * o0.x + w1 * o1.x);
            As[r * 68 + c4 + 1] = f2tf(w0 * o0.y + w1 * o1.y);
            As[r * 68 + c4 + 2] = f2tf(w0 * o0.z + w1 * o1.z);
            As[r * 68 + c4 + 3] = f2tf(w0 * o0.w + w1 * o1.w);
            float4 bv = *(const float4*)&gG[(size_t)h * 4096 + r * 64 + c4];
            Bs[r * 68 + c4 + 0] = f2tf(bv.x); Bs[r * 68 + c4 + 1] = f2tf(bv.y);
            Bs[r * 68 + c4 + 2] = f2tf(bv.z); Bs[r * 68 + c4 + 3] = f2tf(bv.w);
        }
        __syncthreads();
#pragma unroll
        for (int ks = 0; ks < 8; ks++) {
            int k0 = ks * 8;
            unsigned a0 = As[(r0 + g) * 68 + k0 + t];
            unsigned a1 = As[(r0 + g + 8) * 68 + k0 + t];
            unsigned a2 = As[(r0 + g) * 68 + k0 + t + 4];
            unsigned a3 = As[(r0 + g + 8) * 68 + k0 + t + 4];
#pragma unroll
            for (int nt = 0; nt < 4; nt++) {
                int n = c0 + nt * 8 + g;
                unsigned b0 = Bs[(k0 + t) * 68 + n];
                unsigned b1 = Bs[(k0 + t + 4) * 68 + n];
                mma_tf32(acc[nt], a0, a1, a2, a3, b0, b1);
            }
        }
    }
#pragma unroll
    for (int nt = 0; nt < 4; nt++) {
#pragma unroll
        for (int cr = 0; cr < 4; cr++) {
            int r = row0 + r0 + g + (cr >> 1) * 8;
            int ccol = c0 + nt * 8 + 2 * t + (cr & 1);
            float vv = acc[nt][cr] + ob[ccol] + hbuf[(size_t)r * 64 + ccol];
            hbuf[(size_t)r * 64 + ccol] = vv;
        }
    }
}

// ------------------------- fused LN2 + FFN + residual + hist + LN1(next) -------------------------
__global__ void __launch_bounds__(256) ffn_k(
    float* __restrict__ hbuf, const float* __restrict__ g, const float* __restrict__ b,
    const float* __restrict__ W1, const float* __restrict__ b1,
    const float* __restrict__ W2, const float* __restrict__ b2,
    float* __restrict__ hist,
    const float* __restrict__ lnn_g, const float* __restrict__ lnn_b)
{
    __shared__ float Xs[64 * 68];
    __shared__ float Ws[64 * 68];
    __shared__ float redA[64][4];
    int tid = threadIdx.x;
    int row0 = blockIdx.x * 64;
#pragma unroll
    for (int it = 0; it < 4; it++) {
        int idx = tid + it * 256;
        int r = idx >> 4, c4 = (idx & 15) * 4;
        *(float4*)&Xs[r * 68 + c4] = *(const float4*)&hbuf[(size_t)(row0 + r) * 64 + c4];
        *(float4*)&Ws[r * 68 + c4] = *(const float4*)&W1[(size_t)r * 64 + c4];
    }
    __syncthreads();
    int tr = tid >> 2, tp = tid & 3;
    float s = 0.f;
    for (int c = tp * 16; c < tp * 16 + 16; c++) s += Xs[tr * 68 + c];
    redA[tr][tp] = s;
    __syncthreads();
    float mu = (redA[tr][0] + redA[tr][1] + redA[tr][2] + redA[tr][3]) * (1.0f / 64.0f);
    __syncthreads();
    float vs = 0.f;
    for (int c = tp * 16; c < tp * 16 + 16; c++) {
        float d = Xs[tr * 68 + c] - mu;
        vs += d * d;
    }
    redA[tr][tp] = vs;
    __syncthreads();
    float var = (redA[tr][0] + redA[tr][1] + redA[tr][2] + redA[tr][3]) * (1.0f / 64.0f);
    float rs = rsqrtf(var + 1e-5f);
    for (int c = tp * 16; c < tp * 16 + 16; c++)
        Xs[tr * 68 + c] = (Xs[tr * 68 + c] - mu) * rs * g[c] + b[c];
    __syncthreads();
    int tm = tid >> 4, tn = tid & 15;
    float acc[4][4] = {};
#pragma unroll 8
    for (int kk = 0; kk < 64; kk++) {
        float4 bv = *(const float4*)&Ws[kk * 68 + tn * 4];
        float4 av = make_float4(Xs[(tm * 4 + 0) * 68 + kk], Xs[(tm * 4 + 1) * 68 + kk],
                                Xs[(tm * 4 + 2) * 68 + kk], Xs[(tm * 4 + 3) * 68 + kk]);
        FMA16(av, bv, acc)
    }
    __syncthreads();
#pragma unroll
    for (int ii = 0; ii < 4; ii++)
#pragma unroll
        for (int jj = 0; jj < 4; jj++)
            Xs[(tm * 4 + ii) * 68 + tn * 4 + jj] = fmaxf(acc[ii][jj] + b1[tn * 4 + jj], 0.f);
#pragma unroll
    for (int it = 0; it < 4; it++) {
        int idx = tid + it * 256;
        int r = idx >> 4, c4 = (idx & 15) * 4;
        *(float4*)&Ws[r * 68 + c4] = *(const float4*)&W2[(size_t)r * 64 + c4];
    }
    __syncthreads();
    float acc2[4][4] = {};
#pragma unroll 8
    for (int kk = 0; kk < 64; kk++) {
        float4 bv = *(const float4*)&Ws[kk * 68 + tn * 4];
        float4 av = make_float4(Xs[(tm * 4 + 0) * 68 + kk], Xs[(tm * 4 + 1) * 68 + kk],
                                Xs[(tm * 4 + 2) * 68 + kk], Xs[(tm * 4 + 3) * 68 + kk]);
        FMA16(av, bv, acc2)
    }
    __syncthreads();
#pragma unroll
    for (int ii = 0; ii < 4; ii++) {
        int r = row0 + tm * 4 + ii;
#pragma unroll
        for (int jj = 0; jj < 4; jj++) {
            int c = tn * 4 + jj;
            float vv = acc2[ii][jj] + b2[c] + hbuf[(size_t)r * 64 + c];
            hbuf[(size_t)r * 64 + c] = vv;
            hist[(size_t)r * 320 + c] = vv;
            Ws[(tm * 4 + ii) * 68 + c] = vv;   // stage for next-layer LN
        }
    }
    if (lnn_g) {
        __syncthreads();
        ln64_smem(Ws, redA, lnn_g, lnn_b, (float*)g_xn, row0, tid);
    }
}

// ------------------------- scalar FFMA SGEMM (head) -------------------------
__global__ void __launch_bounds__(256) gemm_k(
    const float* __restrict__ A, const float* __restrict__ B, float* __restrict__ C,
    const float* __restrict__ bias, const float* __restrict__ resid,
    int M, int N, int K, int act)
{
    __shared__ float As[16][68];
    __shared__ float Bs[16][68];
    int tid = threadIdx.x;
    int row0 = blockIdx.x * 64, col0 = blockIdx.y * 64;
    int tm = tid >> 4, tn = tid & 15;
    int arow = tid >> 2, ac = tid & 3;
    int bk = tid >> 4, bn = tid & 15;
    float acc[4][4] = {};
    for (int k0 = 0; k0 < K; k0 += 16) {
        float4 a = *(const float4*)&A[(size_t)(row0 + arow) * K + k0 + ac * 4];
        As[ac * 4 + 0][arow] = a.x; As[ac * 4 + 1][arow] = a.y;
        As[ac * 4 + 2][arow] = a.z; As[ac * 4 + 3][arow] = a.w;
        int bcol = col0 + bn * 4;
        float4 bv = make_float4(0.f, 0.f, 0.f, 0.f);
        if (bcol < N) bv = *(const float4*)&B[(size_t)(k0 + bk) * N + bcol];
        *(float4*)&Bs[bk][bn * 4] = bv;
        __syncthreads();
#pragma unroll
        for (int kk = 0; kk < 16; kk++) {
            float4 av = *(const float4*)&As[kk][tm * 4];
            float4 bw = *(const float4*)&Bs[kk][tn * 4];
            FMA16(av, bw, acc)
        }
        __syncthreads();
    }
#pragma unroll
    for (int ii = 0; ii < 4; ii++) {
        int r = row0 + tm * 4 + ii;
#pragma unroll
        for (int jj = 0; jj < 4; jj++) {
            int ccol = col0 + tn * 4 + jj;
            if (ccol < N) {
                float vv = acc[ii][jj];
                if (bias) vv += bias[ccol];
                if (act == 1) vv = fmaxf(vv, 0.f);
                else if (act == 2) vv = tanhf(vv);
                if (resid) vv += resid[(size_t)r * N + ccol];
                C[(size_t)r * N + ccol] = vv;
            }
        }
    }
}

// ------------------------- LayerNorm 256 + tanh, warp per row -------------------------
__global__ void ln256w_k(const float* __restrict__ in, float* __restrict__ out,
                         const float* __restrict__ g, const float* __restrict__ b) {
    int w = threadIdx.x >> 5, lane = threadIdx.x & 31;
    int row = blockIdx.x * 8 + w;
    const float* xr = in + (size_t)row * 256;
    float x[8];
    float s = 0.f;
#pragma unroll
    for (int m = 0; m < 8; m++) { x[m] = xr[lane + 32 * m]; s += x[m]; }
    for (int o = 16; o; o >>= 1) s += __shfl_xor_sync(0xffffffffu, s, o);
    float mu = s * (1.0f / 256.0f);
    float vs = 0.f;
#pragma unroll
    for (int m = 0; m < 8; m++) { float d = x[m] - mu; vs += d * d; }
    for (int o = 16; o; o >>= 1) vs += __shfl_xor_sync(0xffffffffu, vs, o);
    float rs = rsqrtf(vs * (1.0f / 256.0f) + 1e-5f);
#pragma unroll
    for (int m = 0; m < 8; m++) {
        int c = lane + 32 * m;
        out[(size_t)row * 256 + c] = tanhf((x[m] - mu) * rs * g[c] + b[c]);
    }
}

// ------------------------- reductions + final projection -------------------------
__global__ void red1_k(const float* __restrict__ t) {
    __shared__ float sm[256];
    int blk = blockIdx.x, tid = threadIdx.x;
    int col = tid & 31, r0 = tid >> 5;
    float s = 0.f;
    for (int r = r0; r < 128; r += 8) s += t[(size_t)(blk * 128 + r) * 32 + col];
    sm[tid] = s;
    __syncthreads();
    for (int s2 = 4; s2; s2 >>= 1) {
        if (r0 < s2) sm[tid] += sm[tid + s2 * 32];
        __syncthreads();
    }
    if (r0 == 0) g_part[blk * 32 + col] = sm[col];
}

__global__ void red2_k(const float* __restrict__ pw, const float* __restrict__ pb,
                       float* __restrict__ out) {
    __shared__ float mean[32];
    int t = threadIdx.x;
    if (t < 32) {
        float s = 0.f;
        for (int b = 0; b < 128; b++) s += g_part[b * 32 + t];
        mean[t] = s * (1.0f / 16384.0f);
    }
    __syncthreads();
    if (t < 32) {
        float s = pb[t];
        for (int c = 0; c < 32; c++) s += mean[c] * pw[c * 32 + t];
        out[t] = s;
    }
}

// ------------------------- host orchestration -------------------------
extern "C" void kernel_launch(void* const* d_in, const int* in_sizes, int n_in,
                              void* d_out, int out_size)
{
    const float* x      = (const float*)d_in[0];
    const float* coords = (const float*)d_in[1];
    const float* regions= (const float*)d_in[3];
    const float* fe_w1  = (const float*)d_in[4];
    const float* fe_b1  = (const float*)d_in[5];
    const float* fe_w2  = (const float*)d_in[6];
    const float* fe_b2  = (const float*)d_in[7];
    const float* ln1_g  = (const float*)d_in[8];
    const float* ln1_b  = (const float*)d_in[9];
    const float* wq     = (const float*)d_in[10];
    const float* wk     = (const float*)d_in[11];
    const float* wv     = (const float*)d_in[12];
    const float* wrpe   = (const float*)d_in[13];
    const float* ow     = (const float*)d_in[14];
    const float* ob     = (const float*)d_in[15];
    const float* ln2_g  = (const float*)d_in[16];
    const float* ln2_b  = (const float*)d_in[17];
    const float* f1w    = (const float*)d_in[18];
    const float* f1b    = (const float*)d_in[19];
    const float* f2w    = (const float*)d_in[20];
    const float* f2b    = (const float*)d_in[21];
    const float* Wcat   = (const float*)d_in[22];
    const float* m1w    = (const float*)d_in[23];
    const float* m1b    = (const float*)d_in[24];
    const float* mlng   = (const float*)d_in[25];
    const float* mlnb   = (const float*)d_in[26];
    const float* m2w    = (const float*)d_in[27];
    const float* m2b    = (const float*)d_in[28];
    const float* pw     = (const float*)d_in[29];
    const float* pb     = (const float*)d_in[30];
    float* out = (float*)d_out;

    cudaFuncSetAttribute(attn_k, cudaFuncAttributeMaxDynamicSharedMemorySize, 52224);

    float *p_h, *p_hist, *p_t0, *p_u, *p_u2, *p_t, *p_w2, *p_M, *p_G;
    int *p_rhist, *p_rbase, *p_bhist, *p_bbase;
    cudaGetSymbolAddress((void**)&p_h,    g_h);
    cudaGetSymbolAddress((void**)&p_hist, g_hist);
    cudaGetSymbolAddress((void**)&p_t0,   g_t0);
    cudaGetSymbolAddress((void**)&p_u,    g_u);
    cudaGetSymbolAddress((void**)&p_u2,   g_u2);
    cudaGetSymbolAddress((void**)&p_t,    g_t);
    cudaGetSymbolAddress((void**)&p_w2,   g_W2);
    cudaGetSymbolAddress((void**)&p_M,    g_M);
    cudaGetSymbolAddress((void**)&p_G,    g_G);
    cudaGetSymbolAddress((void**)&p_rhist, r_hist);
    cudaGetSymbolAddress((void**)&p_rbase, r_base);
    cudaGetSymbolAddress((void**)&p_bhist, b_hist);
    cudaGetSymbolAddress((void**)&p_bbase, b_base);

    const int M = NNODE;

    // ---- bucket ordering via counting sorts ----
    zero_k<<<512, 256>>>();
    rank_hist_k<<<dim3(64, 2), 256>>>(coords);
    scan_k<<<2, 1024>>>(p_rhist, p_rbase, NNODE, NNODE);
    rank_place_k<<<dim3(64, 2), 256>>>(coords);
    rank_rank_k<<<dim3(64, 2), 256>>>(coords);
    key1_k<<<dim3(64, 16), 256>>>(regions);
    key2_k<<<dim3(64, 16), 256>>>();
    scan_k<<<16, 1024>>>(p_bhist, p_bbase, KBINS, KBINS);
    bucket_place_k<<<dim3(64, 16), 256>>>();
    bucket_pos_k<<<dim3(64, 16), 256>>>();
    w2all_k<<<4, 128>>>(wrpe);
    mh_k<<<32, 256>>>(wq, wk);
    gw_k<<<32, 256>>>(wv, ow);

    // feat encoder + LN1(layer 0)
    ffe_k<<<256, 256>>>(x, fe_w1, fe_b1, fe_w2, fe_b2, ln1_g, ln1_b);

    for (int l = 0; l < 4; l++) {
        tq_k<<<dim3(256, 8), 256>>>(p_M + (size_t)l * 8 * 4096);
        attn_k<<<dim3(256, 8, 2), 256, 52224>>>(coords, p_w2 + l * 16);
        outproj_k<<<256, 256>>>(p_G + (size_t)l * 8 * 4096, ob + l * 64, p_h);
        const float* nlg = (l < 3) ? (ln1_g + (l + 1) * 64) : nullptr;
        const float* nlb = (l < 3) ? (ln1_b + (l + 1) * 64) : nullptr;
        ffn_k<<<256, 256>>>(p_h, ln2_g + l * 64, ln2_b + l * 64,
                            f1w + (size_t)l * 64 * 64, f1b + l * 64,
                            f2w + (size_t)l * 64 * 64, f2b + l * 64,
                            p_hist + (l + 1) * 64, nlg, nlb);
    }

    gemm_k<<<dim3(256, 1), 256>>>(p_hist, Wcat, p_t0, nullptr, nullptr, M, 32, 320, 2);
    gemm_k<<<dim3(256, 4), 256>>>(p_t0, m1w, p_u, m1b, nullptr, M, 256, 32, 0);
    ln256w_k<<<2048, 256>>>(p_u, p_u2, mlng, mlnb);
    gemm_k<<<dim3(256, 1), 256>>>(p_u2, m2w, p_t, m2b, p_t0, M, 32, 256, 0);
    red1_k<<<128, 256>>>(p_t);
    red2_k<<<1, 256>>>(pw, pb, out);
}

// round 10
// speedup vs baseline: 2.5205x; 1.1094x over previous
#include <cuda_runtime.h>
#include <cuda_bf16.h>
#include <math.h>

#define NNODE 16384
#define HEADS 8
#define DIM   64
#define HDIM  512
#define KBINS 40960

// ------------------------- device scratch (no allocs allowed) -------------------------
__device__ int   g_rank[2][NNODE];
__device__ int   g_order[16 * NNODE];
__device__ float g_h[NNODE * DIM];
__device__ float g_xn[NNODE * DIM];          // LN1(h) for the upcoming layer
__device__ float g_T[NNODE * HDIM];          // T = Xn @ M_h  (per layer)
__device__ float g_hist[NNODE * 320];
__device__ float g_outr[16 * NNODE * DIM];   // R = P@X  [nh*8+h][node][d]
__device__ float g_lser[16 * NNODE];
__device__ float g_W2[4 * 16];               // [layer][h][c]
__device__ float g_M[4 * 8 * 64 * 64];       // [layer][head][d][e] = sum_c Wq[d,c]Wk[e,c]/8
__device__ float g_G[4 * 8 * 64 * 64];       // [layer][head][d][e] = Wv_h @ Ow_h (exact)
__device__ float g_t0[NNODE * 32];
__device__ float g_u [NNODE * 256];
__device__ float g_u2[NNODE * 256];
__device__ float g_t [NNODE * 32];
__device__ float g_part[128 * 32];

// sorting scratch
__device__ int r_hist[2][NNODE];
__device__ int r_base[2][NNODE];
__device__ int r_cnt [2][NNODE];
__device__ int r_slot[2][NNODE];
__device__ int b_keys[16][NNODE];
__device__ int b_hist[16][KBINS];
__device__ int b_base[16][KBINS];
__device__ int b_cnt [16][KBINS];
__device__ int b_slot[16][NNODE];
__device__ int g_maxre[16];

// ------------------------- tf32 helpers -------------------------
__device__ __forceinline__ unsigned f2tf(float f) {
    unsigned u;
    asm("cvt.rna.tf32.f32 %0, %1;" : "=r"(u) : "f"(f));
    return u;
}

__device__ __forceinline__ void mma_tf32(float c[4], unsigned a0, unsigned a1,
                                         unsigned a2, unsigned a3,
                                         unsigned b0, unsigned b1) {
    asm volatile(
        "mma.sync.aligned.m16n8k8.row.col.f32.tf32.tf32.f32 "
        "{%0,%1,%2,%3}, {%4,%5,%6,%7}, {%8,%9}, {%0,%1,%2,%3};"
        : "+f"(c[0]), "+f"(c[1]), "+f"(c[2]), "+f"(c[3])
        : "r"(a0), "r"(a1), "r"(a2), "r"(a3), "r"(b0), "r"(b1));
}

// ------------------------- zero all counting scratch -------------------------
__global__ void zero_k() {
    int gid = blockIdx.x * 256 + threadIdx.x;
    int stride = gridDim.x * 256;
    for (int i = gid; i < 2 * NNODE; i += stride) { ((int*)r_hist)[i] = 0; ((int*)r_cnt)[i] = 0; }
    for (int i = gid; i < 16 * KBINS; i += stride) { ((int*)b_hist)[i] = 0; ((int*)b_cnt)[i] = 0; }
    if (gid < 16) g_maxre[gid] = 0;
}

// ------------------------- coordinate ranks via counting -------------------------
__device__ __forceinline__ int coord_bin(float c) {
    int u = (int)(c * 16384.0f);
    return min(16383, max(0, u));
}

__global__ void rank_hist_k(const float* __restrict__ coords) {
    int axis = blockIdx.y;
    int i = blockIdx.x * 256 + threadIdx.x;
    int u = coord_bin(coords[i * 3 + axis]);
    atomicAdd(&r_hist[axis][u], 1);
}

__global__ void __launch_bounds__(1024) scan_k(const int* __restrict__ hist,
                                               int* __restrict__ base,
                                               int nbins, int rowstride) {
    __shared__ int ss[1024];
    int row = blockIdx.x;
    const int* h = hist + (size_t)row * rowstride;
    int* bs = base + (size_t)row * rowstride;
    int t = threadIdx.x;
    int chunk = (nbins + 1023) >> 10;
    int b0 = t * chunk;
    int s = 0;
    for (int m = 0; m < chunk; m++) { int idx = b0 + m; if (idx < nbins) s += h[idx]; }
    ss[t] = s;
    __syncthreads();
    for (int d = 1; d < 1024; d <<= 1) {
        int v = (t >= d) ? ss[t - d] : 0;
        __syncthreads();
        ss[t] += v;
        __syncthreads();
    }
    int run = (t > 0) ? ss[t - 1] : 0;
    for (int m = 0; m < chunk; m++) {
        int idx = b0 + m;
        if (idx < nbins) { bs[idx] = run; run += h[idx]; }
    }
}

__global__ void rank_place_k(const float* __restrict__ coords) {
    int axis = blockIdx.y;
    int i = blockIdx.x * 256 + threadIdx.x;
    int u = coord_bin(coords[i * 3 + axis]);
    int slot = r_base[axis][u] + atomicAdd(&r_cnt[axis][u], 1);
    r_slot[axis][slot] = i;
}

__global__ void rank_rank_k(const float* __restrict__ coords) {
    int axis = blockIdx.y;
    int i = blockIdx.x * 256 + threadIdx.x;
    float ci = coords[i * 3 + axis];
    int u = coord_bin(ci);
    int b = r_base[axis][u], n = r_hist[axis][u];
    int r = 0;
    for (int m = 0; m < n; m++) {
        int j = r_slot[axis][b + m];
        float cj = coords[j * 3 + axis];
        r += (int)((cj < ci) || (cj == ci && j < i));
    }
    g_rank[axis][i] = b + r;
}

// ------------------------- bucket order via counting sort -------------------------
__global__ void key1_k(const float* __restrict__ regions) {
    __shared__ int smax[256];
    int row = blockIdx.y;
    int nh = row >> 3, h = row & 7;
    float qe = 16384.0f / regions[nh * 16 + h];
    float qp = 16384.0f / regions[nh * 16 + 8 + h];
    int i = blockIdx.x * 256 + threadIdx.x;
    int re = (int)floorf((float)g_rank[0][i] / qe) + 1;
    int rp = (int)floorf((float)g_rank[1][i] / qp) + 1;
    b_keys[row][i] = (rp << 16) | re;
    smax[threadIdx.x] = re;
    __syncthreads();
    for (int s = 128; s > 0; s >>= 1) {
        if (threadIdx.x < s) smax[threadIdx.x] = max(smax[threadIdx.x], smax[threadIdx.x + s]);
        __syncthreads();
    }
    if (threadIdx.x == 0) atomicMax(&g_maxre[row], smax[0]);
}

__global__ void key2_k() {
    int row = blockIdx.y;
    int i = blockIdx.x * 256 + threadIdx.x;
    int nb = (int)ceilf(log2f((float)g_maxre[row] + 1.0f));
    int v = b_keys[row][i];
    int key = ((v >> 16) << nb) | (v & 0xffff);
    b_keys[row][i] = key;
    atomicAdd(&b_hist[row][key], 1);
}

__global__ void bucket_place_k() {
    int row = blockIdx.y;
    int i = blockIdx.x * 256 + threadIdx.x;
    int key = b_keys[row][i];
    int slot = b_base[row][key] + atomicAdd(&b_cnt[row][key], 1);
    b_slot[row][slot] = i;
}

__global__ void bucket_pos_k() {
    int row = blockIdx.y;
    int i = blockIdx.x * 256 + threadIdx.x;
    int key = b_keys[row][i];
    int b = b_base[row][key], n = b_hist[row][key];
    int r = 0;
    for (int m = 0; m < n; m++) r += (int)(b_slot[row][b + m] < i);
    g_order[row * NNODE + b + r] = i;
}

// ------------------------- RPE distance weights (all 4 layers) -------------------------
__global__ void w2all_k(const float* __restrict__ wrpe) {   // [4][512][16]
    __shared__ float sq[128];
    int l = blockIdx.x;
    const float* w = wrpe + (size_t)l * 512 * 16;
    int t = threadIdx.x;
    int h = t >> 4, m = t & 15;
    float s = 0.f;
    for (int d = 0; d < 64; d++) s += w[(h * 64 + d) * 16 + m];
    float om = s * (1.0f / 64.0f);
    sq[t] = om * om;
    __syncthreads();
    if (t < 16) {
        int hh = t >> 1, c = t & 1;
        float ww = 0.f;
        for (int kk = 0; kk < 8; kk++) ww += sq[hh * 16 + c * 8 + kk];
        g_W2[l * 16 + t] = ww;
    }
}

// ------------------------- M_h[d][e] = sum_c Wq[d,c] Wk[e,c] / 8 (exact fp32, NT) -------------------------
#define FMA16(av, bv, acc)                                                         \
    acc[0][0]+=av.x*bv.x; acc[0][1]+=av.x*bv.y; acc[0][2]+=av.x*bv.z; acc[0][3]+=av.x*bv.w; \
    acc[1][0]+=av.y*bv.x; acc[1][1]+=av.y*bv.y; acc[1][2]+=av.y*bv.z; acc[1][3]+=av.y*bv.w; \
    acc[2][0]+=av.z*bv.x; acc[2][1]+=av.z*bv.y; acc[2][2]+=av.z*bv.z; acc[2][3]+=av.z*bv.w; \
    acc[3][0]+=av.w*bv.x; acc[3][1]+=av.w*bv.y; acc[3][2]+=av.w*bv.z; acc[3][3]+=av.w*bv.w;

__global__ void __launch_bounds__(256) mh_k(const float* __restrict__ wq,
                                            const float* __restrict__ wk) {
    __shared__ float Aq[64 * 68];   // [d][c]
    __shared__ float Bk[64 * 68];   // [e][c]
    int bx = blockIdx.x;            // l*8 + h
    int l = bx >> 3, h = bx & 7;
    int tid = threadIdx.x;
#pragma unroll
    for (int it = 0; it < 4; it++) {
        int idx = tid + it * 256;
        int d = idx >> 4, c4 = (idx & 15) * 4;
        *(float4*)&Aq[d * 68 + c4] = *(const float4*)&wq[((size_t)(l * 64 + d)) * 512 + h * 64 + c4];
        *(float4*)&Bk[d * 68 + c4] = *(const float4*)&wk[((size_t)(l * 64 + d)) * 512 + h * 64 + c4];
    }
    __syncthreads();
    int tm = tid >> 4, tn = tid & 15;
    float acc[4][4] = {};
#pragma unroll 4
    for (int c = 0; c < 64; c++) {
        float4 av = make_float4(Aq[(tm * 4 + 0) * 68 + c], Aq[(tm * 4 + 1) * 68 + c],
                                Aq[(tm * 4 + 2) * 68 + c], Aq[(tm * 4 + 3) * 68 + c]);
        float4 bv = make_float4(Bk[(tn * 4 + 0) * 68 + c], Bk[(tn * 4 + 1) * 68 + c],
                                Bk[(tn * 4 + 2) * 68 + c], Bk[(tn * 4 + 3) * 68 + c]);
        FMA16(av, bv, acc)
    }
#pragma unroll
    for (int ii = 0; ii < 4; ii++)
#pragma unroll
        for (int jj = 0; jj < 4; jj++)
            g_M[(size_t)bx * 4096 + (tm * 4 + ii) * 64 + tn * 4 + jj] = 0.125f * acc[ii][jj];
}

// ------------------------- G_h = Wv_h @ Ow_h (exact, NN) -------------------------
__global__ void __launch_bounds__(256) gw_k(const float* __restrict__ wv,
                                            const float* __restrict__ ow) {
    __shared__ float Av[64 * 68];   // [d][c]
    __shared__ float Bo[64 * 68];   // [c][e]
    int bx = blockIdx.x;            // l*8 + h
    int l = bx >> 3, h = bx & 7;
    int tid = threadIdx.x;
#pragma unroll
    for (int it = 0; it < 4; it++) {
        int idx = tid + it * 256;
        int r = idx >> 4, c4 = (idx & 15) * 4;
        *(float4*)&Av[r * 68 + c4] = *(const float4*)&wv[((size_t)(l * 64 + r)) * 512 + h * 64 + c4];
        *(float4*)&Bo[r * 68 + c4] = *(const float4*)&ow[((size_t)(l * 512 + h * 64 + r)) * 64 + c4];
    }
    __syncthreads();
    int tm = tid >> 4, tn = tid & 15;
    float acc[4][4] = {};
#pragma unroll 4
    for (int c = 0; c < 64; c++) {
        float4 av = make_float4(Av[(tm * 4 + 0) * 68 + c], Av[(tm * 4 + 1) * 68 + c],
                                Av[(tm * 4 + 2) * 68 + c], Av[(tm * 4 + 3) * 68 + c]);
        float4 bv = *(const float4*)&Bo[c * 68 + tn * 4];
        FMA16(av, bv, acc)
    }
#pragma unroll
    for (int ii = 0; ii < 4; ii++)
#pragma unroll
        for (int jj = 0; jj < 4; jj++)
            g_G[(size_t)bx * 4096 + (tm * 4 + ii) * 64 + tn * 4 + jj] = acc[ii][jj];
}

// ------------------------- shared LN helper (64-wide rows staged in smem) -------------------------
__device__ __forceinline__ void ln64_smem(float* Xs, float (*redA)[4],
                                          const float* g, const float* b,
                                          float* dst, int row0, int tid) {
    int tr = tid >> 2, tp = tid & 3;
    float s = 0.f;
    for (int c = tp * 16; c < tp * 16 + 16; c++) s += Xs[tr * 68 + c];
    redA[tr][tp] = s;
    __syncthreads();
    float mu = (redA[tr][0] + redA[tr][1] + redA[tr][2] + redA[tr][3]) * (1.0f / 64.0f);
    __syncthreads();
    float vs = 0.f;
    for (int c = tp * 16; c < tp * 16 + 16; c++) {
        float d = Xs[tr * 68 + c] - mu;
        vs += d * d;
    }
    redA[tr][tp] = vs;
    __syncthreads();
    float var = (redA[tr][0] + redA[tr][1] + redA[tr][2] + redA[tr][3]) * (1.0f / 64.0f);
    float rs = rsqrtf(var + 1e-5f);
    for (int c = tp * 16; c < tp * 16 + 16; c++)
        dst[(size_t)(row0 + tr) * 64 + c] = (Xs[tr * 68 + c] - mu) * rs * g[c] + b[c];
}

// ------------------------- fused feat encoder + LN1(layer0) (exact FFMA) -------------------------
__global__ void __launch_bounds__(256) ffe_k(
    const float* __restrict__ x,
    const float* __restrict__ W1, const float* __restrict__ b1,
    const float* __restrict__ W2, const float* __restrict__ b2,
    const float* __restrict__ lng, const float* __restrict__ lnb)
{
    __shared__ float Xs16[64 * 17];
    __shared__ float W1s[16 * 68];
    __shared__ float Ts[64 * 68];
    __shared__ float W2s[64 * 68];
    __shared__ float redA[64][4];
    int tid = threadIdx.x;
    int row0 = blockIdx.x * 64;
    {
        int r = tid >> 2, c4 = (tid & 3) * 4;
        float4 xv = *(const float4*)&x[(size_t)(row0 + r) * 16 + c4];
        Xs16[r * 17 + c4 + 0] = xv.x; Xs16[r * 17 + c4 + 1] = xv.y;
        Xs16[r * 17 + c4 + 2] = xv.z; Xs16[r * 17 + c4 + 3] = xv.w;
    }
    if (tid < 16 * 16) {
        int r = tid >> 4, c4 = (tid & 15) * 4;
        *(float4*)&W1s[r * 68 + c4] = *(const float4*)&W1[(size_t)r * 64 + c4];
    }
#pragma unroll
    for (int it = 0; it < 4; it++) {
        int idx = tid + it * 256;
        int r = idx >> 4, c4 = (idx & 15) * 4;
        *(float4*)&W2s[r * 68 + c4] = *(const float4*)&W2[(size_t)r * 64 + c4];
    }
    __syncthreads();
    int tm = tid >> 4, tn = tid & 15;
    float acc[4][4] = {};
#pragma unroll
    for (int kk = 0; kk < 16; kk++) {
        float4 av = make_float4(Xs16[(tm * 4 + 0) * 17 + kk], Xs16[(tm * 4 + 1) * 17 + kk],
                                Xs16[(tm * 4 + 2) * 17 + kk], Xs16[(tm * 4 + 3) * 17 + kk]);
        float4 bv = *(const float4*)&W1s[kk * 68 + tn * 4];
        FMA16(av, bv, acc)
    }
#pragma unroll
    for (int ii = 0; ii < 4; ii++)
#pragma unroll
        for (int jj = 0; jj < 4; jj++)
            Ts[(tm * 4 + ii) * 68 + tn * 4 + jj] = fmaxf(acc[ii][jj] + b1[tn * 4 + jj], 0.f);
    __syncthreads();
    float acc2[4][4] = {};
#pragma unroll 8
    for (int kk = 0; kk < 64; kk++) {
        float4 av = make_float4(Ts[(tm * 4 + 0) * 68 + kk], Ts[(tm * 4 + 1) * 68 + kk],
                                Ts[(tm * 4 + 2) * 68 + kk], Ts[(tm * 4 + 3) * 68 + kk]);
        float4 bv = *(const float4*)&W2s[kk * 68 + tn * 4];
        FMA16(av, bv, acc2)
    }
    __syncthreads();
#pragma unroll
    for (int ii = 0; ii < 4; ii++) {
        int r = row0 + tm * 4 + ii;
#pragma unroll
        for (int jj = 0; jj < 4; jj++) {
            int c = tn * 4 + jj;
            float vv = acc2[ii][jj] + b2[c];
            g_h[(size_t)r * 64 + c] = vv;
            g_hist[(size_t)r * 320 + c] = vv;
            W2s[(tm * 4 + ii) * 68 + c] = vv;   // stage for LN
        }
    }
    __syncthreads();
    ln64_smem(W2s, redA, lng, lnb, (float*)g_xn, row0, tid);
}

// ------------------------- T = Xn @ M_h  (all nodes, per head) -------------------------
__global__ void __launch_bounds__(256) tq_k(const float* __restrict__ Mbase) {
    __shared__ unsigned As[64 * 68];
    __shared__ unsigned Bs[64 * 68];
    int tid = threadIdx.x;
    int row0 = blockIdx.x * 64, h = blockIdx.y;
    const float* Mg = Mbase + (size_t)h * 4096;
#pragma unroll
    for (int it = 0; it < 4; it++) {
        int idx = tid + it * 256;
        int r = idx >> 4, c4 = (idx & 15) * 4;
        float4 av = *(const float4*)&g_xn[(size_t)(row0 + r) * 64 + c4];
        As[r * 68 + c4 + 0] = f2tf(av.x); As[r * 68 + c4 + 1] = f2tf(av.y);
        As[r * 68 + c4 + 2] = f2tf(av.z); As[r * 68 + c4 + 3] = f2tf(av.w);
        float4 bv = *(const float4*)&Mg[r * 64 + c4];
        Bs[r * 68 + c4 + 0] = f2tf(bv.x); Bs[r * 68 + c4 + 1] = f2tf(bv.y);
        Bs[r * 68 + c4 + 2] = f2tf(bv.z); Bs[r * 68 + c4 + 3] = f2tf(bv.w);
    }
    __syncthreads();
    int wid = tid >> 5, lane = tid & 31;
    int g = lane >> 2, t = lane & 3;
    int r0 = (wid & 3) * 16, c0 = (wid >> 2) * 32;
    float acc[4][4] = {};
#pragma unroll
    for (int ks = 0; ks < 8; ks++) {
        int k0 = ks * 8;
        unsigned a0 = As[(r0 + g) * 68 + k0 + t];
        unsigned a1 = As[(r0 + g + 8) * 68 + k0 + t];
        unsigned a2 = As[(r0 + g) * 68 + k0 + t + 4];
        unsigned a3 = As[(r0 + g + 8) * 68 + k0 + t + 4];
#pragma unroll
        for (int nt = 0; nt < 4; nt++) {
            int n = c0 + nt * 8 + g;
            unsigned b0 = Bs[(k0 + t) * 68 + n];
            unsigned b1 = Bs[(k0 + t + 4) * 68 + n];
            mma_tf32(acc[nt], a0, a1, a2, a3, b0, b1);
        }
    }
#pragma unroll
    for (int nt = 0; nt < 4; nt++)
#pragma unroll
        for (int cr = 0; cr < 4; cr++) {
            int r = row0 + r0 + g + (cr >> 1) * 8;
            int c = c0 + nt * 8 + 2 * t + (cr & 1);
            g_T[(size_t)r * 512 + h * 64 + c] = acc[nt][cr];
        }
}

// ------------------------- attention: 2-buffer (X, T->S/P), float4 gathers -------------------------
__global__ void __launch_bounds__(256) attn_k(
    const float* __restrict__ coords, const float* __restrict__ W2row)
{
    __shared__ unsigned Xs[64 * 68];   // X tf32
    __shared__ unsigned Ts[64 * 68];   // T tf32 -> S float / P tf32 [j][i]
    __shared__ int   nd[64];
    __shared__ float cx[64], cy[64], redm[4][64], reds[4][64];

    int tid = threadIdx.x;
    int blk = blockIdx.x, h = blockIdx.y, nh = blockIdx.z;
    int row = nh * 8 + h;
    const int* ord = g_order + row * NNODE + blk * 64;
    if (tid < 64) {
        int nn = ord[tid];
        nd[tid] = nn;
        cx[tid] = coords[nn * 3 + 0];
        cy[tid] = coords[nn * 3 + 1];
    }
    __syncthreads();

    // gather X (LN'd) and T rows via float4
#pragma unroll
    for (int it = 0; it < 4; it++) {
        int idx = tid + it * 256;               // 0..1023
        int i = idx >> 4, q = (idx & 15) * 4;
        size_t nb = (size_t)nd[i];
        float4 xv = *(const float4*)&g_xn[nb * 64 + q];
        Xs[i * 68 + q + 0] = f2tf(xv.x); Xs[i * 68 + q + 1] = f2tf(xv.y);
        Xs[i * 68 + q + 2] = f2tf(xv.z); Xs[i * 68 + q + 3] = f2tf(xv.w);
        float4 tv = *(const float4*)&g_T[nb * 512 + h * 64 + q];
        Ts[i * 68 + q + 0] = f2tf(tv.x); Ts[i * 68 + q + 1] = f2tf(tv.y);
        Ts[i * 68 + q + 2] = f2tf(tv.z); Ts[i * 68 + q + 3] = f2tf(tv.w);
    }
    __syncthreads();

    int wid = tid >> 5, lane = tid & 31;
    int g = lane >> 2, t = lane & 3;
    int r0 = (wid & 3) * 16, c0 = (wid >> 2) * 32;

    // S = T @ X^T (+RPE) in registers
    float acc[4][4] = {};
#pragma unroll
    for (int ks = 0; ks < 8; ks++) {
        int k0 = ks * 8;
        unsigned a0 = Ts[(r0 + g) * 68 + k0 + t];
        unsigned a1 = Ts[(r0 + g + 8) * 68 + k0 + t];
        unsigned a2 = Ts[(r0 + g) * 68 + k0 + t + 4];
        unsigned a3 = Ts[(r0 + g + 8) * 68 + k0 + t + 4];
#pragma unroll
        for (int nt = 0; nt < 4; nt++) {
            int j = c0 + nt * 8 + g;
            unsigned b0 = Xs[j * 68 + k0 + t];
            unsigned b1 = Xs[j * 68 + k0 + t + 4];
            mma_tf32(acc[nt], a0, a1, a2, a3, b0, b1);
        }
    }
    float W0 = W2row[h * 2 + 0], W1 = W2row[h * 2 + 1];
    __syncthreads();   // all reads of Ts done; reuse as S

    float* Sf = (float*)Ts;
#pragma unroll
    for (int nt = 0; nt < 4; nt++) {
        int j0 = c0 + nt * 8 + 2 * t;
#pragma unroll
        for (int cr = 0; cr < 4; cr++) {
            int i = r0 + g + (cr >> 1) * 8;
            int j = j0 + (cr & 1);
            float dx = cx[i] - cx[j], dy = cy[i] - cy[j];
            Sf[j * 68 + i] = acc[nt][cr] - W0 * dx * dx - W1 * dy * dy;
        }
    }
    __syncthreads();

    // softmax over j per query i (layout [j][i])
    int ci = tid & 63, seg = tid >> 6;
    float ml = -3.0e38f;
#pragma unroll
    for (int jj = 0; jj < 16; jj++) ml = fmaxf(ml, Sf[(seg * 16 + jj) * 68 + ci]);
    redm[seg][ci] = ml;
    __syncthreads();
    float mm = fmaxf(fmaxf(redm[0][ci], redm[1][ci]), fmaxf(redm[2][ci], redm[3][ci]));
    float ev[16];
    float sl = 0.f;
#pragma unroll
    for (int jj = 0; jj < 16; jj++) {
        float e = __expf(Sf[(seg * 16 + jj) * 68 + ci] - mm);
        ev[jj] = e;
        sl += e;
    }
    reds[seg][ci] = sl;
    __syncthreads();
    float ssum = reds[0][ci] + reds[1][ci] + reds[2][ci] + reds[3][ci];
    float inv = 1.0f / ssum;
    if (seg == 0) g_lser[row * NNODE + nd[ci]] = mm + __logf(ssum);
    unsigned* Ps = Ts;
#pragma unroll
    for (int jj = 0; jj < 16; jj++)
        Ps[(seg * 16 + jj) * 68 + ci] = f2tf(ev[jj] * inv);
    __syncthreads();

    // R = P @ X  (P stored transposed [j][i]); store straight to gmem
    float racc[4][4] = {};
#pragma unroll
    for (int ks = 0; ks < 8; ks++) {
        int k0 = ks * 8;
        unsigned a0 = Ps[(k0 + t) * 68 + r0 + g];
        unsigned a1 = Ps[(k0 + t) * 68 + r0 + g + 8];
        unsigned a2 = Ps[(k0 + t + 4) * 68 + r0 + g];
        unsigned a3 = Ps[(k0 + t + 4) * 68 + r0 + g + 8];
#pragma unroll
        for (int nt = 0; nt < 4; nt++) {
            int n = c0 + nt * 8 + g;
            unsigned b0 = Xs[(k0 + t) * 68 + n];
            unsigned b1 = Xs[(k0 + t + 4) * 68 + n];
            mma_tf32(racc[nt], a0, a1, a2, a3, b0, b1);
        }
    }
#pragma unroll
    for (int nt = 0; nt < 4; nt++) {
        int d0 = c0 + nt * 8 + 2 * t;
        int iA = r0 + g, iB = r0 + g + 8;
        *(float2*)&g_outr[((size_t)row * NNODE + nd[iA]) * 64 + d0] =
            make_float2(racc[nt][0], racc[nt][1]);
        *(float2*)&g_outr[((size_t)row * NNODE + nd[iB]) * 64 + d0] =
            make_float2(racc[nt][2], racc[nt][3]);
    }
}

// ------------------------- out-projection via G with fused lse-combine -------------------------
__global__ void __launch_bounds__(256) outproj_k(
    const float* __restrict__ gG, const float* __restrict__ ob, float* __restrict__ hbuf)
{
    __shared__ unsigned As[64 * 68];
    __shared__ unsigned Bs[64 * 68];
    __shared__ float w0s[64], w1s[64];
    int tid = threadIdx.x;
    int row0 = blockIdx.x * 64;
    int wid = tid >> 5, lane = tid & 31;
    int g = lane >> 2, t = lane & 3;
    int r0 = (wid & 3) * 16, c0 = (wid >> 2) * 32;
    float acc[4][4] = {};
    for (int h = 0; h < 8; h++) {
        __syncthreads();
        if (tid < 64) {
            int node = row0 + tid;
            float l0 = g_lser[h * NNODE + node];
            float l1 = g_lser[(8 + h) * NNODE + node];
            float m = fmaxf(l0, l1);
            float e0 = __expf(l0 - m), e1 = __expf(l1 - m);
            float inv = 1.0f / (e0 + e1);
            w0s[tid] = e0 * inv;
            w1s[tid] = e1 * inv;
        }
        __syncthreads();
#pragma unroll
        for (int it = 0; it < 4; it++) {
            int idx = tid + it * 256;
            int r = idx >> 4, c4 = (idx & 15) * 4;
            int node = row0 + r;
            float4 o0 = *(const float4*)&g_outr[((size_t)h * NNODE + node) * 64 + c4];
            float4 o1 = *(const float4*)&g_outr[((size_t)(8 + h) * NNODE + node) * 64 + c4];
            float w0 = w0s[r], w1 = w1s[r];
            As[r * 68 + c4 + 0] = f2tf(w0 * o0.x + w1 * o1.x);
            As[r * 68 + c4 + 1] = f2tf(w0 * o0.y + w1 * o1.y);
            As[r * 68 + c4 + 2] = f2tf(w0 * o0.z + w1 * o1.z);
            As[r * 68 + c4 + 3] = f2tf(w0 * o0.w + w1 * o1.w);
            float4 bv = *(const float4*)&gG[(size_t)h * 4096 + r * 64 + c4];
            Bs[r * 68 + c4 + 0] = f2tf(bv.x); Bs[r * 68 + c4 + 1] = f2tf(bv.y);
            Bs[r * 68 + c4 + 2] = f2tf(bv.z); Bs[r * 68 + c4 + 3] = f2tf(bv.w);
        }
        __syncthreads();
#pragma unroll
        for (int ks = 0; ks < 8; ks++) {
            int k0 = ks * 8;
            unsigned a0 = As[(r0 + g) * 68 + k0 + t];
            unsigned a1 = As[(r0 + g + 8) * 68 + k0 + t];
            unsigned a2 = As[(r0 + g) * 68 + k0 + t + 4];
            unsigned a3 = As[(r0 + g + 8) * 68 + k0 + t + 4];
#pragma unroll
            for (int nt = 0; nt < 4; nt++) {
                int n = c0 + nt * 8 + g;
                unsigned b0 = Bs[(k0 + t) * 68 + n];
                unsigned b1 = Bs[(k0 + t + 4) * 68 + n];
                mma_tf32(acc[nt], a0, a1, a2, a3, b0, b1);
            }
        }
    }
#pragma unroll
    for (int nt = 0; nt < 4; nt++) {
#pragma unroll
        for (int cr = 0; cr < 4; cr++) {
            int r = row0 + r0 + g + (cr >> 1) * 8;
            int ccol = c0 + nt * 8 + 2 * t + (cr & 1);
            float vv = acc[nt][cr] + ob[ccol] + hbuf[(size_t)r * 64 + ccol];
            hbuf[(size_t)r * 64 + ccol] = vv;
        }
    }
}

// ------------------------- fused LN2 + FFN + residual + hist + LN1(next) -------------------------
__global__ void __launch_bounds__(256) ffn_k(
    float* __restrict__ hbuf, const float* __restrict__ g, const float* __restrict__ b,
    const float* __restrict__ W1, const float* __restrict__ b1,
    const float* __restrict__ W2, const float* __restrict__ b2,
    float* __restrict__ hist,
    const float* __restrict__ lnn_g, const float* __restrict__ lnn_b)
{
    __shared__ float Xs[64 * 68];
    __shared__ float Ws[64 * 68];
    __shared__ float redA[64][4];
    int tid = threadIdx.x;
    int row0 = blockIdx.x * 64;
#pragma unroll
    for (int it = 0; it < 4; it++) {
        int idx = tid + it * 256;
        int r = idx >> 4, c4 = (idx & 15) * 4;
        *(float4*)&Xs[r * 68 + c4] = *(const float4*)&hbuf[(size_t)(row0 + r) * 64 + c4];
        *(float4*)&Ws[r * 68 + c4] = *(const float4*)&W1[(size_t)r * 64 + c4];
    }
    __syncthreads();
    int tr = tid >> 2, tp = tid & 3;
    float s = 0.f;
    for (int c = tp * 16; c < tp * 16 + 16; c++) s += Xs[tr * 68 + c];
    redA[tr][tp] = s;
    __syncthreads();
    float mu = (redA[tr][0] + redA[tr][1] + redA[tr][2] + redA[tr][3]) * (1.0f / 64.0f);
    __syncthreads();
    float vs = 0.f;
    for (int c = tp * 16; c < tp * 16 + 16; c++) {
        float d = Xs[tr * 68 + c] - mu;
        vs += d * d;
    }
    redA[tr][tp] = vs;
    __syncthreads();
    float var = (redA[tr][0] + redA[tr][1] + redA[tr][2] + redA[tr][3]) * (1.0f / 64.0f);
    float rs = rsqrtf(var + 1e-5f);
    for (int c = tp * 16; c < tp * 16 + 16; c++)
        Xs[tr * 68 + c] = (Xs[tr * 68 + c] - mu) * rs * g[c] + b[c];
    __syncthreads();
    int tm = tid >> 4, tn = tid & 15;
    float acc[4][4] = {};
#pragma unroll 8
    for (int kk = 0; kk < 64; kk++) {
        float4 bv = *(const float4*)&Ws[kk * 68 + tn * 4];
        float4 av = make_float4(Xs[(tm * 4 + 0) * 68 + kk], Xs[(tm * 4 + 1) * 68 + kk],
                                Xs[(tm * 4 + 2) * 68 + kk], Xs[(tm * 4 + 3) * 68 + kk]);
        FMA16(av, bv, acc)
    }
    __syncthreads();
#pragma unroll
    for (int ii = 0; ii < 4; ii++)
#pragma unroll
        for (int jj = 0; jj < 4; jj++)
            Xs[(tm * 4 + ii) * 68 + tn * 4 + jj] = fmaxf(acc[ii][jj] + b1[tn * 4 + jj], 0.f);
#pragma unroll
    for (int it = 0; it < 4; it++) {
        int idx = tid + it * 256;
        int r = idx >> 4, c4 = (idx & 15) * 4;
        *(float4*)&Ws[r * 68 + c4] = *(const float4*)&W2[(size_t)r * 64 + c4];
    }
    __syncthreads();
    float acc2[4][4] = {};
#pragma unroll 8
    for (int kk = 0; kk < 64; kk++) {
        float4 bv = *(const float4*)&Ws[kk * 68 + tn * 4];
        float4 av = make_float4(Xs[(tm * 4 + 0) * 68 + kk], Xs[(tm * 4 + 1) * 68 + kk],
                                Xs[(tm * 4 + 2) * 68 + kk], Xs[(tm * 4 + 3) * 68 + kk]);
        FMA16(av, bv, acc2)
    }
    __syncthreads();
#pragma unroll
    for (int ii = 0; ii < 4; ii++) {
        int r = row0 + tm * 4 + ii;
#pragma unroll
        for (int jj = 0; jj < 4; jj++) {
            int c = tn * 4 + jj;
            float vv = acc2[ii][jj] + b2[c] + hbuf[(size_t)r * 64 + c];
            hbuf[(size_t)r * 64 + c] = vv;
            hist[(size_t)r * 320 + c] = vv;
            Ws[(tm * 4 + ii) * 68 + c] = vv;   // stage for next-layer LN
        }
    }
    if (lnn_g) {
        __syncthreads();
        ln64_smem(Ws, redA, lnn_g, lnn_b, (float*)g_xn, row0, tid);
    }
}

// ------------------------- scalar FFMA SGEMM (head) -------------------------
__global__ void __launch_bounds__(256) gemm_k(
    const float* __restrict__ A, const float* __restrict__ B, float* __restrict__ C,
    const float* __restrict__ bias, const float* __restrict__ resid,
    int M, int N, int K, int act)
{
    __shared__ float As[16][68];
    __shared__ float Bs[16][68];
    int tid = threadIdx.x;
    int row0 = blockIdx.x * 64, col0 = blockIdx.y * 64;
    int tm = tid >> 4, tn = tid & 15;
    int arow = tid >> 2, ac = tid & 3;
    int bk = tid >> 4, bn = tid & 15;
    float acc[4][4] = {};
    for (int k0 = 0; k0 < K; k0 += 16) {
        float4 a = *(const float4*)&A[(size_t)(row0 + arow) * K + k0 + ac * 4];
        As[ac * 4 + 0][arow] = a.x; As[ac * 4 + 1][arow] = a.y;
        As[ac * 4 + 2][arow] = a.z; As[ac * 4 + 3][arow] = a.w;
        int bcol = col0 + bn * 4;
        float4 bv = make_float4(0.f, 0.f, 0.f, 0.f);
        if (bcol < N) bv = *(const float4*)&B[(size_t)(k0 + bk) * N + bcol];
        *(float4*)&Bs[bk][bn * 4] = bv;
        __syncthreads();
#pragma unroll
        for (int kk = 0; kk < 16; kk++) {
            float4 av = *(const float4*)&As[kk][tm * 4];
            float4 bw = *(const float4*)&Bs[kk][tn * 4];
            FMA16(av, bw, acc)
        }
        __syncthreads();
    }
#pragma unroll
    for (int ii = 0; ii < 4; ii++) {
        int r = row0 + tm * 4 + ii;
#pragma unroll
        for (int jj = 0; jj < 4; jj++) {
            int ccol = col0 + tn * 4 + jj;
            if (ccol < N) {
                float vv = acc[ii][jj];
                if (bias) vv += bias[ccol];
                if (act == 1) vv = fmaxf(vv, 0.f);
                else if (act == 2) vv = tanhf(vv);
                if (resid) vv += resid[(size_t)r * N + ccol];
                C[(size_t)r * N + ccol] = vv;
            }
        }
    }
}

// ------------------------- LayerNorm 256 + tanh, warp per row -------------------------
__global__ void ln256w_k(const float* __restrict__ in, float* __restrict__ out,
                         const float* __restrict__ g, const float* __restrict__ b) {
    int w = threadIdx.x >> 5, lane = threadIdx.x & 31;
    int row = blockIdx.x * 8 + w;
    const float* xr = in + (size_t)row * 256;
    float x[8];
    float s = 0.f;
#pragma unroll
    for (int m = 0; m < 8; m++) { x[m] = xr[lane + 32 * m]; s += x[m]; }
    for (int o = 16; o; o >>= 1) s += __shfl_xor_sync(0xffffffffu, s, o);
    float mu = s * (1.0f / 256.0f);
    float vs = 0.f;
#pragma unroll
    for (int m = 0; m < 8; m++) { float d = x[m] - mu; vs += d * d; }
    for (int o = 16; o; o >>= 1) vs += __shfl_xor_sync(0xffffffffu, vs, o);
    float rs = rsqrtf(vs * (1.0f / 256.0f) + 1e-5f);
#pragma unroll
    for (int m = 0; m < 8; m++) {
        int c = lane + 32 * m;
        out[(size_t)row * 256 + c] = tanhf((x[m] - mu) * rs * g[c] + b[c]);
    }
}

// ------------------------- reductions + final projection -------------------------
__global__ void red1_k(const float* __restrict__ t) {
    __shared__ float sm[256];
    int blk = blockIdx.x, tid = threadIdx.x;
    int col = tid & 31, r0 = tid >> 5;
    float s = 0.f;
    for (int r = r0; r < 128; r += 8) s += t[(size_t)(blk * 128 + r) * 32 + col];
    sm[tid] = s;
    __syncthreads();
    for (int s2 = 4; s2; s2 >>= 1) {
        if (r0 < s2) sm[tid] += sm[tid + s2 * 32];
        __syncthreads();
    }
    if (r0 == 0) g_part[blk * 32 + col] = sm[col];
}

__global__ void red2_k(const float* __restrict__ pw, const float* __restrict__ pb,
                       float* __restrict__ out) {
    __shared__ float mean[32];
    int t = threadIdx.x;
    if (t < 32) {
        float s = 0.f;
        for (int b = 0; b < 128; b++) s += g_part[b * 32 + t];
        mean[t] = s * (1.0f / 16384.0f);
    }
    __syncthreads();
    if (t < 32) {
        float s = pb[t];
        for (int c = 0; c < 32; c++) s += mean[c] * pw[c * 32 + t];
        out[t] = s;
    }
}

// ------------------------- host orchestration -------------------------
extern "C" void kernel_launch(void* const* d_in, const int* in_sizes, int n_in,
                              void* d_out, int out_size)
{
    const float* x      = (const float*)d_in[0];
    const float* coords = (const float*)d_in[1];
    const float* regions= (const float*)d_in[3];
    const float* fe_w1  = (const float*)d_in[4];
    const float* fe_b1  = (const float*)d_in[5];
    const float* fe_w2  = (const float*)d_in[6];
    const float* fe_b2  = (const float*)d_in[7];
    const float* ln1_g  = (const float*)d_in[8];
    const float* ln1_b  = (const float*)d_in[9];
    const float* wq     = (const float*)d_in[10];
    const float* wk     = (const float*)d_in[11];
    const float* wv     = (const float*)d_in[12];
    const float* wrpe   = (const float*)d_in[13];
    const float* ow     = (const float*)d_in[14];
    const float* ob     = (const float*)d_in[15];
    const float* ln2_g  = (const float*)d_in[16];
    const float* ln2_b  = (const float*)d_in[17];
    const float* f1w    = (const float*)d_in[18];
    const float* f1b    = (const float*)d_in[19];
    const float* f2w    = (const float*)d_in[20];
    const float* f2b    = (const float*)d_in[21];
    const float* Wcat   = (const float*)d_in[22];
    const float* m1w    = (const float*)d_in[23];
    const float* m1b    = (const float*)d_in[24];
    const float* mlng   = (const float*)d_in[25];
    const float* mlnb   = (const float*)d_in[26];
    const float* m2w    = (const float*)d_in[27];
    const float* m2b    = (const float*)d_in[28];
    const float* pw     = (const float*)d_in[29];
    const float* pb     = (const float*)d_in[30];
    float* out = (float*)d_out;

    float *p_h, *p_hist, *p_t0, *p_u, *p_u2, *p_t, *p_w2, *p_M, *p_G;
    int *p_rhist, *p_rbase, *p_bhist, *p_bbase;
    cudaGetSymbolAddress((void**)&p_h,    g_h);
    cudaGetSymbolAddress((void**)&p_hist, g_hist);
    cudaGetSymbolAddress((void**)&p_t0,   g_t0);
    cudaGetSymbolAddress((void**)&p_u,    g_u);
    cudaGetSymbolAddress((void**)&p_u2,   g_u2);
    cudaGetSymbolAddress((void**)&p_t,    g_t);
    cudaGetSymbolAddress((void**)&p_w2,   g_W2);
    cudaGetSymbolAddress((void**)&p_M,    g_M);
    cudaGetSymbolAddress((void**)&p_G,    g_G);
    cudaGetSymbolAddress((void**)&p_rhist, r_hist);
    cudaGetSymbolAddress((void**)&p_rbase, r_base);
    cudaGetSymbolAddress((void**)&p_bhist, b_hist);
    cudaGetSymbolAddress((void**)&p_bbase, b_base);

    const int M = NNODE;

    // ---- bucket ordering via counting sorts ----
    zero_k<<<512, 256>>>();
    rank_hist_k<<<dim3(64, 2), 256>>>(coords);
    scan_k<<<2, 1024>>>(p_rhist, p_rbase, NNODE, NNODE);
    rank_place_k<<<dim3(64, 2), 256>>>(coords);
    rank_rank_k<<<dim3(64, 2), 256>>>(coords);
    key1_k<<<dim3(64, 16), 256>>>(regions);
    key2_k<<<dim3(64, 16), 256>>>();
    scan_k<<<16, 1024>>>(p_bhist, p_bbase, KBINS, KBINS);
    bucket_place_k<<<dim3(64, 16), 256>>>();
    bucket_pos_k<<<dim3(64, 16), 256>>>();
    w2all_k<<<4, 128>>>(wrpe);
    mh_k<<<32, 256>>>(wq, wk);
    gw_k<<<32, 256>>>(wv, ow);

    // feat encoder + LN1(layer 0)
    ffe_k<<<256, 256>>>(x, fe_w1, fe_b1, fe_w2, fe_b2, ln1_g, ln1_b);

    for (int l = 0; l < 4; l++) {
        tq_k<<<dim3(256, 8), 256>>>(p_M + (size_t)l * 8 * 4096);
        attn_k<<<dim3(256, 8, 2), 256>>>(coords, p_w2 + l * 16);
        outproj_k<<<256, 256>>>(p_G + (size_t)l * 8 * 4096, ob + l * 64, p_h);
        const float* nlg = (l < 3) ? (ln1_g + (l + 1) * 64) : nullptr;
        const float* nlb = (l < 3) ? (ln1_b + (l + 1) * 64) : nullptr;
        ffn_k<<<256, 256>>>(p_h, ln2_g + l * 64, ln2_b + l * 64,
                            f1w + (size_t)l * 64 * 64, f1b + l * 64,
                            f2w + (size_t)l * 64 * 64, f2b + l * 64,
                            p_hist + (l + 1) * 64, nlg, nlb);
    }

    gemm_k<<<dim3(256, 1), 256>>>(p_hist, Wcat, p_t0, nullptr, nullptr, M, 32, 320, 2);
    gemm_k<<<dim3(256, 4), 256>>>(p_t0, m1w, p_u, m1b, nullptr, M, 256, 32, 0);
    ln256w_k<<<2048, 256>>>(p_u, p_u2, mlng, mlnb);
    gemm_k<<<dim3(256, 1), 256>>>(p_u2, m2w, p_t, m2b, p_t0, M, 32, 256, 0);
    red1_k<<<128, 256>>>(p_t);
    red2_k<<<1, 256>>>(pw, pb, out);
}

// round 12
// speedup vs baseline: 2.5891x; 1.0272x over previous
#include <cuda_runtime.h>
#include <cuda_bf16.h>
#include <math.h>

#define NNODE 16384
#define HEADS 8
#define DIM   64
#define HDIM  512
#define KBINS 40960

// ------------------------- device scratch (no allocs allowed) -------------------------
__device__ int   g_rank[2][NNODE];
__device__ int   g_order[16 * NNODE];
__device__ float g_h[NNODE * DIM];
__device__ float g_xn[NNODE * DIM];          // LN1(h), tf32-pre-rounded
__device__ float g_T[NNODE * HDIM];          // T = Xn @ M_h, tf32-pre-rounded
__device__ float g_hist[NNODE * 320];
__device__ float g_outr[16 * NNODE * DIM];   // R = P@X  [nh*8+h][node][d]
__device__ float g_lser[16 * NNODE];
__device__ float g_W2[4 * 16];               // [layer][h][c]
__device__ float g_M[4 * 8 * 64 * 64];       // [layer][head][d][e] = sum_c Wq[d,c]Wk[e,c]/8
__device__ float g_G[4 * 8 * 64 * 64];       // [layer][head][d][e] = Wv_h @ Ow_h (exact)
__device__ float g_t0[NNODE * 32];
__device__ float g_u [NNODE * 256];
__device__ float g_u2[NNODE * 256];
__device__ float g_t [NNODE * 32];
__device__ float g_part[128 * 32];

// sorting scratch
__device__ int r_hist[2][NNODE];
__device__ int r_base[2][NNODE];
__device__ int r_cnt [2][NNODE];
__device__ int r_slot[2][NNODE];
__device__ int b_keys[16][NNODE];
__device__ int b_hist[16][KBINS];
__device__ int b_base[16][KBINS];
__device__ int b_cnt [16][KBINS];
__device__ int b_slot[16][NNODE];
__device__ int g_maxre[16];

// ------------------------- tf32 helpers -------------------------
__device__ __forceinline__ unsigned f2tf(float f) {
    unsigned u;
    asm("cvt.rna.tf32.f32 %0, %1;" : "=r"(u) : "f"(f));
    return u;
}

__device__ __forceinline__ void mma_tf32(float c[4], unsigned a0, unsigned a1,
                                         unsigned a2, unsigned a3,
                                         unsigned b0, unsigned b1) {
    asm volatile(
        "mma.sync.aligned.m16n8k8.row.col.f32.tf32.tf32.f32 "
        "{%0,%1,%2,%3}, {%4,%5,%6,%7}, {%8,%9}, {%0,%1,%2,%3};"
        : "+f"(c[0]), "+f"(c[1]), "+f"(c[2]), "+f"(c[3])
        : "r"(a0), "r"(a1), "r"(a2), "r"(a3), "r"(b0), "r"(b1));
}

// ------------------------- zero all counting scratch -------------------------
__global__ void zero_k() {
    int gid = blockIdx.x * 256 + threadIdx.x;
    int stride = gridDim.x * 256;
    for (int i = gid; i < 2 * NNODE; i += stride) { ((int*)r_hist)[i] = 0; ((int*)r_cnt)[i] = 0; }
    for (int i = gid; i < 16 * KBINS; i += stride) { ((int*)b_hist)[i] = 0; ((int*)b_cnt)[i] = 0; }
    if (gid < 16) g_maxre[gid] = 0;
}

// ------------------------- coordinate ranks via counting -------------------------
__device__ __forceinline__ int coord_bin(float c) {
    int u = (int)(c * 16384.0f);
    return min(16383, max(0, u));
}

__global__ void rank_hist_k(const float* __restrict__ coords) {
    int axis = blockIdx.y;
    int i = blockIdx.x * 256 + threadIdx.x;
    int u = coord_bin(coords[i * 3 + axis]);
    atomicAdd(&r_hist[axis][u], 1);
}

__global__ void __launch_bounds__(1024) scan_k(const int* __restrict__ hist,
                                               int* __restrict__ base,
                                               int nbins, int rowstride) {
    __shared__ int ss[1024];
    int row = blockIdx.x;
    const int* h = hist + (size_t)row * rowstride;
    int* bs = base + (size_t)row * rowstride;
    int t = threadIdx.x;
    int chunk = (nbins + 1023) >> 10;
    int b0 = t * chunk;
    int s = 0;
    for (int m = 0; m < chunk; m++) { int idx = b0 + m; if (idx < nbins) s += h[idx]; }
    ss[t] = s;
    __syncthreads();
    for (int d = 1; d < 1024; d <<= 1) {
        int v = (t >= d) ? ss[t - d] : 0;
        __syncthreads();
        ss[t] += v;
        __syncthreads();
    }
    int run = (t > 0) ? ss[t - 1] : 0;
    for (int m = 0; m < chunk; m++) {
        int idx = b0 + m;
        if (idx < nbins) { bs[idx] = run; run += h[idx]; }
    }
}

__global__ void rank_place_k(const float* __restrict__ coords) {
    int axis = blockIdx.y;
    int i = blockIdx.x * 256 + threadIdx.x;
    int u = coord_bin(coords[i * 3 + axis]);
    int slot = r_base[axis][u] + atomicAdd(&r_cnt[axis][u], 1);
    r_slot[axis][slot] = i;
}

__global__ void rank_rank_k(const float* __restrict__ coords) {
    int axis = blockIdx.y;
    int i = blockIdx.x * 256 + threadIdx.x;
    float ci = coords[i * 3 + axis];
    int u = coord_bin(ci);
    int b = r_base[axis][u], n = r_hist[axis][u];
    int r = 0;
    for (int m = 0; m < n; m++) {
        int j = r_slot[axis][b + m];
        float cj = coords[j * 3 + axis];
        r += (int)((cj < ci) || (cj == ci && j < i));
    }
    g_rank[axis][i] = b + r;
}

// ------------------------- bucket order via counting sort -------------------------
__global__ void key1_k(const float* __restrict__ regions) {
    __shared__ int smax[256];
    int row = blockIdx.y;
    int nh = row >> 3, h = row & 7;
    float qe = 16384.0f / regions[nh * 16 + h];
    float qp = 16384.0f / regions[nh * 16 + 8 + h];
    int i = blockIdx.x * 256 + threadIdx.x;
    int re = (int)floorf((float)g_rank[0][i] / qe) + 1;
    int rp = (int)floorf((float)g_rank[1][i] / qp) + 1;
    b_keys[row][i] = (rp << 16) | re;
    smax[threadIdx.x] = re;
    __syncthreads();
    for (int s = 128; s > 0; s >>= 1) {
        if (threadIdx.x < s) smax[threadIdx.x] = max(smax[threadIdx.x], smax[threadIdx.x + s]);
        __syncthreads();
    }
    if (threadIdx.x == 0) atomicMax(&g_maxre[row], smax[0]);
}

__global__ void key2_k() {
    int row = blockIdx.y;
    int i = blockIdx.x * 256 + threadIdx.x;
    int nb = (int)ceilf(log2f((float)g_maxre[row] + 1.0f));
    int v = b_keys[row][i];
    int key = ((v >> 16) << nb) | (v & 0xffff);
    b_keys[row][i] = key;
    atomicAdd(&b_hist[row][key], 1);
}

__global__ void bucket_place_k() {
    int row = blockIdx.y;
    int i = blockIdx.x * 256 + threadIdx.x;
    int key = b_keys[row][i];
    int slot = b_base[row][key] + atomicAdd(&b_cnt[row][key], 1);
    b_slot[row][slot] = i;
}

__global__ void bucket_pos_k() {
    int row = blockIdx.y;
    int i = blockIdx.x * 256 + threadIdx.x;
    int key = b_keys[row][i];
    int b = b_base[row][key], n = b_hist[row][key];
    int r = 0;
    for (int m = 0; m < n; m++) r += (int)(b_slot[row][b + m] < i);
    g_order[row * NNODE + b + r] = i;
}

// ------------------------- RPE distance weights (all 4 layers) -------------------------
__global__ void w2all_k(const float* __restrict__ wrpe) {   // [4][512][16]
    __shared__ float sq[128];
    int l = blockIdx.x;
    const float* w = wrpe + (size_t)l * 512 * 16;
    int t = threadIdx.x;
    int h = t >> 4, m = t & 15;
    float s = 0.f;
    for (int d = 0; d < 64; d++) s += w[(h * 64 + d) * 16 + m];
    float om = s * (1.0f / 64.0f);
    sq[t] = om * om;
    __syncthreads();
    if (t < 16) {
        int hh = t >> 1, c = t & 1;
        float ww = 0.f;
        for (int kk = 0; kk < 8; kk++) ww += sq[hh * 16 + c * 8 + kk];
        g_W2[l * 16 + t] = ww;
    }
}

// ------------------------- M_h[d][e] = sum_c Wq[d,c] Wk[e,c] / 8 (exact fp32, NT) -------------------------
#define FMA16(av, bv, acc)                                                         \
    acc[0][0]+=av.x*bv.x; acc[0][1]+=av.x*bv.y; acc[0][2]+=av.x*bv.z; acc[0][3]+=av.x*bv.w; \
    acc[1][0]+=av.y*bv.x; acc[1][1]+=av.y*bv.y; acc[1][2]+=av.y*bv.z; acc[1][3]+=av.y*bv.w; \
    acc[2][0]+=av.z*bv.x; acc[2][1]+=av.z*bv.y; acc[2][2]+=av.z*bv.z; acc[2][3]+=av.z*bv.w; \
    acc[3][0]+=av.w*bv.x; acc[3][1]+=av.w*bv.y; acc[3][2]+=av.w*bv.z; acc[3][3]+=av.w*bv.w;

__global__ void __launch_bounds__(256) mh_k(const float* __restrict__ wq,
                                            const float* __restrict__ wk) {
    __shared__ float Aq[64 * 68];   // [d][c]
    __shared__ float Bk[64 * 68];   // [e][c]
    int bx = blockIdx.x;            // l*8 + h
    int l = bx >> 3, h = bx & 7;
    int tid = threadIdx.x;
#pragma unroll
    for (int it = 0; it < 4; it++) {
        int idx = tid + it * 256;
        int d = idx >> 4, c4 = (idx & 15) * 4;
        *(float4*)&Aq[d * 68 + c4] = *(const float4*)&wq[((size_t)(l * 64 + d)) * 512 + h * 64 + c4];
        *(float4*)&Bk[d * 68 + c4] = *(const float4*)&wk[((size_t)(l * 64 + d)) * 512 + h * 64 + c4];
    }
    __syncthreads();
    int tm = tid >> 4, tn = tid & 15;
    float acc[4][4] = {};
#pragma unroll 4
    for (int c = 0; c < 64; c++) {
        float4 av = make_float4(Aq[(tm * 4 + 0) * 68 + c], Aq[(tm * 4 + 1) * 68 + c],
                                Aq[(tm * 4 + 2) * 68 + c], Aq[(tm * 4 + 3) * 68 + c]);
        float4 bv = make_float4(Bk[(tn * 4 + 0) * 68 + c], Bk[(tn * 4 + 1) * 68 + c],
                                Bk[(tn * 4 + 2) * 68 + c], Bk[(tn * 4 + 3) * 68 + c]);
        FMA16(av, bv, acc)
    }
#pragma unroll
    for (int ii = 0; ii < 4; ii++)
#pragma unroll
        for (int jj = 0; jj < 4; jj++)
            g_M[(size_t)bx * 4096 + (tm * 4 + ii) * 64 + tn * 4 + jj] = 0.125f * acc[ii][jj];
}

// ------------------------- G_h = Wv_h @ Ow_h (exact, NN) -------------------------
__global__ void __launch_bounds__(256) gw_k(const float* __restrict__ wv,
                                            const float* __restrict__ ow) {
    __shared__ float Av[64 * 68];   // [d][c]
    __shared__ float Bo[64 * 68];   // [c][e]
    int bx = blockIdx.x;            // l*8 + h
    int l = bx >> 3, h = bx & 7;
    int tid = threadIdx.x;
#pragma unroll
    for (int it = 0; it < 4; it++) {
        int idx = tid + it * 256;
        int r = idx >> 4, c4 = (idx & 15) * 4;
        *(float4*)&Av[r * 68 + c4] = *(const float4*)&wv[((size_t)(l * 64 + r)) * 512 + h * 64 + c4];
        *(float4*)&Bo[r * 68 + c4] = *(const float4*)&ow[((size_t)(l * 512 + h * 64 + r)) * 64 + c4];
    }
    __syncthreads();
    int tm = tid >> 4, tn = tid & 15;
    float acc[4][4] = {};
#pragma unroll 4
    for (int c = 0; c < 64; c++) {
        float4 av = make_float4(Av[(tm * 4 + 0) * 68 + c], Av[(tm * 4 + 1) * 68 + c],
                                Av[(tm * 4 + 2) * 68 + c], Av[(tm * 4 + 3) * 68 + c]);
        float4 bv = *(const float4*)&Bo[c * 68 + tn * 4];
        FMA16(av, bv, acc)
    }
#pragma unroll
    for (int ii = 0; ii < 4; ii++)
#pragma unroll
        for (int jj = 0; jj < 4; jj++)
            g_G[(size_t)bx * 4096 + (tm * 4 + ii) * 64 + tn * 4 + jj] = acc[ii][jj];
}

// ------------------------- shared LN helper; writes tf32-pre-rounded output -------------------------
__device__ __forceinline__ void ln64_smem(const float* Xs, float (*redA)[4],
                                          const float* g, const float* b,
                                          float* dst, int row0, int tid) {
    int tr = tid >> 2, tp = tid & 3;
    float s = 0.f;
    for (int c = tp * 16; c < tp * 16 + 16; c++) s += Xs[tr * 68 + c];
    redA[tr][tp] = s;
    __syncthreads();
    float mu = (redA[tr][0] + redA[tr][1] + redA[tr][2] + redA[tr][3]) * (1.0f / 64.0f);
    __syncthreads();
    float vs = 0.f;
    for (int c = tp * 16; c < tp * 16 + 16; c++) {
        float d = Xs[tr * 68 + c] - mu;
        vs += d * d;
    }
    redA[tr][tp] = vs;
    __syncthreads();
    float var = (redA[tr][0] + redA[tr][1] + redA[tr][2] + redA[tr][3]) * (1.0f / 64.0f);
    float rs = rsqrtf(var + 1e-5f);
    for (int c = tp * 16; c < tp * 16 + 16; c++) {
        float vv = (Xs[tr * 68 + c] - mu) * rs * g[c] + b[c];
        dst[(size_t)(row0 + tr) * 64 + c] = __uint_as_float(f2tf(vv));
    }
}

// ------------------------- fused feat encoder + LN1(layer0) (exact FFMA) -------------------------
__global__ void __launch_bounds__(256) ffe_k(
    const float* __restrict__ x,
    const float* __restrict__ W1, const float* __restrict__ b1,
    const float* __restrict__ W2, const float* __restrict__ b2,
    const float* __restrict__ lng, const float* __restrict__ lnb)
{
    __shared__ float Xs16[64 * 17];
    __shared__ float W1s[16 * 68];
    __shared__ float Ts[64 * 68];
    __shared__ float W2s[64 * 68];
    __shared__ float redA[64][4];
    int tid = threadIdx.x;
    int row0 = blockIdx.x * 64;
    {
        int r = tid >> 2, c4 = (tid & 3) * 4;
        float4 xv = *(const float4*)&x[(size_t)(row0 + r) * 16 + c4];
        Xs16[r * 17 + c4 + 0] = xv.x; Xs16[r * 17 + c4 + 1] = xv.y;
        Xs16[r * 17 + c4 + 2] = xv.z; Xs16[r * 17 + c4 + 3] = xv.w;
    }
    if (tid < 16 * 16) {
        int r = tid >> 4, c4 = (tid & 15) * 4;
        *(float4*)&W1s[r * 68 + c4] = *(const float4*)&W1[(size_t)r * 64 + c4];
    }
#pragma unroll
    for (int it = 0; it < 4; it++) {
        int idx = tid + it * 256;
        int r = idx >> 4, c4 = (idx & 15) * 4;
        *(float4*)&W2s[r * 68 + c4] = *(const float4*)&W2[(size_t)r * 64 + c4];
    }
    __syncthreads();
    int tm = tid >> 4, tn = tid & 15;
    float acc[4][4] = {};
#pragma unroll
    for (int kk = 0; kk < 16; kk++) {
        float4 av = make_float4(Xs16[(tm * 4 + 0) * 17 + kk], Xs16[(tm * 4 + 1) * 17 + kk],
                                Xs16[(tm * 4 + 2) * 17 + kk], Xs16[(tm * 4 + 3) * 17 + kk]);
        float4 bv = *(const float4*)&W1s[kk * 68 + tn * 4];
        FMA16(av, bv, acc)
    }
#pragma unroll
    for (int ii = 0; ii < 4; ii++)
#pragma unroll
        for (int jj = 0; jj < 4; jj++)
            Ts[(tm * 4 + ii) * 68 + tn * 4 + jj] = fmaxf(acc[ii][jj] + b1[tn * 4 + jj], 0.f);
    __syncthreads();
    float acc2[4][4] = {};
#pragma unroll 8
    for (int kk = 0; kk < 64; kk++) {
        float4 av = make_float4(Ts[(tm * 4 + 0) * 68 + kk], Ts[(tm * 4 + 1) * 68 + kk],
                                Ts[(tm * 4 + 2) * 68 + kk], Ts[(tm * 4 + 3) * 68 + kk]);
        float4 bv = *(const float4*)&W2s[kk * 68 + tn * 4];
        FMA16(av, bv, acc2)
    }
    __syncthreads();
#pragma unroll
    for (int ii = 0; ii < 4; ii++) {
        int r = row0 + tm * 4 + ii;
#pragma unroll
        for (int jj = 0; jj < 4; jj++) {
            int c = tn * 4 + jj;
            float vv = acc2[ii][jj] + b2[c];
            g_h[(size_t)r * 64 + c] = vv;
            g_hist[(size_t)r * 320 + c] = vv;
            W2s[(tm * 4 + ii) * 68 + c] = vv;   // stage for LN
        }
    }
    __syncthreads();
    ln64_smem(W2s, redA, lng, lnb, (float*)g_xn, row0, tid);
}

// ------------------------- T = Xn @ M_h  (all nodes, per head), pre-rounded output -------------------------
__global__ void __launch_bounds__(256) tq_k(const float* __restrict__ Mbase) {
    __shared__ unsigned As[64 * 68];
    __shared__ unsigned Bs[64 * 68];
    int tid = threadIdx.x;
    int row0 = blockIdx.x * 64, h = blockIdx.y;
    const float* Mg = Mbase + (size_t)h * 4096;
#pragma unroll
    for (int it = 0; it < 4; it++) {
        int idx = tid + it * 256;
        int r = idx >> 4, c4 = (idx & 15) * 4;
        // g_xn already tf32-rounded: raw copy
        *(uint4*)&As[r * 68 + c4] = *(const uint4*)&g_xn[(size_t)(row0 + r) * 64 + c4];
        float4 bv = *(const float4*)&Mg[r * 64 + c4];
        Bs[r * 68 + c4 + 0] = f2tf(bv.x); Bs[r * 68 + c4 + 1] = f2tf(bv.y);
        Bs[r * 68 + c4 + 2] = f2tf(bv.z); Bs[r * 68 + c4 + 3] = f2tf(bv.w);
    }
    __syncthreads();
    int wid = tid >> 5, lane = tid & 31;
    int g = lane >> 2, t = lane & 3;
    int r0 = (wid & 3) * 16, c0 = (wid >> 2) * 32;
    float acc[4][4] = {};
#pragma unroll
    for (int ks = 0; ks < 8; ks++) {
        int k0 = ks * 8;
        unsigned a0 = As[(r0 + g) * 68 + k0 + t];
        unsigned a1 = As[(r0 + g + 8) * 68 + k0 + t];
        unsigned a2 = As[(r0 + g) * 68 + k0 + t + 4];
        unsigned a3 = As[(r0 + g + 8) * 68 + k0 + t + 4];
#pragma unroll
        for (int nt = 0; nt < 4; nt++) {
            int n = c0 + nt * 8 + g;
            unsigned b0 = Bs[(k0 + t) * 68 + n];
            unsigned b1 = Bs[(k0 + t + 4) * 68 + n];
            mma_tf32(acc[nt], a0, a1, a2, a3, b0, b1);
        }
    }
#pragma unroll
    for (int nt = 0; nt < 4; nt++)
#pragma unroll
        for (int cr = 0; cr < 4; cr++) {
            int r = row0 + r0 + g + (cr >> 1) * 8;
            int c = c0 + nt * 8 + 2 * t + (cr & 1);
            g_T[(size_t)r * 512 + h * 64 + c] = __uint_as_float(f2tf(acc[nt][cr]));
        }
}

// ------------------------- attention: raw tf32 gathers, 2 smem buffers -------------------------
__global__ void __launch_bounds__(256) attn_k(
    const float* __restrict__ coords, const float* __restrict__ W2row)
{
    __shared__ unsigned Xs[64 * 68];   // X tf32
    __shared__ unsigned Ts[64 * 68];   // T tf32 -> S float / P tf32 [j][i]
    __shared__ int   nd[64];
    __shared__ float cx[64], cy[64], redm[4][64], reds[4][64];

    int tid = threadIdx.x;
    int blk = blockIdx.x, h = blockIdx.y, nh = blockIdx.z;
    int row = nh * 8 + h;
    const int* ord = g_order + row * NNODE + blk * 64;
    if (tid < 64) {
        int nn = ord[tid];
        nd[tid] = nn;
        cx[tid] = coords[nn * 3 + 0];
        cy[tid] = coords[nn * 3 + 1];
    }
    __syncthreads();

    // gather pre-rounded X and T rows: raw uint4 copies, no cvt
#pragma unroll
    for (int it = 0; it < 4; it++) {
        int idx = tid + it * 256;               // 0..1023
        int i = idx >> 4, q = (idx & 15) * 4;
        size_t nb = (size_t)nd[i];
        *(uint4*)&Xs[i * 68 + q] = *(const uint4*)&g_xn[nb * 64 + q];
        *(uint4*)&Ts[i * 68 + q] = *(const uint4*)&g_T[nb * 512 + h * 64 + q];
    }
    __syncthreads();

    int wid = tid >> 5, lane = tid & 31;
    int g = lane >> 2, t = lane & 3;
    int r0 = (wid & 3) * 16, c0 = (wid >> 2) * 32;

    // S = T @ X^T (+RPE) in registers
    float acc[4][4] = {};
#pragma unroll
    for (int ks = 0; ks < 8; ks++) {
        int k0 = ks * 8;
        unsigned a0 = Ts[(r0 + g) * 68 + k0 + t];
        unsigned a1 = Ts[(r0 + g + 8) * 68 + k0 + t];
        unsigned a2 = Ts[(r0 + g) * 68 + k0 + t + 4];
        unsigned a3 = Ts[(r0 + g + 8) * 68 + k0 + t + 4];
#pragma unroll
        for (int nt = 0; nt < 4; nt++) {
            int j = c0 + nt * 8 + g;
            unsigned b0 = Xs[j * 68 + k0 + t];
            unsigned b1 = Xs[j * 68 + k0 + t + 4];
            mma_tf32(acc[nt], a0, a1, a2, a3, b0, b1);
        }
    }
    float W0 = W2row[h * 2 + 0], W1 = W2row[h * 2 + 1];
    __syncthreads();   // all reads of Ts done; reuse as S

    float* Sf = (float*)Ts;
#pragma unroll
    for (int nt = 0; nt < 4; nt++) {
        int j0 = c0 + nt * 8 + 2 * t;
#pragma unroll
        for (int cr = 0; cr < 4; cr++) {
            int i = r0 + g + (cr >> 1) * 8;
            int j = j0 + (cr & 1);
            float dx = cx[i] - cx[j], dy = cy[i] - cy[j];
            Sf[j * 68 + i] = acc[nt][cr] - W0 * dx * dx - W1 * dy * dy;
        }
    }
    __syncthreads();

    // softmax over j per query i (layout [j][i])
    int ci = tid & 63, seg = tid >> 6;
    float ml = -3.0e38f;
#pragma unroll
    for (int jj = 0; jj < 16; jj++) ml = fmaxf(ml, Sf[(seg * 16 + jj) * 68 + ci]);
    redm[seg][ci] = ml;
    __syncthreads();
    float mm = fmaxf(fmaxf(redm[0][ci], redm[1][ci]), fmaxf(redm[2][ci], redm[3][ci]));
    float ev[16];
    float sl = 0.f;
#pragma unroll
    for (int jj = 0; jj < 16; jj++) {
        float e = __expf(Sf[(seg * 16 + jj) * 68 + ci] - mm);
        ev[jj] = e;
        sl += e;
    }
    reds[seg][ci] = sl;
    __syncthreads();
    float ssum = reds[0][ci] + reds[1][ci] + reds[2][ci] + reds[3][ci];
    float inv = 1.0f / ssum;
    if (seg == 0) g_lser[row * NNODE + nd[ci]] = mm + __logf(ssum);
    unsigned* Ps = Ts;
#pragma unroll
    for (int jj = 0; jj < 16; jj++)
        Ps[(seg * 16 + jj) * 68 + ci] = f2tf(ev[jj] * inv);
    __syncthreads();

    // R = P @ X  (P stored transposed [j][i]); store straight to gmem
    float racc[4][4] = {};
#pragma unroll
    for (int ks = 0; ks < 8; ks++) {
        int k0 = ks * 8;
        unsigned a0 = Ps[(k0 + t) * 68 + r0 + g];
        unsigned a1 = Ps[(k0 + t) * 68 + r0 + g + 8];
        unsigned a2 = Ps[(k0 + t + 4) * 68 + r0 + g];
        unsigned a3 = Ps[(k0 + t + 4) * 68 + r0 + g + 8];
#pragma unroll
        for (int nt = 0; nt < 4; nt++) {
            int n = c0 + nt * 8 + g;
            unsigned b0 = Xs[(k0 + t) * 68 + n];
            unsigned b1 = Xs[(k0 + t + 4) * 68 + n];
            mma_tf32(racc[nt], a0, a1, a2, a3, b0, b1);
        }
    }
#pragma unroll
    for (int nt = 0; nt < 4; nt++) {
        int d0 = c0 + nt * 8 + 2 * t;
        int iA = r0 + g, iB = r0 + g + 8;
        *(float2*)&g_outr[((size_t)row * NNODE + nd[iA]) * 64 + d0] =
            make_float2(racc[nt][0], racc[nt][1]);
        *(float2*)&g_outr[((size_t)row * NNODE + nd[iB]) * 64 + d0] =
            make_float2(racc[nt][2], racc[nt][3]);
    }
}

// ------------------------- fused epilogue: outproj + LN2 + FFN + resid + hist + LN1(next) ----------
// dynamic smem: AsU[64*68] u32 | BsU[64*68] u32 | Hs[64*68] f32  (52224 bytes)
__global__ void __launch_bounds__(256) epi_k(
    const float* __restrict__ gG, const float* __restrict__ ob,
    const float* __restrict__ lg2, const float* __restrict__ lb2,
    const float* __restrict__ W1, const float* __restrict__ b1,
    const float* __restrict__ W2, const float* __restrict__ b2,
    float* __restrict__ hist,
    const float* __restrict__ lnn_g, const float* __restrict__ lnn_b)
{
    extern __shared__ unsigned dyn[];
    unsigned* AsU = dyn;
    unsigned* BsU = dyn + 64 * 68;
    float*    Hs  = (float*)(dyn + 2 * 64 * 68);
    __shared__ float redA[64][4];
    __shared__ float w0s[64], w1s[64];
    float* As = (float*)AsU;
    float* Ws = (float*)BsU;
    int tid = threadIdx.x;
    int row0 = blockIdx.x * 64;
    int wid = tid >> 5, lane = tid & 31;
    int g = lane >> 2, t = lane & 3;
    int r0 = (wid & 3) * 16, c0 = (wid >> 2) * 32;

    // ---- stage 1: out-projection with fused lse-combine over 8 heads ----
    float acc[4][4] = {};
    for (int h = 0; h < 8; h++) {
        __syncthreads();
        if (tid < 64) {
            int node = row0 + tid;
            float l0 = g_lser[h * NNODE + node];
            float l1 = g_lser[(8 + h) * NNODE + node];
            float m = fmaxf(l0, l1);
            float e0 = __expf(l0 - m), e1 = __expf(l1 - m);
            float inv = 1.0f / (e0 + e1);
            w0s[tid] = e0 * inv;
            w1s[tid] = e1 * inv;
        }
        __syncthreads();
#pragma unroll
        for (int it = 0; it < 4; it++) {
            int idx = tid + it * 256;
            int r = idx >> 4, c4 = (idx & 15) * 4;
            int node = row0 + r;
            float4 o0 = *(const float4*)&g_outr[((size_t)h * NNODE + node) * 64 + c4];
            float4 o1 = *(const float4*)&g_outr[((size_t)(8 + h) * NNODE + node) * 64 + c4];
            float w0 = w0s[r], w1 = w1s[r];
            AsU[r * 68 + c4 + 0] = f2tf(w0 * o0.x + w1 * o1.x);
            AsU[r * 68 + c4 + 1] = f2tf(w0 * o0.y + w1 * o1.y);
            AsU[r * 68 + c4 + 2] = f2tf(w0 * o0.z + w1 * o1.z);
            AsU[r * 68 + c4 + 3] = f2tf(w0 * o0.w + w1 * o1.w);
            float4 bv = *(const float4*)&gG[(size_t)h * 4096 + r * 64 + c4];
            BsU[r * 68 + c4 + 0] = f2tf(bv.x); BsU[r * 68 + c4 + 1] = f2tf(bv.y);
            BsU[r * 68 + c4 + 2] = f2tf(bv.z); BsU[r * 68 + c4 + 3] = f2tf(bv.w);
        }
        __syncthreads();
#pragma unroll
        for (int ks = 0; ks < 8; ks++) {
            int k0 = ks * 8;
            unsigned a0 = AsU[(r0 + g) * 68 + k0 + t];
            unsigned a1 = AsU[(r0 + g + 8) * 68 + k0 + t];
            unsigned a2 = AsU[(r0 + g) * 68 + k0 + t + 4];
            unsigned a3 = AsU[(r0 + g + 8) * 68 + k0 + t + 4];
#pragma unroll
            for (int nt = 0; nt < 4; nt++) {
                int n = c0 + nt * 8 + g;
                unsigned b0 = BsU[(k0 + t) * 68 + n];
                unsigned b1 = BsU[(k0 + t + 4) * 68 + n];
                mma_tf32(acc[nt], a0, a1, a2, a3, b0, b1);
            }
        }
    }
    __syncthreads();
    // h1 = attn_out + ob + h_old  -> Hs
#pragma unroll
    for (int nt = 0; nt < 4; nt++) {
#pragma unroll
        for (int cr = 0; cr < 4; cr++) {
            int rl = r0 + g + (cr >> 1) * 8;
            int ccol = c0 + nt * 8 + 2 * t + (cr & 1);
            Hs[rl * 68 + ccol] = acc[nt][cr] + ob[ccol] + g_h[(size_t)(row0 + rl) * 64 + ccol];
        }
    }
    __syncthreads();

    // ---- stage 2: LN2 (Hs -> As) + load W1 ----
    {
        int tr = tid >> 2, tp = tid & 3;
        float s = 0.f;
        for (int c = tp * 16; c < tp * 16 + 16; c++) s += Hs[tr * 68 + c];
        redA[tr][tp] = s;
        __syncthreads();
        float mu = (redA[tr][0] + redA[tr][1] + redA[tr][2] + redA[tr][3]) * (1.0f / 64.0f);
        __syncthreads();
        float vs = 0.f;
        for (int c = tp * 16; c < tp * 16 + 16; c++) {
            float d = Hs[tr * 68 + c] - mu;
            vs += d * d;
        }
        redA[tr][tp] = vs;
        __syncthreads();
        float var = (redA[tr][0] + redA[tr][1] + redA[tr][2] + redA[tr][3]) * (1.0f / 64.0f);
        float rs = rsqrtf(var + 1e-5f);
        for (int c = tp * 16; c < tp * 16 + 16; c++)
            As[tr * 68 + c] = (Hs[tr * 68 + c] - mu) * rs * lg2[c] + lb2[c];
    }
#pragma unroll
    for (int it = 0; it < 4; it++) {
        int idx = tid + it * 256;
        int r = idx >> 4, c4 = (idx & 15) * 4;
        *(float4*)&Ws[r * 68 + c4] = *(const float4*)&W1[(size_t)r * 64 + c4];
    }
    __syncthreads();

    // ---- stage 3: FFN ----
    int tm = tid >> 4, tn = tid & 15;
    float ac1[4][4] = {};
#pragma unroll 8
    for (int kk = 0; kk < 64; kk++) {
        float4 bv = *(const float4*)&Ws[kk * 68 + tn * 4];
        float4 av = make_float4(As[(tm * 4 + 0) * 68 + kk], As[(tm * 4 + 1) * 68 + kk],
                                As[(tm * 4 + 2) * 68 + kk], As[(tm * 4 + 3) * 68 + kk]);
        FMA16(av, bv, ac1)
    }
    __syncthreads();
#pragma unroll
    for (int ii = 0; ii < 4; ii++)
#pragma unroll
        for (int jj = 0; jj < 4; jj++)
            As[(tm * 4 + ii) * 68 + tn * 4 + jj] = fmaxf(ac1[ii][jj] + b1[tn * 4 + jj], 0.f);
#pragma unroll
    for (int it = 0; it < 4; it++) {
        int idx = tid + it * 256;
        int r = idx >> 4, c4 = (idx & 15) * 4;
        *(float4*)&Ws[r * 68 + c4] = *(const float4*)&W2[(size_t)r * 64 + c4];
    }
    __syncthreads();
    float ac2[4][4] = {};
#pragma unroll 8
    for (int kk = 0; kk < 64; kk++) {
        float4 bv = *(const float4*)&Ws[kk * 68 + tn * 4];
        float4 av = make_float4(As[(tm * 4 + 0) * 68 + kk], As[(tm * 4 + 1) * 68 + kk],
                                As[(tm * 4 + 2) * 68 + kk], As[(tm * 4 + 3) * 68 + kk]);
        FMA16(av, bv, ac2)
    }
    __syncthreads();
#pragma unroll
    for (int ii = 0; ii < 4; ii++) {
        int r = row0 + tm * 4 + ii;
        int rl = tm * 4 + ii;
#pragma unroll
        for (int jj = 0; jj < 4; jj++) {
            int c = tn * 4 + jj;
            float vv = ac2[ii][jj] + b2[c] + Hs[rl * 68 + c];
            g_h[(size_t)r * 64 + c] = vv;
            hist[(size_t)r * 320 + c] = vv;
            As[rl * 68 + c] = vv;   // stage final h for next-layer LN
        }
    }
    if (lnn_g) {
        __syncthreads();
        ln64_smem(As, redA, lnn_g, lnn_b, (float*)g_xn, row0, tid);
    }
}

// ------------------------- scalar FFMA SGEMM (head) -------------------------
__global__ void __launch_bounds__(256) gemm_k(
    const float* __restrict__ A, const float* __restrict__ B, float* __restrict__ C,
    const float* __restrict__ bias, const float* __restrict__ resid,
    int M, int N, int K, int act)
{
    __shared__ float As[16][68];
    __shared__ float Bs[16][68];
    int tid = threadIdx.x;
    int row0 = blockIdx.x * 64, col0 = blockIdx.y * 64;
    int tm = tid >> 4, tn = tid & 15;
    int arow = tid >> 2, ac = tid & 3;
    int bk = tid >> 4, bn = tid & 15;
    float acc[4][4] = {};
    for (int k0 = 0; k0 < K; k0 += 16) {
        float4 a = *(const float4*)&A[(size_t)(row0 + arow) * K + k0 + ac * 4];
        As[ac * 4 + 0][arow] = a.x; As[ac * 4 + 1][arow] = a.y;
        As[ac * 4 + 2][arow] = a.z; As[ac * 4 + 3][arow] = a.w;
        int bcol = col0 + bn * 4;
        float4 bv = make_float4(0.f, 0.f, 0.f, 0.f);
        if (bcol < N) bv = *(const float4*)&B[(size_t)(k0 + bk) * N + bcol];
        *(float4*)&Bs[bk][bn * 4] = bv;
        __syncthreads();
#pragma unroll
        for (int kk = 0; kk < 16; kk++) {
            float4 av = *(const float4*)&As[kk][tm * 4];
            float4 bw = *(const float4*)&Bs[kk][tn * 4];
            FMA16(av, bw, acc)
        }
        __syncthreads();
    }
#pragma unroll
    for (int ii = 0; ii < 4; ii++) {
        int r = row0 + tm * 4 + ii;
#pragma unroll
        for (int jj = 0; jj < 4; jj++) {
            int ccol = col0 + tn * 4 + jj;
            if (ccol < N) {
                float vv = acc[ii][jj];
                if (bias) vv += bias[ccol];
                if (act == 1) vv = fmaxf(vv, 0.f);
                else if (act == 2) vv = tanhf(vv);
                if (resid) vv += resid[(size_t)r * N + ccol];
                C[(size_t)r * N + ccol] = vv;
            }
        }
    }
}

// ------------------------- LayerNorm 256 + tanh, warp per row -------------------------
__global__ void ln256w_k(const float* __restrict__ in, float* __restrict__ out,
                         const float* __restrict__ g, const float* __restrict__ b) {
    int w = threadIdx.x >> 5, lane = threadIdx.x & 31;
    int row = blockIdx.x * 8 + w;
    const float* xr = in + (size_t)row * 256;
    float x[8];
    float s = 0.f;
#pragma unroll
    for (int m = 0; m < 8; m++) { x[m] = xr[lane + 32 * m]; s += x[m]; }
    for (int o = 16; o; o >>= 1) s += __shfl_xor_sync(0xffffffffu, s, o);
    float mu = s * (1.0f / 256.0f);
    float vs = 0.f;
#pragma unroll
    for (int m = 0; m < 8; m++) { float d = x[m] - mu; vs += d * d; }
    for (int o = 16; o; o >>= 1) vs += __shfl_xor_sync(0xffffffffu, vs, o);
    float rs = rsqrtf(vs * (1.0f / 256.0f) + 1e-5f);
#pragma unroll
    for (int m = 0; m < 8; m++) {
        int c = lane + 32 * m;
        out[(size_t)row * 256 + c] = tanhf((x[m] - mu) * rs * g[c] + b[c]);
    }
}

// ------------------------- reductions + final projection -------------------------
__global__ void red1_k(const float* __restrict__ t) {
    __shared__ float sm[256];
    int blk = blockIdx.x, tid = threadIdx.x;
    int col = tid & 31, r0 = tid >> 5;
    float s = 0.f;
    for (int r = r0; r < 128; r += 8) s += t[(size_t)(blk * 128 + r) * 32 + col];
    sm[tid] = s;
    __syncthreads();
    for (int s2 = 4; s2; s2 >>= 1) {
        if (r0 < s2) sm[tid] += sm[tid + s2 * 32];
        __syncthreads();
    }
    if (r0 == 0) g_part[blk * 32 + col] = sm[col];
}

__global__ void red2_k(const float* __restrict__ pw, const float* __restrict__ pb,
                       float* __restrict__ out) {
    __shared__ float mean[32];
    int t = threadIdx.x;
    if (t < 32) {
        float s = 0.f;
        for (int b = 0; b < 128; b++) s += g_part[b * 32 + t];
        mean[t] = s * (1.0f / 16384.0f);
    }
    __syncthreads();
    if (t < 32) {
        float s = pb[t];
        for (int c = 0; c < 32; c++) s += mean[c] * pw[c * 32 + t];
        out[t] = s;
    }
}

// ------------------------- host orchestration -------------------------
extern "C" void kernel_launch(void* const* d_in, const int* in_sizes, int n_in,
                              void* d_out, int out_size)
{
    const float* x      = (const float*)d_in[0];
    const float* coords = (const float*)d_in[1];
    const float* regions= (const float*)d_in[3];
    const float* fe_w1  = (const float*)d_in[4];
    const float* fe_b1  = (const float*)d_in[5];
    const float* fe_w2  = (const float*)d_in[6];
    const float* fe_b2  = (const float*)d_in[7];
    const float* ln1_g  = (const float*)d_in[8];
    const float* ln1_b  = (const float*)d_in[9];
    const float* wq     = (const float*)d_in[10];
    const float* wk     = (const float*)d_in[11];
    const float* wv     = (const float*)d_in[12];
    const float* wrpe   = (const float*)d_in[13];
    const float* ow     = (const float*)d_in[14];
    const float* ob     = (const float*)d_in[15];
    const float* ln2_g  = (const float*)d_in[16];
    const float* ln2_b  = (const float*)d_in[17];
    const float* f1w    = (const float*)d_in[18];
    const float* f1b    = (const float*)d_in[19];
    const float* f2w    = (const float*)d_in[20];
    const float* f2b    = (const float*)d_in[21];
    const float* Wcat   = (const float*)d_in[22];
    const float* m1w    = (const float*)d_in[23];
    const float* m1b    = (const float*)d_in[24];
    const float* mlng   = (const float*)d_in[25];
    const float* mlnb   = (const float*)d_in[26];
    const float* m2w    = (const float*)d_in[27];
    const float* m2b    = (const float*)d_in[28];
    const float* pw     = (const float*)d_in[29];
    const float* pb     = (const float*)d_in[30];
    float* out = (float*)d_out;

    cudaFuncSetAttribute(epi_k, cudaFuncAttributeMaxDynamicSharedMemorySize, 52224);

    float *p_hist, *p_t0, *p_u, *p_u2, *p_t, *p_w2, *p_M, *p_G;
    int *p_rhist, *p_rbase, *p_bhist, *p_bbase;
    cudaGetSymbolAddress((void**)&p_hist, g_hist);
    cudaGetSymbolAddress((void**)&p_t0,   g_t0);
    cudaGetSymbolAddress((void**)&p_u,    g_u);
    cudaGetSymbolAddress((void**)&p_u2,   g_u2);
    cudaGetSymbolAddress((void**)&p_t,    g_t);
    cudaGetSymbolAddress((void**)&p_w2,   g_W2);
    cudaGetSymbolAddress((void**)&p_M,    g_M);
    cudaGetSymbolAddress((void**)&p_G,    g_G);
    cudaGetSymbolAddress((void**)&p_rhist, r_hist);
    cudaGetSymbolAddress((void**)&p_rbase, r_base);
    cudaGetSymbolAddress((void**)&p_bhist, b_hist);
    cudaGetSymbolAddress((void**)&p_bbase, b_base);

    const int M = NNODE;

    // ---- bucket ordering via counting sorts ----
    zero_k<<<512, 256>>>();
    rank_hist_k<<<dim3(64, 2), 256>>>(coords);
    scan_k<<<2, 1024>>>(p_rhist, p_rbase, NNODE, NNODE);
    rank_place_k<<<dim3(64, 2), 256>>>(coords);
    rank_rank_k<<<dim3(64, 2), 256>>>(coords);
    key1_k<<<dim3(64, 16), 256>>>(regions);
    key2_k<<<dim3(64, 16), 256>>>();
    scan_k<<<16, 1024>>>(p_bhist, p_bbase, KBINS, KBINS);
    bucket_place_k<<<dim3(64, 16), 256>>>();
    bucket_pos_k<<<dim3(64, 16), 256>>>();
    w2all_k<<<4, 128>>>(wrpe);
    mh_k<<<32, 256>>>(wq, wk);
    gw_k<<<32, 256>>>(wv, ow);

    // feat encoder + LN1(layer 0)
    ffe_k<<<256, 256>>>(x, fe_w1, fe_b1, fe_w2, fe_b2, ln1_g, ln1_b);

    for (int l = 0; l < 4; l++) {
        tq_k<<<dim3(256, 8), 256>>>(p_M + (size_t)l * 8 * 4096);
        attn_k<<<dim3(256, 8, 2), 256>>>(coords, p_w2 + l * 16);
        const float* nlg = (l < 3) ? (ln1_g + (l + 1) * 64) : nullptr;
        const float* nlb = (l < 3) ? (ln1_b + (l + 1) * 64) : nullptr;
        epi_k<<<256, 256, 52224>>>(p_G + (size_t)l * 8 * 4096, ob + l * 64,
                                   ln2_g + l * 64, ln2_b + l * 64,
                                   f1w + (size_t)l * 64 * 64, f1b + l * 64,
                                   f2w + (size_t)l * 64 * 64, f2b + l * 64,
                                   p_hist + (l + 1) * 64, nlg, nlb);
    }

    gemm_k<<<dim3(256, 1), 256>>>(p_hist, Wcat, p_t0, nullptr, nullptr, M, 32, 320, 2);
    gemm_k<<<dim3(256, 4), 256>>>(p_t0, m1w, p_u, m1b, nullptr, M, 256, 32, 0);
    ln256w_k<<<2048, 256>>>(p_u, p_u2, mlng, mlnb);
    gemm_k<<<dim3(256, 1), 256>>>(p_u2, m2w, p_t, m2b, p_t0, M, 32, 256, 0);
    red1_k<<<128, 256>>>(p_t);
    red2_k<<<1, 256>>>(pw, pb, out);
}

// round 13
// speedup vs baseline: 2.6719x; 1.0320x over previous
#include <cuda_runtime.h>
#include <cuda_bf16.h>
#include <math.h>

#define NNODE 16384
#define HEADS 8
#define DIM   64
#define HDIM  512
#define KBINS 40960

// ------------------------- device scratch (no allocs allowed) -------------------------
__device__ int   g_rank[2][NNODE];
__device__ int   g_order[16 * NNODE];
__device__ float g_h[NNODE * DIM];
__device__ float g_xn[NNODE * DIM];          // LN1(h), tf32-pre-rounded
__device__ float g_T[NNODE * HDIM];          // T = Xn @ M_h, tf32-pre-rounded
__device__ float g_hist[NNODE * 320];
__device__ float g_outr[16 * NNODE * DIM];   // R = P@X  [nh*8+h][node][d]
__device__ float g_lser[16 * NNODE];
__device__ float g_W2[4 * 16];               // [layer][h][c]
__device__ float g_M[4 * 8 * 64 * 64];       // [layer][head][d][e] = sum_c Wq[d,c]Wk[e,c]/8
__device__ float g_G[4 * 8 * 64 * 64];       // [layer][head][d][e] = Wv_h @ Ow_h (exact)
__device__ float g_t0[NNODE * 32];
__device__ float g_u [NNODE * 256];
__device__ float g_u2[NNODE * 256];
__device__ float g_t [NNODE * 32];
__device__ float g_part[128 * 32];

// sorting scratch
__device__ int r_hist[2][NNODE];
__device__ int r_base[2][NNODE];
__device__ int r_cnt [2][NNODE];
__device__ int r_slot[2][NNODE];
__device__ int b_keys[16][NNODE];
__device__ int b_hist[16][KBINS];
__device__ int b_base[16][KBINS];
__device__ int b_cnt [16][KBINS];
__device__ int b_slot[16][NNODE];

// ------------------------- tf32 / async helpers -------------------------
__device__ __forceinline__ unsigned f2tf(float f) {
    unsigned u;
    asm("cvt.rna.tf32.f32 %0, %1;" : "=r"(u) : "f"(f));
    return u;
}

__device__ __forceinline__ void mma_tf32(float c[4], unsigned a0, unsigned a1,
                                         unsigned a2, unsigned a3,
                                         unsigned b0, unsigned b1) {
    asm volatile(
        "mma.sync.aligned.m16n8k8.row.col.f32.tf32.tf32.f32 "
        "{%0,%1,%2,%3}, {%4,%5,%6,%7}, {%8,%9}, {%0,%1,%2,%3};"
        : "+f"(c[0]), "+f"(c[1]), "+f"(c[2]), "+f"(c[3])
        : "r"(a0), "r"(a1), "r"(a2), "r"(a3), "r"(b0), "r"(b1));
}

__device__ __forceinline__ void cp16(void* smem, const void* gmem) {
    unsigned sa = (unsigned)__cvta_generic_to_shared(smem);
    asm volatile("cp.async.cg.shared.global [%0], [%1], 16;" :: "r"(sa), "l"(gmem));
}
__device__ __forceinline__ void cp_commit_wait() {
    asm volatile("cp.async.commit_group;");
    asm volatile("cp.async.wait_group 0;");
}

// ------------------------- zero all counting scratch -------------------------
__global__ void zero_k() {
    int gid = blockIdx.x * 256 + threadIdx.x;
    int stride = gridDim.x * 256;
    for (int i = gid; i < 2 * NNODE; i += stride) { ((int*)r_hist)[i] = 0; ((int*)r_cnt)[i] = 0; }
    for (int i = gid; i < 16 * KBINS; i += stride) { ((int*)b_hist)[i] = 0; ((int*)b_cnt)[i] = 0; }
}

// ------------------------- coordinate ranks via counting -------------------------
__device__ __forceinline__ int coord_bin(float c) {
    int u = (int)(c * 16384.0f);
    return min(16383, max(0, u));
}

__global__ void rank_hist_k(const float* __restrict__ coords) {
    int axis = blockIdx.y;
    int i = blockIdx.x * 256 + threadIdx.x;
    int u = coord_bin(coords[i * 3 + axis]);
    atomicAdd(&r_hist[axis][u], 1);
}

__global__ void __launch_bounds__(1024) scan_k(const int* __restrict__ hist,
                                               int* __restrict__ base,
                                               int nbins, int rowstride) {
    __shared__ int ss[1024];
    int row = blockIdx.x;
    const int* h = hist + (size_t)row * rowstride;
    int* bs = base + (size_t)row * rowstride;
    int t = threadIdx.x;
    int chunk = (nbins + 1023) >> 10;
    int b0 = t * chunk;
    int s = 0;
    for (int m = 0; m < chunk; m++) { int idx = b0 + m; if (idx < nbins) s += h[idx]; }
    ss[t] = s;
    __syncthreads();
    for (int d = 1; d < 1024; d <<= 1) {
        int v = (t >= d) ? ss[t - d] : 0;
        __syncthreads();
        ss[t] += v;
        __syncthreads();
    }
    int run = (t > 0) ? ss[t - 1] : 0;
    for (int m = 0; m < chunk; m++) {
        int idx = b0 + m;
        if (idx < nbins) { bs[idx] = run; run += h[idx]; }
    }
}

__global__ void rank_place_k(const float* __restrict__ coords) {
    int axis = blockIdx.y;
    int i = blockIdx.x * 256 + threadIdx.x;
    int u = coord_bin(coords[i * 3 + axis]);
    int slot = r_base[axis][u] + atomicAdd(&r_cnt[axis][u], 1);
    r_slot[axis][slot] = i;
}

__global__ void rank_rank_k(const float* __restrict__ coords) {
    int axis = blockIdx.y;
    int i = blockIdx.x * 256 + threadIdx.x;
    float ci = coords[i * 3 + axis];
    int u = coord_bin(ci);
    int b = r_base[axis][u], n = r_hist[axis][u];
    int r = 0;
    for (int m = 0; m < n; m++) {
        int j = r_slot[axis][b + m];
        float cj = coords[j * 3 + axis];
        r += (int)((cj < ci) || (cj == ci && j < i));
    }
    g_rank[axis][i] = b + r;
}

// ------------------------- bucket keys (analytic bit width) + histogram -------------------------
__global__ void key_k(const float* __restrict__ regions) {
    int row = blockIdx.y;
    int nh = row >> 3, h = row & 7;
    float qe = 16384.0f / regions[nh * 16 + h];
    float qp = 16384.0f / regions[nh * 16 + 8 + h];
    // ranks are a permutation of 0..16383 and floor(r/qe) is monotone in r
    int maxre = (int)floorf(16383.0f / qe) + 1;
    int nb = (int)ceilf(log2f((float)maxre + 1.0f));
    int i = blockIdx.x * 256 + threadIdx.x;
    int re = (int)floorf((float)g_rank[0][i] / qe) + 1;
    int rp = (int)floorf((float)g_rank[1][i] / qp) + 1;
    int key = (rp << nb) | re;
    b_keys[row][i] = key;
    atomicAdd(&b_hist[row][key], 1);
}

__global__ void bucket_place_k() {
    int row = blockIdx.y;
    int i = blockIdx.x * 256 + threadIdx.x;
    int key = b_keys[row][i];
    int slot = b_base[row][key] + atomicAdd(&b_cnt[row][key], 1);
    b_slot[row][slot] = i;
}

__global__ void bucket_pos_k() {
    int row = blockIdx.y;
    int i = blockIdx.x * 256 + threadIdx.x;
    int key = b_keys[row][i];
    int b = b_base[row][key], n = b_hist[row][key];
    int r = 0;
    for (int m = 0; m < n; m++) r += (int)(b_slot[row][b + m] < i);
    g_order[row * NNODE + b + r] = i;
}

// ------------------------- RPE distance weights (all 4 layers) -------------------------
__global__ void w2all_k(const float* __restrict__ wrpe) {   // [4][512][16]
    __shared__ float sq[128];
    int l = blockIdx.x;
    const float* w = wrpe + (size_t)l * 512 * 16;
    int t = threadIdx.x;
    int h = t >> 4, m = t & 15;
    float s = 0.f;
    for (int d = 0; d < 64; d++) s += w[(h * 64 + d) * 16 + m];
    float om = s * (1.0f / 64.0f);
    sq[t] = om * om;
    __syncthreads();
    if (t < 16) {
        int hh = t >> 1, c = t & 1;
        float ww = 0.f;
        for (int kk = 0; kk < 8; kk++) ww += sq[hh * 16 + c * 8 + kk];
        g_W2[l * 16 + t] = ww;
    }
}

// ------------------------- M_h[d][e] = sum_c Wq[d,c] Wk[e,c] / 8 (exact fp32, NT) -------------------------
#define FMA16(av, bv, acc)                                                         \
    acc[0][0]+=av.x*bv.x; acc[0][1]+=av.x*bv.y; acc[0][2]+=av.x*bv.z; acc[0][3]+=av.x*bv.w; \
    acc[1][0]+=av.y*bv.x; acc[1][1]+=av.y*bv.y; acc[1][2]+=av.y*bv.z; acc[1][3]+=av.y*bv.w; \
    acc[2][0]+=av.z*bv.x; acc[2][1]+=av.z*bv.y; acc[2][2]+=av.z*bv.z; acc[2][3]+=av.z*bv.w; \
    acc[3][0]+=av.w*bv.x; acc[3][1]+=av.w*bv.y; acc[3][2]+=av.w*bv.z; acc[3][3]+=av.w*bv.w;

__global__ void __launch_bounds__(256) mh_k(const float* __restrict__ wq,
                                            const float* __restrict__ wk) {
    __shared__ float Aq[64 * 68];   // [d][c]
    __shared__ float Bk[64 * 68];   // [e][c]
    int bx = blockIdx.x;            // l*8 + h
    int l = bx >> 3, h = bx & 7;
    int tid = threadIdx.x;
#pragma unroll
    for (int it = 0; it < 4; it++) {
        int idx = tid + it * 256;
        int d = idx >> 4, c4 = (idx & 15) * 4;
        *(float4*)&Aq[d * 68 + c4] = *(const float4*)&wq[((size_t)(l * 64 + d)) * 512 + h * 64 + c4];
        *(float4*)&Bk[d * 68 + c4] = *(const float4*)&wk[((size_t)(l * 64 + d)) * 512 + h * 64 + c4];
    }
    __syncthreads();
    int tm = tid >> 4, tn = tid & 15;
    float acc[4][4] = {};
#pragma unroll 4
    for (int c = 0; c < 64; c++) {
        float4 av = make_float4(Aq[(tm * 4 + 0) * 68 + c], Aq[(tm * 4 + 1) * 68 + c],
                                Aq[(tm * 4 + 2) * 68 + c], Aq[(tm * 4 + 3) * 68 + c]);
        float4 bv = make_float4(Bk[(tn * 4 + 0) * 68 + c], Bk[(tn * 4 + 1) * 68 + c],
                                Bk[(tn * 4 + 2) * 68 + c], Bk[(tn * 4 + 3) * 68 + c]);
        FMA16(av, bv, acc)
    }
#pragma unroll
    for (int ii = 0; ii < 4; ii++)
#pragma unroll
        for (int jj = 0; jj < 4; jj++)
            g_M[(size_t)bx * 4096 + (tm * 4 + ii) * 64 + tn * 4 + jj] = 0.125f * acc[ii][jj];
}

// ------------------------- G_h = Wv_h @ Ow_h (exact, NN) -------------------------
__global__ void __launch_bounds__(256) gw_k(const float* __restrict__ wv,
                                            const float* __restrict__ ow) {
    __shared__ float Av[64 * 68];   // [d][c]
    __shared__ float Bo[64 * 68];   // [c][e]
    int bx = blockIdx.x;            // l*8 + h
    int l = bx >> 3, h = bx & 7;
    int tid = threadIdx.x;
#pragma unroll
    for (int it = 0; it < 4; it++) {
        int idx = tid + it * 256;
        int r = idx >> 4, c4 = (idx & 15) * 4;
        *(float4*)&Av[r * 68 + c4] = *(const float4*)&wv[((size_t)(l * 64 + r)) * 512 + h * 64 + c4];
        *(float4*)&Bo[r * 68 + c4] = *(const float4*)&ow[((size_t)(l * 512 + h * 64 + r)) * 64 + c4];
    }
    __syncthreads();
    int tm = tid >> 4, tn = tid & 15;
    float acc[4][4] = {};
#pragma unroll 4
    for (int c = 0; c < 64; c++) {
        float4 av = make_float4(Av[(tm * 4 + 0) * 68 + c], Av[(tm * 4 + 1) * 68 + c],
                                Av[(tm * 4 + 2) * 68 + c], Av[(tm * 4 + 3) * 68 + c]);
        float4 bv = *(const float4*)&Bo[c * 68 + tn * 4];
        FMA16(av, bv, acc)
    }
#pragma unroll
    for (int ii = 0; ii < 4; ii++)
#pragma unroll
        for (int jj = 0; jj < 4; jj++)
            g_G[(size_t)bx * 4096 + (tm * 4 + ii) * 64 + tn * 4 + jj] = acc[ii][jj];
}

// ------------------------- shared LN helper; writes tf32-pre-rounded output -------------------------
__device__ __forceinline__ void ln64_smem(const float* Xs, float (*redA)[4],
                                          const float* g, const float* b,
                                          float* dst, int row0, int tid) {
    int tr = tid >> 2, tp = tid & 3;
    float s = 0.f;
    for (int c = tp * 16; c < tp * 16 + 16; c++) s += Xs[tr * 68 + c];
    redA[tr][tp] = s;
    __syncthreads();
    float mu = (redA[tr][0] + redA[tr][1] + redA[tr][2] + redA[tr][3]) * (1.0f / 64.0f);
    __syncthreads();
    float vs = 0.f;
    for (int c = tp * 16; c < tp * 16 + 16; c++) {
        float d = Xs[tr * 68 + c] - mu;
        vs += d * d;
    }
    redA[tr][tp] = vs;
    __syncthreads();
    float var = (redA[tr][0] + redA[tr][1] + redA[tr][2] + redA[tr][3]) * (1.0f / 64.0f);
    float rs = rsqrtf(var + 1e-5f);
    for (int c = tp * 16; c < tp * 16 + 16; c++) {
        float vv = (Xs[tr * 68 + c] - mu) * rs * g[c] + b[c];
        dst[(size_t)(row0 + tr) * 64 + c] = __uint_as_float(f2tf(vv));
    }
}

// ------------------------- fused feat encoder + LN1(layer0) (exact FFMA) -------------------------
__global__ void __launch_bounds__(256) ffe_k(
    const float* __restrict__ x,
    const float* __restrict__ W1, const float* __restrict__ b1,
    const float* __restrict__ W2, const float* __restrict__ b2,
    const float* __restrict__ lng, const float* __restrict__ lnb)
{
    __shared__ float Xs16[64 * 17];
    __shared__ float W1s[16 * 68];
    __shared__ float Ts[64 * 68];
    __shared__ float W2s[64 * 68];
    __shared__ float redA[64][4];
    int tid = threadIdx.x;
    int row0 = blockIdx.x * 64;
    {
        int r = tid >> 2, c4 = (tid & 3) * 4;
        float4 xv = *(const float4*)&x[(size_t)(row0 + r) * 16 + c4];
        Xs16[r * 17 + c4 + 0] = xv.x; Xs16[r * 17 + c4 + 1] = xv.y;
        Xs16[r * 17 + c4 + 2] = xv.z; Xs16[r * 17 + c4 + 3] = xv.w;
    }
    if (tid < 16 * 16) {
        int r = tid >> 4, c4 = (tid & 15) * 4;
        *(float4*)&W1s[r * 68 + c4] = *(const float4*)&W1[(size_t)r * 64 + c4];
    }
#pragma unroll
    for (int it = 0; it < 4; it++) {
        int idx = tid + it * 256;
        int r = idx >> 4, c4 = (idx & 15) * 4;
        *(float4*)&W2s[r * 68 + c4] = *(const float4*)&W2[(size_t)r * 64 + c4];
    }
    __syncthreads();
    int tm = tid >> 4, tn = tid & 15;
    float acc[4][4] = {};
#pragma unroll
    for (int kk = 0; kk < 16; kk++) {
        float4 av = make_float4(Xs16[(tm * 4 + 0) * 17 + kk], Xs16[(tm * 4 + 1) * 17 + kk],
                                Xs16[(tm * 4 + 2) * 17 + kk], Xs16[(tm * 4 + 3) * 17 + kk]);
        float4 bv = *(const float4*)&W1s[kk * 68 + tn * 4];
        FMA16(av, bv, acc)
    }
#pragma unroll
    for (int ii = 0; ii < 4; ii++)
#pragma unroll
        for (int jj = 0; jj < 4; jj++)
            Ts[(tm * 4 + ii) * 68 + tn * 4 + jj] = fmaxf(acc[ii][jj] + b1[tn * 4 + jj], 0.f);
    __syncthreads();
    float acc2[4][4] = {};
#pragma unroll 8
    for (int kk = 0; kk < 64; kk++) {
        float4 av = make_float4(Ts[(tm * 4 + 0) * 68 + kk], Ts[(tm * 4 + 1) * 68 + kk],
                                Ts[(tm * 4 + 2) * 68 + kk], Ts[(tm * 4 + 3) * 68 + kk]);
        float4 bv = *(const float4*)&W2s[kk * 68 + tn * 4];
        FMA16(av, bv, acc2)
    }
    __syncthreads();
#pragma unroll
    for (int ii = 0; ii < 4; ii++) {
        int r = row0 + tm * 4 + ii;
#pragma unroll
        for (int jj = 0; jj < 4; jj++) {
            int c = tn * 4 + jj;
            float vv = acc2[ii][jj] + b2[c];
            g_h[(size_t)r * 64 + c] = vv;
            g_hist[(size_t)r * 320 + c] = vv;
            W2s[(tm * 4 + ii) * 68 + c] = vv;   // stage for LN
        }
    }
    __syncthreads();
    ln64_smem(W2s, redA, lng, lnb, (float*)g_xn, row0, tid);
}

// ------------------------- T = Xn @ M_h  (all nodes, per head), pre-rounded output -------------------------
__global__ void __launch_bounds__(256) tq_k(const float* __restrict__ Mbase) {
    __shared__ unsigned As[64 * 68];
    __shared__ unsigned Bs[64 * 68];
    int tid = threadIdx.x;
    int row0 = blockIdx.x * 64, h = blockIdx.y;
    const float* Mg = Mbase + (size_t)h * 4096;
#pragma unroll
    for (int it = 0; it < 4; it++) {
        int idx = tid + it * 256;
        int r = idx >> 4, c4 = (idx & 15) * 4;
        cp16(&As[r * 68 + c4], &g_xn[(size_t)(row0 + r) * 64 + c4]);   // pre-rounded
        float4 bv = *(const float4*)&Mg[r * 64 + c4];
        Bs[r * 68 + c4 + 0] = f2tf(bv.x); Bs[r * 68 + c4 + 1] = f2tf(bv.y);
        Bs[r * 68 + c4 + 2] = f2tf(bv.z); Bs[r * 68 + c4 + 3] = f2tf(bv.w);
    }
    cp_commit_wait();
    __syncthreads();
    int wid = tid >> 5, lane = tid & 31;
    int g = lane >> 2, t = lane & 3;
    int r0 = (wid & 3) * 16, c0 = (wid >> 2) * 32;
    float acc[4][4] = {};
#pragma unroll
    for (int ks = 0; ks < 8; ks++) {
        int k0 = ks * 8;
        unsigned a0 = As[(r0 + g) * 68 + k0 + t];
        unsigned a1 = As[(r0 + g + 8) * 68 + k0 + t];
        unsigned a2 = As[(r0 + g) * 68 + k0 + t + 4];
        unsigned a3 = As[(r0 + g + 8) * 68 + k0 + t + 4];
#pragma unroll
        for (int nt = 0; nt < 4; nt++) {
            int n = c0 + nt * 8 + g;
            unsigned b0 = Bs[(k0 + t) * 68 + n];
            unsigned b1 = Bs[(k0 + t + 4) * 68 + n];
            mma_tf32(acc[nt], a0, a1, a2, a3, b0, b1);
        }
    }
#pragma unroll
    for (int nt = 0; nt < 4; nt++)
#pragma unroll
        for (int cr = 0; cr < 4; cr++) {
            int r = row0 + r0 + g + (cr >> 1) * 8;
            int c = c0 + nt * 8 + 2 * t + (cr & 1);
            g_T[(size_t)r * 512 + h * 64 + c] = __uint_as_float(f2tf(acc[nt][cr]));
        }
}

// ------------------------- attention: cp.async tf32 gathers, 2 smem buffers -------------------------
__global__ void __launch_bounds__(256) attn_k(
    const float* __restrict__ coords, const float* __restrict__ W2row)
{
    __shared__ unsigned Xs[64 * 68];   // X tf32
    __shared__ unsigned Ts[64 * 68];   // T tf32 -> S float / P tf32 [j][i]
    __shared__ int   nd[64];
    __shared__ float cx[64], cy[64], redm[4][64], reds[4][64];

    int tid = threadIdx.x;
    int blk = blockIdx.x, h = blockIdx.y, nh = blockIdx.z;
    int row = nh * 8 + h;
    const int* ord = g_order + row * NNODE + blk * 64;
    if (tid < 64) {
        int nn = ord[tid];
        nd[tid] = nn;
        cx[tid] = coords[nn * 3 + 0];
        cy[tid] = coords[nn * 3 + 1];
    }
    __syncthreads();

    // gather pre-rounded X and T rows via cp.async (no register round-trip)
#pragma unroll
    for (int it = 0; it < 4; it++) {
        int idx = tid + it * 256;               // 0..1023
        int i = idx >> 4, q = (idx & 15) * 4;
        size_t nb = (size_t)nd[i];
        cp16(&Xs[i * 68 + q], &g_xn[nb * 64 + q]);
        cp16(&Ts[i * 68 + q], &g_T[nb * 512 + h * 64 + q]);
    }
    cp_commit_wait();
    __syncthreads();

    int wid = tid >> 5, lane = tid & 31;
    int g = lane >> 2, t = lane & 3;
    int r0 = (wid & 3) * 16, c0 = (wid >> 2) * 32;

    // S = T @ X^T (+RPE) in registers
    float acc[4][4] = {};
#pragma unroll
    for (int ks = 0; ks < 8; ks++) {
        int k0 = ks * 8;
        unsigned a0 = Ts[(r0 + g) * 68 + k0 + t];
        unsigned a1 = Ts[(r0 + g + 8) * 68 + k0 + t];
        unsigned a2 = Ts[(r0 + g) * 68 + k0 + t + 4];
        unsigned a3 = Ts[(r0 + g + 8) * 68 + k0 + t + 4];
#pragma unroll
        for (int nt = 0; nt < 4; nt++) {
            int j = c0 + nt * 8 + g;
            unsigned b0 = Xs[j * 68 + k0 + t];
            unsigned b1 = Xs[j * 68 + k0 + t + 4];
            mma_tf32(acc[nt], a0, a1, a2, a3, b0, b1);
        }
    }
    float W0 = W2row[h * 2 + 0], W1 = W2row[h * 2 + 1];
    __syncthreads();   // all reads of Ts done; reuse as S

    float* Sf = (float*)Ts;
#pragma unroll
    for (int nt = 0; nt < 4; nt++) {
        int j0 = c0 + nt * 8 + 2 * t;
#pragma unroll
        for (int cr = 0; cr < 4; cr++) {
            int i = r0 + g + (cr >> 1) * 8;
            int j = j0 + (cr & 1);
            float dx = cx[i] - cx[j], dy = cy[i] - cy[j];
            Sf[j * 68 + i] = acc[nt][cr] - W0 * dx * dx - W1 * dy * dy;
        }
    }
    __syncthreads();

    // softmax over j per query i (layout [j][i])
    int ci = tid & 63, seg = tid >> 6;
    float ml = -3.0e38f;
#pragma unroll
    for (int jj = 0; jj < 16; jj++) ml = fmaxf(ml, Sf[(seg * 16 + jj) * 68 + ci]);
    redm[seg][ci] = ml;
    __syncthreads();
    float mm = fmaxf(fmaxf(redm[0][ci], redm[1][ci]), fmaxf(redm[2][ci], redm[3][ci]));
    float ev[16];
    float sl = 0.f;
#pragma unroll
    for (int jj = 0; jj < 16; jj++) {
        float e = __expf(Sf[(seg * 16 + jj) * 68 + ci] - mm);
        ev[jj] = e;
        sl += e;
    }
    reds[seg][ci] = sl;
    __syncthreads();
    float ssum = reds[0][ci] + reds[1][ci] + reds[2][ci] + reds[3][ci];
    float inv = 1.0f / ssum;
    if (seg == 0) g_lser[row * NNODE + nd[ci]] = mm + __logf(ssum);
    unsigned* Ps = Ts;
#pragma unroll
    for (int jj = 0; jj < 16; jj++)
        Ps[(seg * 16 + jj) * 68 + ci] = f2tf(ev[jj] * inv);
    __syncthreads();

    // R = P @ X  (P stored transposed [j][i]); store straight to gmem
    float racc[4][4] = {};
#pragma unroll
    for (int ks = 0; ks < 8; ks++) {
        int k0 = ks * 8;
        unsigned a0 = Ps[(k0 + t) * 68 + r0 + g];
        unsigned a1 = Ps[(k0 + t) * 68 + r0 + g + 8];
        unsigned a2 = Ps[(k0 + t + 4) * 68 + r0 + g];
        unsigned a3 = Ps[(k0 + t + 4) * 68 + r0 + g + 8];
#pragma unroll
        for (int nt = 0; nt < 4; nt++) {
            int n = c0 + nt * 8 + g;
            unsigned b0 = Xs[(k0 + t) * 68 + n];
            unsigned b1 = Xs[(k0 + t + 4) * 68 + n];
            mma_tf32(racc[nt], a0, a1, a2, a3, b0, b1);
        }
    }
#pragma unroll
    for (int nt = 0; nt < 4; nt++) {
        int d0 = c0 + nt * 8 + 2 * t;
        int iA = r0 + g, iB = r0 + g + 8;
        *(float2*)&g_outr[((size_t)row * NNODE + nd[iA]) * 64 + d0] =
            make_float2(racc[nt][0], racc[nt][1]);
        *(float2*)&g_outr[((size_t)row * NNODE + nd[iB]) * 64 + d0] =
            make_float2(racc[nt][2], racc[nt][3]);
    }
}

// ------------------------- fused epilogue: outproj + LN2 + FFN + resid + hist + LN1(next) ----------
// dynamic smem: AsU[64*68] u32 | BsU[64*68] u32 | Hs[64*68] f32  (52224 bytes)
__global__ void __launch_bounds__(256) epi_k(
    const float* __restrict__ gG, const float* __restrict__ ob,
    const float* __restrict__ lg2, const float* __restrict__ lb2,
    const float* __restrict__ W1, const float* __restrict__ b1,
    const float* __restrict__ W2, const float* __restrict__ b2,
    float* __restrict__ hist,
    const float* __restrict__ lnn_g, const float* __restrict__ lnn_b)
{
    extern __shared__ unsigned dyn[];
    unsigned* AsU = dyn;
    unsigned* BsU = dyn + 64 * 68;
    float*    Hs  = (float*)(dyn + 2 * 64 * 68);
    __shared__ float redA[64][4];
    __shared__ float w0s[64], w1s[64];
    float* As = (float*)AsU;
    float* Ws = (float*)BsU;
    int tid = threadIdx.x;
    int row0 = blockIdx.x * 64;
    int wid = tid >> 5, lane = tid & 31;
    int g = lane >> 2, t = lane & 3;
    int r0 = (wid & 3) * 16, c0 = (wid >> 2) * 32;

    // ---- stage 1: out-projection with fused lse-combine over 8 heads ----
    float acc[4][4] = {};
    for (int h = 0; h < 8; h++) {
        __syncthreads();
        if (tid < 64) {
            int node = row0 + tid;
            float l0 = g_lser[h * NNODE + node];
            float l1 = g_lser[(8 + h) * NNODE + node];
            float m = fmaxf(l0, l1);
            float e0 = __expf(l0 - m), e1 = __expf(l1 - m);
            float inv = 1.0f / (e0 + e1);
            w0s[tid] = e0 * inv;
            w1s[tid] = e1 * inv;
        }
        __syncthreads();
#pragma unroll
        for (int it = 0; it < 4; it++) {
            int idx = tid + it * 256;
            int r = idx >> 4, c4 = (idx & 15) * 4;
            int node = row0 + r;
            float4 o0 = *(const float4*)&g_outr[((size_t)h * NNODE + node) * 64 + c4];
            float4 o1 = *(const float4*)&g_outr[((size_t)(8 + h) * NNODE + node) * 64 + c4];
            float w0 = w0s[r], w1 = w1s[r];
            AsU[r * 68 + c4 + 0] = f2tf(w0 * o0.x + w1 * o1.x);
            AsU[r * 68 + c4 + 1] = f2tf(w0 * o0.y + w1 * o1.y);
            AsU[r * 68 + c4 + 2] = f2tf(w0 * o0.z + w1 * o1.z);
            AsU[r * 68 + c4 + 3] = f2tf(w0 * o0.w + w1 * o1.w);
            float4 bv = *(const float4*)&gG[(size_t)h * 4096 + r * 64 + c4];
            BsU[r * 68 + c4 + 0] = f2tf(bv.x); BsU[r * 68 + c4 + 1] = f2tf(bv.y);
            BsU[r * 68 + c4 + 2] = f2tf(bv.z); BsU[r * 68 + c4 + 3] = f2tf(bv.w);
        }
        __syncthreads();
#pragma unroll
        for (int ks = 0; ks < 8; ks++) {
            int k0 = ks * 8;
            unsigned a0 = AsU[(r0 + g) * 68 + k0 + t];
            unsigned a1 = AsU[(r0 + g + 8) * 68 + k0 + t];
            unsigned a2 = AsU[(r0 + g) * 68 + k0 + t + 4];
            unsigned a3 = AsU[(r0 + g + 8) * 68 + k0 + t + 4];
#pragma unroll
            for (int nt = 0; nt < 4; nt++) {
                int n = c0 + nt * 8 + g;
                unsigned b0 = BsU[(k0 + t) * 68 + n];
                unsigned b1 = BsU[(k0 + t + 4) * 68 + n];
                mma_tf32(acc[nt], a0, a1, a2, a3, b0, b1);
            }
        }
    }
    __syncthreads();
#pragma unroll
    for (int nt = 0; nt < 4; nt++) {
#pragma unroll
        for (int cr = 0; cr < 4; cr++) {
            int rl = r0 + g + (cr >> 1) * 8;
            int ccol = c0 + nt * 8 + 2 * t + (cr & 1);
            Hs[rl * 68 + ccol] = acc[nt][cr] + ob[ccol] + g_h[(size_t)(row0 + rl) * 64 + ccol];
        }
    }
    __syncthreads();

    // ---- stage 2: LN2 (Hs -> As) + load W1 ----
    {
        int tr = tid >> 2, tp = tid & 3;
        float s = 0.f;
        for (int c = tp * 16; c < tp * 16 + 16; c++) s += Hs[tr * 68 + c];
        redA[tr][tp] = s;
        __syncthreads();
        float mu = (redA[tr][0] + redA[tr][1] + redA[tr][2] + redA[tr][3]) * (1.0f / 64.0f);
        __syncthreads();
        float vs = 0.f;
        for (int c = tp * 16; c < tp * 16 + 16; c++) {
            float d = Hs[tr * 68 + c] - mu;
            vs += d * d;
        }
        redA[tr][tp] = vs;
        __syncthreads();
        float var = (redA[tr][0] + redA[tr][1] + redA[tr][2] + redA[tr][3]) * (1.0f / 64.0f);
        float rs = rsqrtf(var + 1e-5f);
        for (int c = tp * 16; c < tp * 16 + 16; c++)
            As[tr * 68 + c] = (Hs[tr * 68 + c] - mu) * rs * lg2[c] + lb2[c];
    }
#pragma unroll
    for (int it = 0; it < 4; it++) {
        int idx = tid + it * 256;
        int r = idx >> 4, c4 = (idx & 15) * 4;
        *(float4*)&Ws[r * 68 + c4] = *(const float4*)&W1[(size_t)r * 64 + c4];
    }
    __syncthreads();

    // ---- stage 3: FFN ----
    int tm = tid >> 4, tn = tid & 15;
    float ac1[4][4] = {};
#pragma unroll 8
    for (int kk = 0; kk < 64; kk++) {
        float4 bv = *(const float4*)&Ws[kk * 68 + tn * 4];
        float4 av = make_float4(As[(tm * 4 + 0) * 68 + kk], As[(tm * 4 + 1) * 68 + kk],
                                As[(tm * 4 + 2) * 68 + kk], As[(tm * 4 + 3) * 68 + kk]);
        FMA16(av, bv, ac1)
    }
    __syncthreads();
#pragma unroll
    for (int ii = 0; ii < 4; ii++)
#pragma unroll
        for (int jj = 0; jj < 4; jj++)
            As[(tm * 4 + ii) * 68 + tn * 4 + jj] = fmaxf(ac1[ii][jj] + b1[tn * 4 + jj], 0.f);
#pragma unroll
    for (int it = 0; it < 4; it++) {
        int idx = tid + it * 256;
        int r = idx >> 4, c4 = (idx & 15) * 4;
        *(float4*)&Ws[r * 68 + c4] = *(const float4*)&W2[(size_t)r * 64 + c4];
    }
    __syncthreads();
    float ac2[4][4] = {};
#pragma unroll 8
    for (int kk = 0; kk < 64; kk++) {
        float4 bv = *(const float4*)&Ws[kk * 68 + tn * 4];
        float4 av = make_float4(As[(tm * 4 + 0) * 68 + kk], As[(tm * 4 + 1) * 68 + kk],
                                As[(tm * 4 + 2) * 68 + kk], As[(tm * 4 + 3) * 68 + kk]);
        FMA16(av, bv, ac2)
    }
    __syncthreads();
#pragma unroll
    for (int ii = 0; ii < 4; ii++) {
        int r = row0 + tm * 4 + ii;
        int rl = tm * 4 + ii;
#pragma unroll
        for (int jj = 0; jj < 4; jj++) {
            int c = tn * 4 + jj;
            float vv = ac2[ii][jj] + b2[c] + Hs[rl * 68 + c];
            g_h[(size_t)r * 64 + c] = vv;
            hist[(size_t)r * 320 + c] = vv;
            As[rl * 68 + c] = vv;   // stage final h for next-layer LN
        }
    }
    if (lnn_g) {
        __syncthreads();
        ln64_smem(As, redA, lnn_g, lnn_b, (float*)g_xn, row0, tid);
    }
}

// ------------------------- scalar FFMA SGEMM (head) -------------------------
__global__ void __launch_bounds__(256) gemm_k(
    const float* __restrict__ A, const float* __restrict__ B, float* __restrict__ C,
    const float* __restrict__ bias, const float* __restrict__ resid,
    int M, int N, int K, int act)
{
    __shared__ float As[16][68];
    __shared__ float Bs[16][68];
    int tid = threadIdx.x;
    int row0 = blockIdx.x * 64, col0 = blockIdx.y * 64;
    int tm = tid >> 4, tn = tid & 15;
    int arow = tid >> 2, ac = tid & 3;
    int bk = tid >> 4, bn = tid & 15;
    float acc[4][4] = {};
    for (int k0 = 0; k0 < K; k0 += 16) {
        float4 a = *(const float4*)&A[(size_t)(row0 + arow) * K + k0 + ac * 4];
        As[ac * 4 + 0][arow] = a.x; As[ac * 4 + 1][arow] = a.y;
        As[ac * 4 + 2][arow] = a.z; As[ac * 4 + 3][arow] = a.w;
        int bcol = col0 + bn * 4;
        float4 bv = make_float4(0.f, 0.f, 0.f, 0.f);
        if (bcol < N) bv = *(const float4*)&B[(size_t)(k0 + bk) * N + bcol];
        *(float4*)&Bs[bk][bn * 4] = bv;
        __syncthreads();
#pragma unroll
        for (int kk = 0; kk < 16; kk++) {
            float4 av = *(const float4*)&As[kk][tm * 4];
            float4 bw = *(const float4*)&Bs[kk][tn * 4];
            FMA16(av, bw, acc)
        }
        __syncthreads();
    }
#pragma unroll
    for (int ii = 0; ii < 4; ii++) {
        int r = row0 + tm * 4 + ii;
#pragma unroll
        for (int jj = 0; jj < 4; jj++) {
            int ccol = col0 + tn * 4 + jj;
            if (ccol < N) {
                float vv = acc[ii][jj];
                if (bias) vv += bias[ccol];
                if (act == 1) vv = fmaxf(vv, 0.f);
                else if (act == 2) vv = tanhf(vv);
                if (resid) vv += resid[(size_t)r * N + ccol];
                C[(size_t)r * N + ccol] = vv;
            }
        }
    }
}

// ------------------------- LayerNorm 256 + tanh, warp per row -------------------------
__global__ void ln256w_k(const float* __restrict__ in, float* __restrict__ out,
                         const float* __restrict__ g, const float* __restrict__ b) {
    int w = threadIdx.x >> 5, lane = threadIdx.x & 31;
    int row = blockIdx.x * 8 + w;
    const float* xr = in + (size_t)row * 256;
    float x[8];
    float s = 0.f;
#pragma unroll
    for (int m = 0; m < 8; m++) { x[m] = xr[lane + 32 * m]; s += x[m]; }
    for (int o = 16; o; o >>= 1) s += __shfl_xor_sync(0xffffffffu, s, o);
    float mu = s * (1.0f / 256.0f);
    float vs = 0.f;
#pragma unroll
    for (int m = 0; m < 8; m++) { float d = x[m] - mu; vs += d * d; }
    for (int o = 16; o; o >>= 1) vs += __shfl_xor_sync(0xffffffffu, vs, o);
    float rs = rsqrtf(vs * (1.0f / 256.0f) + 1e-5f);
#pragma unroll
    for (int m = 0; m < 8; m++) {
        int c = lane + 32 * m;
        out[(size_t)row * 256 + c] = tanhf((x[m] - mu) * rs * g[c] + b[c]);
    }
}

// ------------------------- reductions + final projection -------------------------
__global__ void red1_k(const float* __restrict__ t) {
    __shared__ float sm[256];
    int blk = blockIdx.x, tid = threadIdx.x;
    int col = tid & 31, r0 = tid >> 5;
    float s = 0.f;
    for (int r = r0; r < 128; r += 8) s += t[(size_t)(blk * 128 + r) * 32 + col];
    sm[tid] = s;
    __syncthreads();
    for (int s2 = 4; s2; s2 >>= 1) {
        if (r0 < s2) sm[tid] += sm[tid + s2 * 32];
        __syncthreads();
    }
    if (r0 == 0) g_part[blk * 32 + col] = sm[col];
}

__global__ void red2_k(const float* __restrict__ pw, const float* __restrict__ pb,
                       float* __restrict__ out) {
    __shared__ float mean[32];
    int t = threadIdx.x;
    if (t < 32) {
        float s = 0.f;
        for (int b = 0; b < 128; b++) s += g_part[b * 32 + t];
        mean[t] = s * (1.0f / 16384.0f);
    }
    __syncthreads();
    if (t < 32) {
        float s = pb[t];
        for (int c = 0; c < 32; c++) s += mean[c] * pw[c * 32 + t];
        out[t] = s;
    }
}

// ------------------------- host orchestration -------------------------
extern "C" void kernel_launch(void* const* d_in, const int* in_sizes, int n_in,
                              void* d_out, int out_size)
{
    const float* x      = (const float*)d_in[0];
    const float* coords = (const float*)d_in[1];
    const float* regions= (const float*)d_in[3];
    const float* fe_w1  = (const float*)d_in[4];
    const float* fe_b1  = (const float*)d_in[5];
    const float* fe_w2  = (const float*)d_in[6];
    const float* fe_b2  = (const float*)d_in[7];
    const float* ln1_g  = (const float*)d_in[8];
    const float* ln1_b  = (const float*)d_in[9];
    const float* wq     = (const float*)d_in[10];
    const float* wk     = (const float*)d_in[11];
    const float* wv     = (const float*)d_in[12];
    const float* wrpe   = (const float*)d_in[13];
    const float* ow     = (const float*)d_in[14];
    const float* ob     = (const float*)d_in[15];
    const float* ln2_g  = (const float*)d_in[16];
    const float* ln2_b  = (const float*)d_in[17];
    const float* f1w    = (const float*)d_in[18];
    const float* f1b    = (const float*)d_in[19];
    const float* f2w    = (const float*)d_in[20];
    const float* f2b    = (const float*)d_in[21];
    const float* Wcat   = (const float*)d_in[22];
    const float* m1w    = (const float*)d_in[23];
    const float* m1b    = (const float*)d_in[24];
    const float* mlng   = (const float*)d_in[25];
    const float* mlnb   = (const float*)d_in[26];
    const float* m2w    = (const float*)d_in[27];
    const float* m2b    = (const float*)d_in[28];
    const float* pw     = (const float*)d_in[29];
    const float* pb     = (const float*)d_in[30];
    float* out = (float*)d_out;

    cudaFuncSetAttribute(epi_k, cudaFuncAttributeMaxDynamicSharedMemorySize, 52224);

    float *p_hist, *p_t0, *p_u, *p_u2, *p_t, *p_w2, *p_M, *p_G;
    int *p_rhist, *p_rbase, *p_bhist, *p_bbase;
    cudaGetSymbolAddress((void**)&p_hist, g_hist);
    cudaGetSymbolAddress((void**)&p_t0,   g_t0);
    cudaGetSymbolAddress((void**)&p_u,    g_u);
    cudaGetSymbolAddress((void**)&p_u2,   g_u2);
    cudaGetSymbolAddress((void**)&p_t,    g_t);
    cudaGetSymbolAddress((void**)&p_w2,   g_W2);
    cudaGetSymbolAddress((void**)&p_M,    g_M);
    cudaGetSymbolAddress((void**)&p_G,    g_G);
    cudaGetSymbolAddress((void**)&p_rhist, r_hist);
    cudaGetSymbolAddress((void**)&p_rbase, r_base);
    cudaGetSymbolAddress((void**)&p_bhist, b_hist);
    cudaGetSymbolAddress((void**)&p_bbase, b_base);

    const int M = NNODE;

    // ---- bucket ordering via counting sorts ----
    zero_k<<<512, 256>>>();
    rank_hist_k<<<dim3(64, 2), 256>>>(coords);
    scan_k<<<2, 1024>>>(p_rhist, p_rbase, NNODE, NNODE);
    rank_place_k<<<dim3(64, 2), 256>>>(coords);
    rank_rank_k<<<dim3(64, 2), 256>>>(coords);
    key_k<<<dim3(64, 16), 256>>>(regions);
    scan_k<<<16, 1024>>>(p_bhist, p_bbase, KBINS, KBINS);
    bucket_place_k<<<dim3(64, 16), 256>>>();
    bucket_pos_k<<<dim3(64, 16), 256>>>();
    w2all_k<<<4, 128>>>(wrpe);
    mh_k<<<32, 256>>>(wq, wk);
    gw_k<<<32, 256>>>(wv, ow);

    // feat encoder + LN1(layer 0)
    ffe_k<<<256, 256>>>(x, fe_w1, fe_b1, fe_w2, fe_b2, ln1_g, ln1_b);

    for (int l = 0; l < 4; l++) {
        tq_k<<<dim3(256, 8), 256>>>(p_M + (size_t)l * 8 * 4096);
        attn_k<<<dim3(256, 8, 2), 256>>>(coords, p_w2 + l * 16);
        const float* nlg = (l < 3) ? (ln1_g + (l + 1) * 64) : nullptr;
        const float* nlb = (l < 3) ? (ln1_b + (l + 1) * 64) : nullptr;
        epi_k<<<256, 256, 52224>>>(p_G + (size_t)l * 8 * 4096, ob + l * 64,
                                   ln2_g + l * 64, ln2_b + l * 64,
                                   f1w + (size_t)l * 64 * 64, f1b + l * 64,
                                   f2w + (size_t)l * 64 * 64, f2b + l * 64,
                                   p_hist + (l + 1) * 64, nlg, nlb);
    }

    gemm_k<<<dim3(256, 1), 256>>>(p_hist, Wcat, p_t0, nullptr, nullptr, M, 32, 320, 2);
    gemm_k<<<dim3(256, 4), 256>>>(p_t0, m1w, p_u, m1b, nullptr, M, 256, 32, 0);
    ln256w_k<<<2048, 256>>>(p_u, p_u2, mlng, mlnb);
    gemm_k<<<dim3(256, 1), 256>>>(p_u2, m2w, p_t, m2b, p_t0, M, 32, 256, 0);
    red1_k<<<128, 256>>>(p_t);
    red2_k<<<1, 256>>>(pw, pb, out);
}